// round 8
// baseline (speedup 1.0000x reference)
#include <cuda_runtime.h>
#include <cuda_bf16.h>
#include <math.h>
#include <stdint.h>

#define Bn    2
#define Sn    2048
#define DIN   2048
#define Hn    16
#define Gn    4
#define HD    128
#define DOUT  2048
#define GROUPn 4          // H / G
#define EPSf  1e-6f
#define Mrows (Bn*Sn)     // 4096

// ---------------- scratch (device globals; no allocation allowed) ----------
__device__ float g_QG  [(size_t)Bn*Sn*Hn*2*HD];   // [b,s,h,2*HD]  (q | gate)
__device__ float g_KV  [(size_t)Bn*Sn*(2*Gn*HD)]; // [b,s, K(512) | V(512)]

// bf16 hi/lo attention operands
__device__ __nv_bfloat16 g_Qh[(size_t)Bn*Hn*Sn*HD];
__device__ __nv_bfloat16 g_Ql[(size_t)Bn*Hn*Sn*HD];
__device__ __nv_bfloat16 g_Kh[(size_t)Bn*Gn*Sn*HD];
__device__ __nv_bfloat16 g_Kl[(size_t)Bn*Gn*Sn*HD];
__device__ __nv_bfloat16 g_Vh[(size_t)Bn*Gn*Sn*HD];
__device__ __nv_bfloat16 g_Vl[(size_t)Bn*Gn*Sn*HD];

// bf16 split scratch for GEMMs
__device__ __nv_bfloat16 g_xh  [(size_t)Mrows*DIN];
__device__ __nv_bfloat16 g_xl  [(size_t)Mrows*DIN];
__device__ __nv_bfloat16 g_Wqh [(size_t)(2*DOUT)*DIN];
__device__ __nv_bfloat16 g_Wql [(size_t)(2*DOUT)*DIN];
__device__ __nv_bfloat16 g_Wkvh[(size_t)(2*Gn*HD)*DIN];  // [K(512)|V(512)][2048]
__device__ __nv_bfloat16 g_Wkvl[(size_t)(2*Gn*HD)*DIN];
__device__ __nv_bfloat16 g_Woh [(size_t)DIN*DOUT];
__device__ __nv_bfloat16 g_Wol [(size_t)DIN*DOUT];
__device__ __nv_bfloat16 g_Cxh [(size_t)Mrows*DOUT];
__device__ __nv_bfloat16 g_Cxl [(size_t)Mrows*DOUT];

// ======================= PTX helpers (compute_103 baseline only) ==========
__device__ __forceinline__ uint32_t smem_u32(const void* p) {
    uint32_t a;
    asm("{ .reg .u64 t; cvta.to.shared.u64 t, %1; cvt.u32.u64 %0, t; }" : "=r"(a) : "l"(p));
    return a;
}
__device__ __forceinline__ void cp16(uint32_t s, const void* g) {
    asm volatile("cp.async.cg.shared.global [%0], [%1], 16;" :: "r"(s), "l"(g));
}
#define CP_COMMIT() asm volatile("cp.async.commit_group;" ::: "memory")
#define CP_WAIT(n)  asm volatile("cp.async.wait_group %0;" :: "n"(n) : "memory")

__device__ __forceinline__ void ldsm_x4(uint32_t* r, uint32_t addr) {
    asm volatile("ldmatrix.sync.aligned.m8n8.x4.shared.b16 {%0,%1,%2,%3}, [%4];"
        : "=r"(r[0]), "=r"(r[1]), "=r"(r[2]), "=r"(r[3]) : "r"(addr));
}
__device__ __forceinline__ void ldsm_x4t(uint32_t* r, uint32_t addr) {
    asm volatile("ldmatrix.sync.aligned.m8n8.x4.trans.shared.b16 {%0,%1,%2,%3}, [%4];"
        : "=r"(r[0]), "=r"(r[1]), "=r"(r[2]), "=r"(r[3]) : "r"(addr));
}
__device__ __forceinline__ void mma16816(float* d, const uint32_t* a, const uint32_t* b) {
    asm volatile(
        "mma.sync.aligned.m16n8k16.row.col.f32.bf16.bf16.f32 "
        "{%0,%1,%2,%3}, {%4,%5,%6,%7}, {%8,%9}, {%0,%1,%2,%3};"
        : "+f"(d[0]), "+f"(d[1]), "+f"(d[2]), "+f"(d[3])
        : "r"(a[0]), "r"(a[1]), "r"(a[2]), "r"(a[3]), "r"(b[0]), "r"(b[1]));
}
__device__ __forceinline__ float ex2f(float x) {
    float r; asm("ex2.approx.f32 %0, %1;" : "=f"(r) : "f"(x)); return r;
}
__device__ __forceinline__ uint32_t packbf2(float lo, float hi) {
    uint32_t r; asm("cvt.rn.bf16x2.f32 %0, %1, %2;" : "=r"(r) : "f"(hi), "f"(lo)); return r;
}

// ======================= split / transpose-split ==========================
__global__ __launch_bounds__(256) void fsplit(const float* __restrict__ in,
                                              __nv_bfloat16* __restrict__ h,
                                              __nv_bfloat16* __restrict__ l, int n)
{
    int i = (blockIdx.x * 256 + threadIdx.x) * 4;
    if (i >= n) return;
    float4 v = *(const float4*)(in + i);
    __nv_bfloat16 h0 = __float2bfloat16(v.x), h1 = __float2bfloat16(v.y);
    __nv_bfloat16 h2 = __float2bfloat16(v.z), h3 = __float2bfloat16(v.w);
    __nv_bfloat16 l0 = __float2bfloat16(v.x - __bfloat162float(h0));
    __nv_bfloat16 l1 = __float2bfloat16(v.y - __bfloat162float(h1));
    __nv_bfloat16 l2 = __float2bfloat16(v.z - __bfloat162float(h2));
    __nv_bfloat16 l3 = __float2bfloat16(v.w - __bfloat162float(h3));
    *(__nv_bfloat162*)(h + i)     = __nv_bfloat162(h0, h1);
    *(__nv_bfloat162*)(h + i + 2) = __nv_bfloat162(h2, h3);
    *(__nv_bfloat162*)(l + i)     = __nv_bfloat162(l0, l1);
    *(__nv_bfloat162*)(l + i + 2) = __nv_bfloat162(l2, l3);
}

// W[K,N] fp32 -> Th/Tl[N,K] bf16 (transpose + split)
__global__ __launch_bounds__(256) void tsplit(const float* __restrict__ W,
                                              __nv_bfloat16* __restrict__ Th,
                                              __nv_bfloat16* __restrict__ Tl,
                                              int K, int N)
{
    __shared__ float t[32][33];
    const int n0 = blockIdx.x * 32, k0 = blockIdx.y * 32;
    const int tx = threadIdx.x, ty = threadIdx.y;  // (32, 8)
    #pragma unroll
    for (int r = 0; r < 4; r++)
        t[ty + r * 8][tx] = W[(size_t)(k0 + ty + r * 8) * N + n0 + tx];
    __syncthreads();
    #pragma unroll
    for (int r = 0; r < 4; r++) {
        int n = n0 + ty + r * 8, k = k0 + tx;
        float v = t[tx][ty + r * 8];
        __nv_bfloat16 h = __float2bfloat16(v);
        __nv_bfloat16 l = __float2bfloat16(v - __bfloat162float(h));
        Th[(size_t)n * K + k] = h;
        Tl[(size_t)n * K + k] = l;
    }
}

// ======================= HMMA split-bf16 GEMM (256x128, 3-stage) ===========
// C[M,N] = A[M,K] * B^T, A (hi/lo) [M,K], Bt (hi/lo) [N,K], K-major bf16.
// 256 threads (8 warps as 4m x 2n), warp tile 64x64, K-chunk 32. 1 sync/chunk.
#define GBK    32
#define LDS    40
#define ATILEB (256 * LDS * 2)   // 20480 B
#define BTILEB (128 * LDS * 2)   // 10240 B
#define STAGEB (2 * ATILEB + 2 * BTILEB)  // 61440 B
#define NSTAGE 3
#define GEMM_SMEM (NSTAGE * STAGEB)       // 184320 B
#define OFF_AL  ATILEB
#define OFF_BH  (2 * ATILEB)
#define OFF_BL  (2 * ATILEB + BTILEB)

__device__ __forceinline__ void load_stage(
    uint32_t smb, int stage,
    const __nv_bfloat16* __restrict__ pAh, const __nv_bfloat16* __restrict__ pAl,
    const __nv_bfloat16* __restrict__ pBh, const __nv_bfloat16* __restrict__ pBl,
    int K, int kc, int tid)
{
    const uint32_t sb = smb + stage * STAGEB;
    #pragma unroll
    for (int i = 0; i < 4; i++) {
        const int u = tid + i * 256;
        const int row = u >> 2, col = (u & 3) * 8;
        const uint32_t so = (uint32_t)(row * LDS + col) * 2;
        const size_t g = (size_t)row * K + kc + col;
        cp16(sb + so,          pAh + g);
        cp16(sb + OFF_AL + so, pAl + g);
    }
    #pragma unroll
    for (int i = 0; i < 2; i++) {
        const int u = tid + i * 256;
        const int row = u >> 2, col = (u & 3) * 8;
        const uint32_t so = (uint32_t)(row * LDS + col) * 2;
        const size_t g = (size_t)row * K + kc + col;
        cp16(sb + OFF_BH + so, pBh + g);
        cp16(sb + OFF_BL + so, pBl + g);
    }
}

__global__ __launch_bounds__(256, 1) void gemm_tc(
    const __nv_bfloat16* __restrict__ Ah, const __nv_bfloat16* __restrict__ Al,
    const __nv_bfloat16* __restrict__ Bh, const __nv_bfloat16* __restrict__ Bl,
    float* __restrict__ C, int M, int N, int K)
{
    extern __shared__ char sm[];
    const uint32_t smb = smem_u32(sm);
    const int tid  = threadIdx.x;
    const int wid  = tid >> 5, lane = tid & 31;
    const int wm   = wid & 3;
    const int wn   = wid >> 2;
    const int mbr  = blockIdx.y * 256, nbr = blockIdx.x * 128;

    const __nv_bfloat16* pAh = Ah + (size_t)mbr * K;
    const __nv_bfloat16* pAl = Al + (size_t)mbr * K;
    const __nv_bfloat16* pBh = Bh + (size_t)nbr * K;
    const __nv_bfloat16* pBl = Bl + (size_t)nbr * K;

    float acc[4][8][4];
    #pragma unroll
    for (int i = 0; i < 4; i++)
        #pragma unroll
        for (int j = 0; j < 8; j++)
            #pragma unroll
            for (int k = 0; k < 4; k++) acc[i][j][k] = 0.f;

    const uint32_t aoff = (uint32_t)((wm * 64 + (lane & 15)) * LDS + ((lane >> 4) * 8)) * 2;
    const uint32_t boff = (uint32_t)((wn * 64 + (lane & 7) + ((lane >> 4) << 3)) * LDS
                                     + (((lane >> 3) & 1) * 8)) * 2;

    const int NC = K / GBK;
    load_stage(smb, 0, pAh, pAl, pBh, pBl, K, 0, tid);
    CP_COMMIT();
    load_stage(smb, 1, pAh, pAl, pBh, pBl, K, GBK, tid);
    CP_COMMIT();

    int st_idx = 0;
    for (int c = 0; c < NC; c++) {
        if (c + 1 < NC) { CP_WAIT(1); } else { CP_WAIT(0); }
        __syncthreads();
        if (c + 2 < NC) {
            int ns = st_idx + 2; if (ns >= NSTAGE) ns -= NSTAGE;
            load_stage(smb, ns, pAh, pAl, pBh, pBl, K, (c + 2) * GBK, tid);
            CP_COMMIT();
        }

        const uint32_t st = smb + st_idx * STAGEB;
        #pragma unroll
        for (int ks = 0; ks < 2; ks++) {
            const uint32_t kb = ks * 32;
            uint32_t bh[16], bl[16];
            #pragma unroll
            for (int n16 = 0; n16 < 4; n16++) {
                ldsm_x4(bh + 4 * n16, st + OFF_BH + boff + n16 * (16 * LDS * 2) + kb);
                ldsm_x4(bl + 4 * n16, st + OFF_BL + boff + n16 * (16 * LDS * 2) + kb);
            }
            #pragma unroll
            for (int mf = 0; mf < 4; mf++) {
                uint32_t ah[4], al[4];
                ldsm_x4(ah, st + aoff + mf * (16 * LDS * 2) + kb);
                ldsm_x4(al, st + OFF_AL + aoff + mf * (16 * LDS * 2) + kb);
                #pragma unroll
                for (int nf = 0; nf < 8; nf++)
                    mma16816(acc[mf][nf], ah, &bh[(nf >> 1) * 4 + (nf & 1) * 2]);
                #pragma unroll
                for (int nf = 0; nf < 8; nf++)
                    mma16816(acc[mf][nf], ah, &bl[(nf >> 1) * 4 + (nf & 1) * 2]);
                #pragma unroll
                for (int nf = 0; nf < 8; nf++)
                    mma16816(acc[mf][nf], al, &bh[(nf >> 1) * 4 + (nf & 1) * 2]);
            }
        }
        if (++st_idx == NSTAGE) st_idx = 0;
    }

    #pragma unroll
    for (int mf = 0; mf < 4; mf++) {
        const int r0 = mbr + wm * 64 + mf * 16 + (lane >> 2);
        #pragma unroll
        for (int nf = 0; nf < 8; nf++) {
            const int n0 = nbr + wn * 64 + nf * 8 + (lane & 3) * 2;
            *(float2*)(C + (size_t)r0 * N + n0)       = make_float2(acc[mf][nf][0], acc[mf][nf][1]);
            *(float2*)(C + (size_t)(r0 + 8) * N + n0) = make_float2(acc[mf][nf][2], acc[mf][nf][3]);
        }
    }
}

// ---------------- rmsnorm + rope for Q -> bf16 hi/lo -----------------------
__global__ __launch_bounds__(128) void qnorm_rope(
    const float* __restrict__ QG, const float* __restrict__ w,
    const float* __restrict__ cosT, const float* __restrict__ sinT,
    __nv_bfloat16* __restrict__ Qh, __nv_bfloat16* __restrict__ Ql)
{
    const int s = blockIdx.x, h = blockIdx.y, b = blockIdx.z;
    const int d = threadIdx.x;
    const float* src = QG + (((size_t)(b * Sn + s) * Hn + h) * 2 * HD);
    float x = src[d];
    float ss = x * x;
    #pragma unroll
    for (int o = 16; o > 0; o >>= 1) ss += __shfl_xor_sync(0xffffffffu, ss, o);
    __shared__ float wsum[4];
    if ((d & 31) == 0) wsum[d >> 5] = ss;
    __syncthreads();
    float tot = wsum[0] + wsum[1] + wsum[2] + wsum[3];
    float inv = rsqrtf(tot * (1.0f / HD) + EPSf);
    float n = x * inv * (1.0f + w[d]);
    __shared__ float nb[HD];
    nb[d] = n;
    __syncthreads();
    float c  = cosT[(size_t)s * HD + d];
    float sn = sinT[(size_t)s * HD + d];
    float rot = (d < HD / 2) ? -nb[d + HD / 2] : nb[d - HD / 2];
    float y = n * c + rot * sn;
    __nv_bfloat16 hh = __float2bfloat16(y);
    const size_t dst = ((size_t)(b * Hn + h) * Sn + s) * HD + d;
    Qh[dst] = hh;
    Ql[dst] = __float2bfloat16(y - __bfloat162float(hh));
}

// ---------------- rmsnorm + rope for K -> hi/lo, plus V split --------------
__global__ __launch_bounds__(128) void knorm_rope_vsplit(
    const float* __restrict__ KV,
    const float* __restrict__ w,
    const float* __restrict__ cosT, const float* __restrict__ sinT,
    __nv_bfloat16* __restrict__ Kh, __nv_bfloat16* __restrict__ Kl,
    __nv_bfloat16* __restrict__ Vh, __nv_bfloat16* __restrict__ Vl)
{
    const int s = blockIdx.x, g = blockIdx.y, b = blockIdx.z;
    const int d = threadIdx.x;
    const float* row = KV + (size_t)(b * Sn + s) * (2 * Gn * HD) + g * HD;
    float x = row[d];
    float ss = x * x;
    #pragma unroll
    for (int o = 16; o > 0; o >>= 1) ss += __shfl_xor_sync(0xffffffffu, ss, o);
    __shared__ float wsum[4];
    if ((d & 31) == 0) wsum[d >> 5] = ss;
    __syncthreads();
    float tot = wsum[0] + wsum[1] + wsum[2] + wsum[3];
    float inv = rsqrtf(tot * (1.0f / HD) + EPSf);
    float n = x * inv * (1.0f + w[d]);
    __shared__ float nb[HD];
    nb[d] = n;
    __syncthreads();
    float c  = cosT[(size_t)s * HD + d];
    float sn = sinT[(size_t)s * HD + d];
    float rot = (d < HD / 2) ? -nb[d + HD / 2] : nb[d - HD / 2];
    float y = n * c + rot * sn;
    const size_t dst = ((size_t)(b * Gn + g) * Sn + s) * HD + d;
    __nv_bfloat16 kh = __float2bfloat16(y);
    Kh[dst] = kh;
    Kl[dst] = __float2bfloat16(y - __bfloat162float(kh));
    float v = row[Gn * HD + d];
    __nv_bfloat16 vh = __float2bfloat16(v);
    Vh[dst] = vh;
    Vl[dst] = __float2bfloat16(v - __bfloat162float(vh));
}

// ================= HMMA causal flash attention + sigmoid gate ==============
// BQ=128, 4 warps x m32 (two m16 groups per warp), BK=64, HD=128.
// 3-term split on QK^T and PV. Epilogue writes bf16 hi/lo Ctx (fused fsplit).
#define AT_LDS  136
#define Q_ELE   (128 * AT_LDS)
#define KT_ELE  (64 * AT_LDS)
#define KVSTAGE_ELE (4 * KT_ELE)
#define ATT_SMEM ((2 * Q_ELE + 2 * KVSTAGE_ELE) * 2)   // 208896 bytes
#define CSC 0.12751666806979654f    // (1/sqrt(128)) * log2(e)
#define NEGINF __int_as_float(0xff800000)

__device__ __forceinline__ void kv_load(
    uint32_t smb, int stage,
    const __nv_bfloat16* kh, const __nv_bfloat16* kl,
    const __nv_bfloat16* vh, const __nv_bfloat16* vl, int tid)
{
    const uint32_t base = smb + (2 * Q_ELE + stage * KVSTAGE_ELE) * 2;
    #pragma unroll
    for (int i = 0; i < 8; i++) {
        int u = tid + i * 128;          // 0..1023
        int row = u >> 4, c8 = (u & 15) * 8;
        uint32_t so = (uint32_t)(row * AT_LDS + c8) * 2;
        size_t go = (size_t)row * HD + c8;
        cp16(base + 0 * KT_ELE * 2 + so, kh + go);
        cp16(base + 1 * KT_ELE * 2 + so, kl + go);
        cp16(base + 2 * KT_ELE * 2 + so, vh + go);
        cp16(base + 3 * KT_ELE * 2 + so, vl + go);
    }
}

__global__ __launch_bounds__(128, 1) void attn_mma(
    const __nv_bfloat16* __restrict__ Qh, const __nv_bfloat16* __restrict__ Ql,
    const __nv_bfloat16* __restrict__ Kh, const __nv_bfloat16* __restrict__ Kl,
    const __nv_bfloat16* __restrict__ Vh, const __nv_bfloat16* __restrict__ Vl,
    const float* __restrict__ QG,
    __nv_bfloat16* __restrict__ Cxh, __nv_bfloat16* __restrict__ Cxl)
{
    extern __shared__ __nv_bfloat16 smem_bf[];
    const uint32_t smb = smem_u32(smem_bf);
    const int qi = blockIdx.x, h = blockIdx.y, b = blockIdx.z;
    const int g  = h / GROUPn;
    const int tid = threadIdx.x, lane = tid & 31, w = tid >> 5;   // 4 warps

    const __nv_bfloat16* gQh = Qh + ((size_t)(b * Hn + h) * Sn + (size_t)qi * 128) * HD;
    const __nv_bfloat16* gQl = Ql + ((size_t)(b * Hn + h) * Sn + (size_t)qi * 128) * HD;
    const __nv_bfloat16* gKh = Kh + ((size_t)(b * Gn + g) * Sn) * HD;
    const __nv_bfloat16* gKl = Kl + ((size_t)(b * Gn + g) * Sn) * HD;
    const __nv_bfloat16* gVh = Vh + ((size_t)(b * Gn + g) * Sn) * HD;
    const __nv_bfloat16* gVl = Vl + ((size_t)(b * Gn + g) * Sn) * HD;

    // load Q hi/lo into smem (128 x 128)
    #pragma unroll
    for (int i = 0; i < 16; i++) {
        int u = tid + i * 128;
        int row = u >> 4, c8 = (u & 15) * 8;
        *(uint4*)(smem_bf + row * AT_LDS + c8)         = *(const uint4*)(gQh + (size_t)row * HD + c8);
        *(uint4*)(smem_bf + Q_ELE + row * AT_LDS + c8) = *(const uint4*)(gQl + (size_t)row * HD + c8);
    }

    float m_[4], l_[4];
    #pragma unroll
    for (int i = 0; i < 4; i++) { m_[i] = NEGINF; l_[i] = 0.f; }
    float oacc[2][16][4];
    #pragma unroll
    for (int gq = 0; gq < 2; gq++)
        #pragma unroll
        for (int nf = 0; nf < 16; nf++)
            #pragma unroll
            for (int k = 0; k < 4; k++) oacc[gq][nf][k] = 0.f;

    // row mapping: group gq rows = w*32 + gq*16 + (lane>>2) (+8 for second half)
    int rg[4];   // [gq*2+half] global q row
    #pragma unroll
    for (int gq = 0; gq < 2; gq++) {
        rg[2 * gq]     = qi * 128 + w * 32 + gq * 16 + (lane >> 2);
        rg[2 * gq + 1] = rg[2 * gq] + 8;
    }

    kv_load(smb, 0, gKh, gKl, gVh, gVl, tid);
    CP_COMMIT();

    const int ntiles = 2 * qi + 2;
    for (int t = 0; t < ntiles; t++) {
        CP_WAIT(0);
        __syncthreads();
        if (t + 1 < ntiles) {
            kv_load(smb, (t + 1) & 1,
                    gKh + (size_t)(t + 1) * 64 * HD, gKl + (size_t)(t + 1) * 64 * HD,
                    gVh + (size_t)(t + 1) * 64 * HD, gVl + (size_t)(t + 1) * 64 * HD, tid);
            CP_COMMIT();
        }

        const uint32_t kb = smb + (2 * Q_ELE + (t & 1) * KVSTAGE_ELE) * 2;

        // ---- scores: S = Q K^T (3-term split, B-register reuse) ----
        float sacc[2][8][4];
        #pragma unroll
        for (int gq = 0; gq < 2; gq++)
            #pragma unroll
            for (int j = 0; j < 8; j++)
                #pragma unroll
                for (int k = 0; k < 4; k++) sacc[gq][j][k] = 0.f;

        #pragma unroll
        for (int kq = 0; kq < 8; kq++) {
            uint32_t a_h[2][4], a_l[2][4], bb[16];
            #pragma unroll
            for (int gq = 0; gq < 2; gq++) {
                const uint32_t qaddr = smb +
                    (uint32_t)((w * 32 + gq * 16 + (lane & 15)) * AT_LDS
                               + ((lane >> 4) << 3) + kq * 16) * 2;
                ldsm_x4(a_h[gq], qaddr);
                ldsm_x4(a_l[gq], qaddr + Q_ELE * 2);
            }
            uint32_t kaddr[4];
            #pragma unroll
            for (int n16 = 0; n16 < 4; n16++) {
                kaddr[n16] = kb +
                    (uint32_t)((n16 * 16 + (lane & 7) + ((lane >> 4) << 3)) * AT_LDS
                               + (((lane >> 3) & 1) << 3) + kq * 16) * 2;
                ldsm_x4(bb + 4 * n16, kaddr[n16]);             // K hi
            }
            // hh
            #pragma unroll
            for (int n16 = 0; n16 < 4; n16++)
                #pragma unroll
                for (int gq = 0; gq < 2; gq++) {
                    mma16816(sacc[gq][2 * n16],     a_h[gq], bb + 4 * n16);
                    mma16816(sacc[gq][2 * n16 + 1], a_h[gq], bb + 4 * n16 + 2);
                }
            // lh (uses K hi before overwrite)
            #pragma unroll
            for (int n16 = 0; n16 < 4; n16++)
                #pragma unroll
                for (int gq = 0; gq < 2; gq++) {
                    mma16816(sacc[gq][2 * n16],     a_l[gq], bb + 4 * n16);
                    mma16816(sacc[gq][2 * n16 + 1], a_l[gq], bb + 4 * n16 + 2);
                }
            // reload as K lo, then hl
            #pragma unroll
            for (int n16 = 0; n16 < 4; n16++)
                ldsm_x4(bb + 4 * n16, kaddr[n16] + KT_ELE * 2);
            #pragma unroll
            for (int n16 = 0; n16 < 4; n16++)
                #pragma unroll
                for (int gq = 0; gq < 2; gq++) {
                    mma16816(sacc[gq][2 * n16],     a_h[gq], bb + 4 * n16);
                    mma16816(sacc[gq][2 * n16 + 1], a_h[gq], bb + 4 * n16 + 2);
                }
        }

        // ---- online softmax (log2 domain) ----
        const bool needmask = (t >= 2 * qi);
        float f_[4];
        #pragma unroll
        for (int gq = 0; gq < 2; gq++) {
            float mt0 = m_[2 * gq], mt1 = m_[2 * gq + 1];
            #pragma unroll
            for (int j = 0; j < 8; j++) {
                const int c0 = t * 64 + j * 8 + (lane & 3) * 2;
                #pragma unroll
                for (int k = 0; k < 4; k++) sacc[gq][j][k] *= CSC;
                if (needmask) {
                    if (c0     > rg[2 * gq])     sacc[gq][j][0] = NEGINF;
                    if (c0 + 1 > rg[2 * gq])     sacc[gq][j][1] = NEGINF;
                    if (c0     > rg[2 * gq + 1]) sacc[gq][j][2] = NEGINF;
                    if (c0 + 1 > rg[2 * gq + 1]) sacc[gq][j][3] = NEGINF;
                }
                mt0 = fmaxf(mt0, fmaxf(sacc[gq][j][0], sacc[gq][j][1]));
                mt1 = fmaxf(mt1, fmaxf(sacc[gq][j][2], sacc[gq][j][3]));
            }
            mt0 = fmaxf(mt0, __shfl_xor_sync(0xffffffffu, mt0, 1));
            mt0 = fmaxf(mt0, __shfl_xor_sync(0xffffffffu, mt0, 2));
            mt1 = fmaxf(mt1, __shfl_xor_sync(0xffffffffu, mt1, 1));
            mt1 = fmaxf(mt1, __shfl_xor_sync(0xffffffffu, mt1, 2));
            f_[2 * gq]     = ex2f(m_[2 * gq] - mt0);
            f_[2 * gq + 1] = ex2f(m_[2 * gq + 1] - mt1);
            m_[2 * gq] = mt0; m_[2 * gq + 1] = mt1;
            float s0 = 0.f, s1 = 0.f;
            #pragma unroll
            for (int j = 0; j < 8; j++) {
                sacc[gq][j][0] = ex2f(sacc[gq][j][0] - mt0);
                sacc[gq][j][1] = ex2f(sacc[gq][j][1] - mt0);
                sacc[gq][j][2] = ex2f(sacc[gq][j][2] - mt1);
                sacc[gq][j][3] = ex2f(sacc[gq][j][3] - mt1);
                s0 += sacc[gq][j][0] + sacc[gq][j][1];
                s1 += sacc[gq][j][2] + sacc[gq][j][3];
            }
            l_[2 * gq]     = l_[2 * gq]     * f_[2 * gq]     + s0;
            l_[2 * gq + 1] = l_[2 * gq + 1] * f_[2 * gq + 1] + s1;
            #pragma unroll
            for (int nf = 0; nf < 16; nf++) {
                oacc[gq][nf][0] *= f_[2 * gq];     oacc[gq][nf][1] *= f_[2 * gq];
                oacc[gq][nf][2] *= f_[2 * gq + 1]; oacc[gq][nf][3] *= f_[2 * gq + 1];
            }
        }

        // ---- PV: out += P V (3-term split) ----
        #pragma unroll
        for (int kk = 0; kk < 4; kk++) {
            uint32_t a_h[2][4], a_l[2][4];
            #pragma unroll
            for (int gq = 0; gq < 2; gq++)
                #pragma unroll
                for (int half = 0; half < 2; half++) {
                    const float p0 = sacc[gq][2 * kk + half][0], p1 = sacc[gq][2 * kk + half][1];
                    const float p2 = sacc[gq][2 * kk + half][2], p3 = sacc[gq][2 * kk + half][3];
                    const uint32_t h01 = packbf2(p0, p1);
                    const uint32_t h23 = packbf2(p2, p3);
                    a_h[gq][2 * half]     = h01;
                    a_h[gq][2 * half + 1] = h23;
                    a_l[gq][2 * half]     = packbf2(p0 - __uint_as_float(h01 << 16),
                                                    p1 - __uint_as_float(h01 & 0xffff0000u));
                    a_l[gq][2 * half + 1] = packbf2(p2 - __uint_as_float(h23 << 16),
                                                    p3 - __uint_as_float(h23 & 0xffff0000u));
                }
            #pragma unroll
            for (int dp = 0; dp < 4; dp++) {    // dc = 2dp, 2dp+1
                uint32_t bvh0[4], bvl0[4], bvh1[4], bvl1[4];
                const uint32_t va0 = kb + 2 * KT_ELE * 2 +
                    (uint32_t)((kk * 16 + (lane & 15)) * AT_LDS + (2 * dp) * 16 + ((lane >> 4) << 3)) * 2;
                const uint32_t va1 = va0 + 32;
                ldsm_x4t(bvh0, va0);
                ldsm_x4t(bvl0, va0 + KT_ELE * 2);
                ldsm_x4t(bvh1, va1);
                ldsm_x4t(bvl1, va1 + KT_ELE * 2);
                #pragma unroll
                for (int gq = 0; gq < 2; gq++) {
                    // hh
                    mma16816(oacc[gq][4 * dp],     a_h[gq], bvh0);
                    mma16816(oacc[gq][4 * dp + 1], a_h[gq], bvh0 + 2);
                    mma16816(oacc[gq][4 * dp + 2], a_h[gq], bvh1);
                    mma16816(oacc[gq][4 * dp + 3], a_h[gq], bvh1 + 2);
                    // hl
                    mma16816(oacc[gq][4 * dp],     a_h[gq], bvl0);
                    mma16816(oacc[gq][4 * dp + 1], a_h[gq], bvl0 + 2);
                    mma16816(oacc[gq][4 * dp + 2], a_h[gq], bvl1);
                    mma16816(oacc[gq][4 * dp + 3], a_h[gq], bvl1 + 2);
                    // lh
                    mma16816(oacc[gq][4 * dp],     a_l[gq], bvh0);
                    mma16816(oacc[gq][4 * dp + 1], a_l[gq], bvh0 + 2);
                    mma16816(oacc[gq][4 * dp + 2], a_l[gq], bvh1);
                    mma16816(oacc[gq][4 * dp + 3], a_l[gq], bvh1 + 2);
                }
            }
        }
    }

    // ---- epilogue: /l, * sigmoid(gate), write bf16 hi/lo Ctx ----
    #pragma unroll
    for (int i = 0; i < 4; i++) {
        l_[i] += __shfl_xor_sync(0xffffffffu, l_[i], 1);
        l_[i] += __shfl_xor_sync(0xffffffffu, l_[i], 2);
        l_[i] = 1.0f / l_[i];
    }
    #pragma unroll
    for (int gq = 0; gq < 2; gq++)
        #pragma unroll
        for (int nf = 0; nf < 16; nf++) {
            const int dim = nf * 8 + (lane & 3) * 2;
            #pragma unroll
            for (int rr = 0; rr < 2; rr++) {
                const int q = rg[2 * gq + rr];
                const float invl = l_[2 * gq + rr];
                const float a0 = oacc[gq][nf][2 * rr], a1 = oacc[gq][nf][2 * rr + 1];
                const float2 gt = *(const float2*)(QG + (((size_t)(b * Sn + q) * Hn + h) * 2 * HD) + HD + dim);
                const float v0 = a0 * invl * (1.0f / (1.0f + expf(-gt.x)));
                const float v1 = a1 * invl * (1.0f / (1.0f + expf(-gt.y)));
                const __nv_bfloat16 h0 = __float2bfloat16(v0);
                const __nv_bfloat16 h1 = __float2bfloat16(v1);
                const size_t off = (size_t)(b * Sn + q) * DOUT + h * HD + dim;
                *(__nv_bfloat162*)(Cxh + off) = __nv_bfloat162(h0, h1);
                *(__nv_bfloat162*)(Cxl + off) =
                    __nv_bfloat162(__float2bfloat16(v0 - __bfloat162float(h0)),
                                   __float2bfloat16(v1 - __bfloat162float(h1)));
            }
        }
}

// ---------------------------- launcher -------------------------------------
extern "C" void kernel_launch(void* const* d_in, const int* in_sizes, int n_in,
                              void* d_out, int out_size)
{
    const float* x    = (const float*)d_in[0];
    const float* Wq   = (const float*)d_in[1];
    const float* Wk   = (const float*)d_in[2];
    const float* Wv   = (const float*)d_in[3];
    const float* Wo   = (const float*)d_in[4];
    const float* qw   = (const float*)d_in[5];
    const float* kw   = (const float*)d_in[6];
    const float* cosT = (const float*)d_in[7];
    const float* sinT = (const float*)d_in[8];
    float* out = (float*)d_out;

    float *QG, *KV;
    cudaGetSymbolAddress((void**)&QG, g_QG);
    cudaGetSymbolAddress((void**)&KV, g_KV);

    __nv_bfloat16 *Qhp, *Qlp, *Khp, *Klp, *Vhp, *Vlp;
    cudaGetSymbolAddress((void**)&Qhp, g_Qh);
    cudaGetSymbolAddress((void**)&Qlp, g_Ql);
    cudaGetSymbolAddress((void**)&Khp, g_Kh);
    cudaGetSymbolAddress((void**)&Klp, g_Kl);
    cudaGetSymbolAddress((void**)&Vhp, g_Vh);
    cudaGetSymbolAddress((void**)&Vlp, g_Vl);

    __nv_bfloat16 *xh, *xl, *Wqh, *Wql, *Wkvh, *Wkvl, *Woh, *Wol, *Cxh, *Cxl;
    cudaGetSymbolAddress((void**)&xh,   g_xh);
    cudaGetSymbolAddress((void**)&xl,   g_xl);
    cudaGetSymbolAddress((void**)&Wqh,  g_Wqh);
    cudaGetSymbolAddress((void**)&Wql,  g_Wql);
    cudaGetSymbolAddress((void**)&Wkvh, g_Wkvh);
    cudaGetSymbolAddress((void**)&Wkvl, g_Wkvl);
    cudaGetSymbolAddress((void**)&Woh,  g_Woh);
    cudaGetSymbolAddress((void**)&Wol,  g_Wol);
    cudaGetSymbolAddress((void**)&Cxh,  g_Cxh);
    cudaGetSymbolAddress((void**)&Cxl,  g_Cxl);

    cudaFuncSetAttribute(gemm_tc, cudaFuncAttributeMaxDynamicSharedMemorySize, GEMM_SMEM);
    cudaFuncSetAttribute(attn_mma, cudaFuncAttributeMaxDynamicSharedMemorySize, ATT_SMEM);

    const int M = Mrows;          // 4096
    const int NKV = 2 * Gn * HD;  // 1024

    fsplit<<<(M * DIN / 4 + 255) / 256, 256>>>(x, xh, xl, M * DIN);
    tsplit<<<dim3((2 * DOUT) / 32, DIN / 32), dim3(32, 8)>>>(Wq, Wqh, Wql, DIN, 2 * DOUT);
    tsplit<<<dim3((Gn * HD) / 32, DIN / 32), dim3(32, 8)>>>(Wk, Wkvh, Wkvl, DIN, Gn * HD);
    tsplit<<<dim3((Gn * HD) / 32, DIN / 32), dim3(32, 8)>>>(
        Wv, Wkvh + (size_t)(Gn * HD) * DIN, Wkvl + (size_t)(Gn * HD) * DIN, DIN, Gn * HD);
    tsplit<<<dim3(DIN / 32, DOUT / 32), dim3(32, 8)>>>(Wo, Woh, Wol, DOUT, DIN);

    gemm_tc<<<dim3((2 * DOUT) / 128, M / 256), 256, GEMM_SMEM>>>(
        xh, xl, Wqh, Wql, QG, M, 2 * DOUT, DIN);
    gemm_tc<<<dim3(NKV / 128, M / 256), 256, GEMM_SMEM>>>(
        xh, xl, Wkvh, Wkvl, KV, M, NKV, DIN);

    qnorm_rope<<<dim3(Sn, Hn, Bn), 128>>>(QG, qw, cosT, sinT, Qhp, Qlp);
    knorm_rope_vsplit<<<dim3(Sn, Gn, Bn), 128>>>(KV, kw, cosT, sinT,
                                                 Khp, Klp, Vhp, Vlp);

    attn_mma<<<dim3(Sn / 128, Hn, Bn), 128, ATT_SMEM>>>(
        Qhp, Qlp, Khp, Klp, Vhp, Vlp, QG, Cxh, Cxl);

    gemm_tc<<<dim3(DIN / 128, M / 256), 256, GEMM_SMEM>>>(
        Cxh, Cxl, Woh, Wol, out, M, DIN, DOUT);
}

// round 9
// speedup vs baseline: 1.0853x; 1.0853x over previous
#include <cuda_runtime.h>
#include <cuda_bf16.h>
#include <math.h>
#include <stdint.h>

#define Bn    2
#define Sn    2048
#define DIN   2048
#define Hn    16
#define Gn    4
#define HD    128
#define DOUT  2048
#define GROUPn 4          // H / G
#define EPSf  1e-6f
#define Mrows (Bn*Sn)     // 4096

// ---------------- scratch (device globals; no allocation allowed) ----------
__device__ float g_QG  [(size_t)Bn*Sn*Hn*2*HD];   // [b,s,h,2*HD]  (q | gate)
__device__ float g_KV  [(size_t)Bn*Sn*(2*Gn*HD)]; // [b,s, K(512) | V(512)]

// bf16 hi/lo attention operands
__device__ __nv_bfloat16 g_Qh[(size_t)Bn*Hn*Sn*HD];
__device__ __nv_bfloat16 g_Ql[(size_t)Bn*Hn*Sn*HD];
__device__ __nv_bfloat16 g_Kh[(size_t)Bn*Gn*Sn*HD];
__device__ __nv_bfloat16 g_Kl[(size_t)Bn*Gn*Sn*HD];
__device__ __nv_bfloat16 g_Vh[(size_t)Bn*Gn*Sn*HD];
__device__ __nv_bfloat16 g_Vl[(size_t)Bn*Gn*Sn*HD];

// bf16 split scratch for GEMMs
__device__ __nv_bfloat16 g_xh  [(size_t)Mrows*DIN];
__device__ __nv_bfloat16 g_xl  [(size_t)Mrows*DIN];
__device__ __nv_bfloat16 g_Wqh [(size_t)(2*DOUT)*DIN];
__device__ __nv_bfloat16 g_Wql [(size_t)(2*DOUT)*DIN];
__device__ __nv_bfloat16 g_Wkvh[(size_t)(2*Gn*HD)*DIN];  // [K(512)|V(512)][2048]
__device__ __nv_bfloat16 g_Wkvl[(size_t)(2*Gn*HD)*DIN];
__device__ __nv_bfloat16 g_Woh [(size_t)DIN*DOUT];
__device__ __nv_bfloat16 g_Wol [(size_t)DIN*DOUT];
__device__ __nv_bfloat16 g_Cxh [(size_t)Mrows*DOUT];
__device__ __nv_bfloat16 g_Cxl [(size_t)Mrows*DOUT];

// ======================= PTX helpers (compute_103 baseline only) ==========
__device__ __forceinline__ uint32_t smem_u32(const void* p) {
    uint32_t a;
    asm("{ .reg .u64 t; cvta.to.shared.u64 t, %1; cvt.u32.u64 %0, t; }" : "=r"(a) : "l"(p));
    return a;
}
__device__ __forceinline__ void cp16(uint32_t s, const void* g) {
    asm volatile("cp.async.cg.shared.global [%0], [%1], 16;" :: "r"(s), "l"(g));
}
#define CP_COMMIT() asm volatile("cp.async.commit_group;" ::: "memory")
#define CP_WAIT(n)  asm volatile("cp.async.wait_group %0;" :: "n"(n) : "memory")

__device__ __forceinline__ void ldsm_x4(uint32_t* r, uint32_t addr) {
    asm volatile("ldmatrix.sync.aligned.m8n8.x4.shared.b16 {%0,%1,%2,%3}, [%4];"
        : "=r"(r[0]), "=r"(r[1]), "=r"(r[2]), "=r"(r[3]) : "r"(addr));
}
__device__ __forceinline__ void ldsm_x4t(uint32_t* r, uint32_t addr) {
    asm volatile("ldmatrix.sync.aligned.m8n8.x4.trans.shared.b16 {%0,%1,%2,%3}, [%4];"
        : "=r"(r[0]), "=r"(r[1]), "=r"(r[2]), "=r"(r[3]) : "r"(addr));
}
__device__ __forceinline__ void mma16816(float* d, const uint32_t* a, const uint32_t* b) {
    asm volatile(
        "mma.sync.aligned.m16n8k16.row.col.f32.bf16.bf16.f32 "
        "{%0,%1,%2,%3}, {%4,%5,%6,%7}, {%8,%9}, {%0,%1,%2,%3};"
        : "+f"(d[0]), "+f"(d[1]), "+f"(d[2]), "+f"(d[3])
        : "r"(a[0]), "r"(a[1]), "r"(a[2]), "r"(a[3]), "r"(b[0]), "r"(b[1]));
}
__device__ __forceinline__ float ex2f(float x) {
    float r; asm("ex2.approx.f32 %0, %1;" : "=f"(r) : "f"(x)); return r;
}
__device__ __forceinline__ uint32_t packbf2(float lo, float hi) {
    uint32_t r; asm("cvt.rn.bf16x2.f32 %0, %1, %2;" : "=r"(r) : "f"(hi), "f"(lo)); return r;
}

// ======================= split / transpose-split ==========================
__global__ __launch_bounds__(256) void fsplit(const float* __restrict__ in,
                                              __nv_bfloat16* __restrict__ h,
                                              __nv_bfloat16* __restrict__ l, int n)
{
    int i = (blockIdx.x * 256 + threadIdx.x) * 4;
    if (i >= n) return;
    float4 v = *(const float4*)(in + i);
    __nv_bfloat16 h0 = __float2bfloat16(v.x), h1 = __float2bfloat16(v.y);
    __nv_bfloat16 h2 = __float2bfloat16(v.z), h3 = __float2bfloat16(v.w);
    __nv_bfloat16 l0 = __float2bfloat16(v.x - __bfloat162float(h0));
    __nv_bfloat16 l1 = __float2bfloat16(v.y - __bfloat162float(h1));
    __nv_bfloat16 l2 = __float2bfloat16(v.z - __bfloat162float(h2));
    __nv_bfloat16 l3 = __float2bfloat16(v.w - __bfloat162float(h3));
    *(__nv_bfloat162*)(h + i)     = __nv_bfloat162(h0, h1);
    *(__nv_bfloat162*)(h + i + 2) = __nv_bfloat162(h2, h3);
    *(__nv_bfloat162*)(l + i)     = __nv_bfloat162(l0, l1);
    *(__nv_bfloat162*)(l + i + 2) = __nv_bfloat162(l2, l3);
}

// W[K,N] fp32 -> Th/Tl[N,K] bf16 (transpose + split)
__global__ __launch_bounds__(256) void tsplit(const float* __restrict__ W,
                                              __nv_bfloat16* __restrict__ Th,
                                              __nv_bfloat16* __restrict__ Tl,
                                              int K, int N)
{
    __shared__ float t[32][33];
    const int n0 = blockIdx.x * 32, k0 = blockIdx.y * 32;
    const int tx = threadIdx.x, ty = threadIdx.y;  // (32, 8)
    #pragma unroll
    for (int r = 0; r < 4; r++)
        t[ty + r * 8][tx] = W[(size_t)(k0 + ty + r * 8) * N + n0 + tx];
    __syncthreads();
    #pragma unroll
    for (int r = 0; r < 4; r++) {
        int n = n0 + ty + r * 8, k = k0 + tx;
        float v = t[tx][ty + r * 8];
        __nv_bfloat16 h = __float2bfloat16(v);
        __nv_bfloat16 l = __float2bfloat16(v - __bfloat162float(h));
        Th[(size_t)n * K + k] = h;
        Tl[(size_t)n * K + k] = l;
    }
}

// ======================= HMMA split-bf16 GEMM (256x128, 3-stage) ===========
// C[M,N] = A[M,K] * B^T, A (hi/lo) [M,K], Bt (hi/lo) [N,K], K-major bf16.
// 256 threads (8 warps as 4m x 2n), warp tile 64x64, K-chunk 32. 1 sync/chunk.
#define GBK    32
#define LDS    40
#define ATILEB (256 * LDS * 2)   // 20480 B
#define BTILEB (128 * LDS * 2)   // 10240 B
#define STAGEB (2 * ATILEB + 2 * BTILEB)  // 61440 B
#define NSTAGE 3
#define GEMM_SMEM (NSTAGE * STAGEB)       // 184320 B
#define OFF_AL  ATILEB
#define OFF_BH  (2 * ATILEB)
#define OFF_BL  (2 * ATILEB + BTILEB)

__device__ __forceinline__ void load_stage(
    uint32_t smb, int stage,
    const __nv_bfloat16* __restrict__ pAh, const __nv_bfloat16* __restrict__ pAl,
    const __nv_bfloat16* __restrict__ pBh, const __nv_bfloat16* __restrict__ pBl,
    int K, int kc, int tid)
{
    const uint32_t sb = smb + stage * STAGEB;
    #pragma unroll
    for (int i = 0; i < 4; i++) {
        const int u = tid + i * 256;
        const int row = u >> 2, col = (u & 3) * 8;
        const uint32_t so = (uint32_t)(row * LDS + col) * 2;
        const size_t g = (size_t)row * K + kc + col;
        cp16(sb + so,          pAh + g);
        cp16(sb + OFF_AL + so, pAl + g);
    }
    #pragma unroll
    for (int i = 0; i < 2; i++) {
        const int u = tid + i * 256;
        const int row = u >> 2, col = (u & 3) * 8;
        const uint32_t so = (uint32_t)(row * LDS + col) * 2;
        const size_t g = (size_t)row * K + kc + col;
        cp16(sb + OFF_BH + so, pBh + g);
        cp16(sb + OFF_BL + so, pBl + g);
    }
}

__global__ __launch_bounds__(256, 1) void gemm_tc(
    const __nv_bfloat16* __restrict__ Ah, const __nv_bfloat16* __restrict__ Al,
    const __nv_bfloat16* __restrict__ Bh, const __nv_bfloat16* __restrict__ Bl,
    float* __restrict__ C, int M, int N, int K)
{
    extern __shared__ char sm[];
    const uint32_t smb = smem_u32(sm);
    const int tid  = threadIdx.x;
    const int wid  = tid >> 5, lane = tid & 31;
    const int wm   = wid & 3;
    const int wn   = wid >> 2;
    const int mbr  = blockIdx.y * 256, nbr = blockIdx.x * 128;

    const __nv_bfloat16* pAh = Ah + (size_t)mbr * K;
    const __nv_bfloat16* pAl = Al + (size_t)mbr * K;
    const __nv_bfloat16* pBh = Bh + (size_t)nbr * K;
    const __nv_bfloat16* pBl = Bl + (size_t)nbr * K;

    float acc[4][8][4];
    #pragma unroll
    for (int i = 0; i < 4; i++)
        #pragma unroll
        for (int j = 0; j < 8; j++)
            #pragma unroll
            for (int k = 0; k < 4; k++) acc[i][j][k] = 0.f;

    const uint32_t aoff = (uint32_t)((wm * 64 + (lane & 15)) * LDS + ((lane >> 4) * 8)) * 2;
    const uint32_t boff = (uint32_t)((wn * 64 + (lane & 7) + ((lane >> 4) << 3)) * LDS
                                     + (((lane >> 3) & 1) * 8)) * 2;

    const int NC = K / GBK;
    load_stage(smb, 0, pAh, pAl, pBh, pBl, K, 0, tid);
    CP_COMMIT();
    load_stage(smb, 1, pAh, pAl, pBh, pBl, K, GBK, tid);
    CP_COMMIT();

    int st_idx = 0;
    for (int c = 0; c < NC; c++) {
        if (c + 1 < NC) { CP_WAIT(1); } else { CP_WAIT(0); }
        __syncthreads();
        if (c + 2 < NC) {
            int ns = st_idx + 2; if (ns >= NSTAGE) ns -= NSTAGE;
            load_stage(smb, ns, pAh, pAl, pBh, pBl, K, (c + 2) * GBK, tid);
            CP_COMMIT();
        }

        const uint32_t st = smb + st_idx * STAGEB;
        #pragma unroll
        for (int ks = 0; ks < 2; ks++) {
            const uint32_t kb = ks * 32;
            uint32_t bh[16], bl[16];
            #pragma unroll
            for (int n16 = 0; n16 < 4; n16++) {
                ldsm_x4(bh + 4 * n16, st + OFF_BH + boff + n16 * (16 * LDS * 2) + kb);
                ldsm_x4(bl + 4 * n16, st + OFF_BL + boff + n16 * (16 * LDS * 2) + kb);
            }
            #pragma unroll
            for (int mf = 0; mf < 4; mf++) {
                uint32_t ah[4], al[4];
                ldsm_x4(ah, st + aoff + mf * (16 * LDS * 2) + kb);
                ldsm_x4(al, st + OFF_AL + aoff + mf * (16 * LDS * 2) + kb);
                #pragma unroll
                for (int nf = 0; nf < 8; nf++)
                    mma16816(acc[mf][nf], ah, &bh[(nf >> 1) * 4 + (nf & 1) * 2]);
                #pragma unroll
                for (int nf = 0; nf < 8; nf++)
                    mma16816(acc[mf][nf], ah, &bl[(nf >> 1) * 4 + (nf & 1) * 2]);
                #pragma unroll
                for (int nf = 0; nf < 8; nf++)
                    mma16816(acc[mf][nf], al, &bh[(nf >> 1) * 4 + (nf & 1) * 2]);
            }
        }
        if (++st_idx == NSTAGE) st_idx = 0;
    }

    #pragma unroll
    for (int mf = 0; mf < 4; mf++) {
        const int r0 = mbr + wm * 64 + mf * 16 + (lane >> 2);
        #pragma unroll
        for (int nf = 0; nf < 8; nf++) {
            const int n0 = nbr + wn * 64 + nf * 8 + (lane & 3) * 2;
            *(float2*)(C + (size_t)r0 * N + n0)       = make_float2(acc[mf][nf][0], acc[mf][nf][1]);
            *(float2*)(C + (size_t)(r0 + 8) * N + n0) = make_float2(acc[mf][nf][2], acc[mf][nf][3]);
        }
    }
}

// ---------------- rmsnorm + rope for Q -> bf16 hi/lo -----------------------
__global__ __launch_bounds__(128) void qnorm_rope(
    const float* __restrict__ QG, const float* __restrict__ w,
    const float* __restrict__ cosT, const float* __restrict__ sinT,
    __nv_bfloat16* __restrict__ Qh, __nv_bfloat16* __restrict__ Ql)
{
    const int s = blockIdx.x, h = blockIdx.y, b = blockIdx.z;
    const int d = threadIdx.x;
    const float* src = QG + (((size_t)(b * Sn + s) * Hn + h) * 2 * HD);
    float x = src[d];
    float ss = x * x;
    #pragma unroll
    for (int o = 16; o > 0; o >>= 1) ss += __shfl_xor_sync(0xffffffffu, ss, o);
    __shared__ float wsum[4];
    if ((d & 31) == 0) wsum[d >> 5] = ss;
    __syncthreads();
    float tot = wsum[0] + wsum[1] + wsum[2] + wsum[3];
    float inv = rsqrtf(tot * (1.0f / HD) + EPSf);
    float n = x * inv * (1.0f + w[d]);
    __shared__ float nb[HD];
    nb[d] = n;
    __syncthreads();
    float c  = cosT[(size_t)s * HD + d];
    float sn = sinT[(size_t)s * HD + d];
    float rot = (d < HD / 2) ? -nb[d + HD / 2] : nb[d - HD / 2];
    float y = n * c + rot * sn;
    __nv_bfloat16 hh = __float2bfloat16(y);
    const size_t dst = ((size_t)(b * Hn + h) * Sn + s) * HD + d;
    Qh[dst] = hh;
    Ql[dst] = __float2bfloat16(y - __bfloat162float(hh));
}

// ---------------- rmsnorm + rope for K -> hi/lo, plus V split --------------
__global__ __launch_bounds__(128) void knorm_rope_vsplit(
    const float* __restrict__ KV,
    const float* __restrict__ w,
    const float* __restrict__ cosT, const float* __restrict__ sinT,
    __nv_bfloat16* __restrict__ Kh, __nv_bfloat16* __restrict__ Kl,
    __nv_bfloat16* __restrict__ Vh, __nv_bfloat16* __restrict__ Vl)
{
    const int s = blockIdx.x, g = blockIdx.y, b = blockIdx.z;
    const int d = threadIdx.x;
    const float* row = KV + (size_t)(b * Sn + s) * (2 * Gn * HD) + g * HD;
    float x = row[d];
    float ss = x * x;
    #pragma unroll
    for (int o = 16; o > 0; o >>= 1) ss += __shfl_xor_sync(0xffffffffu, ss, o);
    __shared__ float wsum[4];
    if ((d & 31) == 0) wsum[d >> 5] = ss;
    __syncthreads();
    float tot = wsum[0] + wsum[1] + wsum[2] + wsum[3];
    float inv = rsqrtf(tot * (1.0f / HD) + EPSf);
    float n = x * inv * (1.0f + w[d]);
    __shared__ float nb[HD];
    nb[d] = n;
    __syncthreads();
    float c  = cosT[(size_t)s * HD + d];
    float sn = sinT[(size_t)s * HD + d];
    float rot = (d < HD / 2) ? -nb[d + HD / 2] : nb[d - HD / 2];
    float y = n * c + rot * sn;
    const size_t dst = ((size_t)(b * Gn + g) * Sn + s) * HD + d;
    __nv_bfloat16 kh = __float2bfloat16(y);
    Kh[dst] = kh;
    Kl[dst] = __float2bfloat16(y - __bfloat162float(kh));
    float v = row[Gn * HD + d];
    __nv_bfloat16 vh = __float2bfloat16(v);
    Vh[dst] = vh;
    Vl[dst] = __float2bfloat16(v - __bfloat162float(vh));
}

// ================= HMMA causal flash attention + sigmoid gate ==============
// BQ=128 (8 warps x m16), BK=64, HD=128. 3-term split on QK^T and PV.
// Single __syncthreads per tile. Epilogue writes bf16 hi/lo Ctx (fused fsplit).
#define AT_LDS  136
#define Q_ELE   (128 * AT_LDS)
#define KT_ELE  (64 * AT_LDS)
#define KVSTAGE_ELE (4 * KT_ELE)
#define ATT_SMEM ((2 * Q_ELE + 2 * KVSTAGE_ELE) * 2)   // 208896 bytes
#define CSC 0.12751666806979654f    // (1/sqrt(128)) * log2(e)
#define NEGINF __int_as_float(0xff800000)

__device__ __forceinline__ void kv_load(
    uint32_t smb, int stage,
    const __nv_bfloat16* kh, const __nv_bfloat16* kl,
    const __nv_bfloat16* vh, const __nv_bfloat16* vl, int tid)
{
    const uint32_t base = smb + (2 * Q_ELE + stage * KVSTAGE_ELE) * 2;
    #pragma unroll
    for (int i = 0; i < 4; i++) {
        int u = tid + i * 256;          // 0..1023
        int row = u >> 4, c8 = (u & 15) * 8;
        uint32_t so = (uint32_t)(row * AT_LDS + c8) * 2;
        size_t go = (size_t)row * HD + c8;
        cp16(base + 0 * KT_ELE * 2 + so, kh + go);
        cp16(base + 1 * KT_ELE * 2 + so, kl + go);
        cp16(base + 2 * KT_ELE * 2 + so, vh + go);
        cp16(base + 3 * KT_ELE * 2 + so, vl + go);
    }
}

__global__ __launch_bounds__(256, 1) void attn_mma(
    const __nv_bfloat16* __restrict__ Qh, const __nv_bfloat16* __restrict__ Ql,
    const __nv_bfloat16* __restrict__ Kh, const __nv_bfloat16* __restrict__ Kl,
    const __nv_bfloat16* __restrict__ Vh, const __nv_bfloat16* __restrict__ Vl,
    const float* __restrict__ QG,
    __nv_bfloat16* __restrict__ Cxh, __nv_bfloat16* __restrict__ Cxl)
{
    extern __shared__ __nv_bfloat16 smem_bf[];
    const uint32_t smb = smem_u32(smem_bf);
    const int qi = blockIdx.x, h = blockIdx.y, b = blockIdx.z;
    const int g  = h / GROUPn;
    const int tid = threadIdx.x, lane = tid & 31, w = tid >> 5;

    const __nv_bfloat16* gQh = Qh + ((size_t)(b * Hn + h) * Sn + (size_t)qi * 128) * HD;
    const __nv_bfloat16* gQl = Ql + ((size_t)(b * Hn + h) * Sn + (size_t)qi * 128) * HD;
    const __nv_bfloat16* gKh = Kh + ((size_t)(b * Gn + g) * Sn) * HD;
    const __nv_bfloat16* gKl = Kl + ((size_t)(b * Gn + g) * Sn) * HD;
    const __nv_bfloat16* gVh = Vh + ((size_t)(b * Gn + g) * Sn) * HD;
    const __nv_bfloat16* gVl = Vl + ((size_t)(b * Gn + g) * Sn) * HD;

    // load Q hi/lo into smem (128 x 128)
    #pragma unroll
    for (int i = 0; i < 8; i++) {
        int u = tid + i * 256;
        int row = u >> 4, c8 = (u & 15) * 8;
        *(uint4*)(smem_bf + row * AT_LDS + c8)         = *(const uint4*)(gQh + (size_t)row * HD + c8);
        *(uint4*)(smem_bf + Q_ELE + row * AT_LDS + c8) = *(const uint4*)(gQl + (size_t)row * HD + c8);
    }

    float m1s = NEGINF, m2s = NEGINF, l1 = 0.f, l2 = 0.f;
    float oacc[16][4];
    #pragma unroll
    for (int nf = 0; nf < 16; nf++)
        #pragma unroll
        for (int k = 0; k < 4; k++) oacc[nf][k] = 0.f;

    const int r1rel = w * 16 + (lane >> 2);   // 0..127
    const int r1g = qi * 128 + r1rel;
    const int r2g = r1g + 8;

    kv_load(smb, 0, gKh, gKl, gVh, gVl, tid);
    CP_COMMIT();

    const int ntiles = 2 * qi + 2;
    for (int t = 0; t < ntiles; t++) {
        CP_WAIT(0);
        __syncthreads();      // KV stage (t&1) ready AND all warps done with it from t-2
        if (t + 1 < ntiles) {
            kv_load(smb, (t + 1) & 1,
                    gKh + (size_t)(t + 1) * 64 * HD, gKl + (size_t)(t + 1) * 64 * HD,
                    gVh + (size_t)(t + 1) * 64 * HD, gVl + (size_t)(t + 1) * 64 * HD, tid);
            CP_COMMIT();
        }

        const uint32_t kb = smb + (2 * Q_ELE + (t & 1) * KVSTAGE_ELE) * 2;

        // ---- scores: S = Q K^T (3-term split, term-major) ----
        float sacc[8][4];
        #pragma unroll
        for (int j = 0; j < 8; j++)
            #pragma unroll
            for (int k = 0; k < 4; k++) sacc[j][k] = 0.f;

        #pragma unroll
        for (int kq = 0; kq < 8; kq++) {
            uint32_t ah[4], al[4], bh[16], bl[16];
            const uint32_t qaddr = smb +
                (uint32_t)((w * 16 + (lane & 15)) * AT_LDS + ((lane >> 4) << 3) + kq * 16) * 2;
            ldsm_x4(ah, qaddr);
            ldsm_x4(al, qaddr + Q_ELE * 2);
            #pragma unroll
            for (int n16 = 0; n16 < 4; n16++) {
                const uint32_t kaddr = kb +
                    (uint32_t)((n16 * 16 + (lane & 7) + ((lane >> 4) << 3)) * AT_LDS
                               + (((lane >> 3) & 1) << 3) + kq * 16) * 2;
                ldsm_x4(bh + 4 * n16, kaddr);
                ldsm_x4(bl + 4 * n16, kaddr + KT_ELE * 2);
            }
            #pragma unroll
            for (int n16 = 0; n16 < 4; n16++) {
                mma16816(sacc[2 * n16],     ah, bh + 4 * n16);
                mma16816(sacc[2 * n16 + 1], ah, bh + 4 * n16 + 2);
            }
            #pragma unroll
            for (int n16 = 0; n16 < 4; n16++) {
                mma16816(sacc[2 * n16],     ah, bl + 4 * n16);
                mma16816(sacc[2 * n16 + 1], ah, bl + 4 * n16 + 2);
            }
            #pragma unroll
            for (int n16 = 0; n16 < 4; n16++) {
                mma16816(sacc[2 * n16],     al, bh + 4 * n16);
                mma16816(sacc[2 * n16 + 1], al, bh + 4 * n16 + 2);
            }
        }

        // ---- online softmax (log2 domain) ----
        const bool needmask = (t >= 2 * qi);
        float mt1 = m1s, mt2 = m2s;
        #pragma unroll
        for (int j = 0; j < 8; j++) {
            const int c0 = t * 64 + j * 8 + (lane & 3) * 2;
            #pragma unroll
            for (int k = 0; k < 4; k++) sacc[j][k] *= CSC;
            if (needmask) {
                if (c0     > r1g) sacc[j][0] = NEGINF;
                if (c0 + 1 > r1g) sacc[j][1] = NEGINF;
                if (c0     > r2g) sacc[j][2] = NEGINF;
                if (c0 + 1 > r2g) sacc[j][3] = NEGINF;
            }
            mt1 = fmaxf(mt1, fmaxf(sacc[j][0], sacc[j][1]));
            mt2 = fmaxf(mt2, fmaxf(sacc[j][2], sacc[j][3]));
        }
        mt1 = fmaxf(mt1, __shfl_xor_sync(0xffffffffu, mt1, 1));
        mt1 = fmaxf(mt1, __shfl_xor_sync(0xffffffffu, mt1, 2));
        mt2 = fmaxf(mt2, __shfl_xor_sync(0xffffffffu, mt2, 1));
        mt2 = fmaxf(mt2, __shfl_xor_sync(0xffffffffu, mt2, 2));
        const float f1 = ex2f(m1s - mt1), f2 = ex2f(m2s - mt2);
        m1s = mt1; m2s = mt2;
        float s1 = 0.f, s2 = 0.f;
        #pragma unroll
        for (int j = 0; j < 8; j++) {
            sacc[j][0] = ex2f(sacc[j][0] - mt1);
            sacc[j][1] = ex2f(sacc[j][1] - mt1);
            sacc[j][2] = ex2f(sacc[j][2] - mt2);
            sacc[j][3] = ex2f(sacc[j][3] - mt2);
            s1 += sacc[j][0] + sacc[j][1];
            s2 += sacc[j][2] + sacc[j][3];
        }
        l1 = l1 * f1 + s1;
        l2 = l2 * f2 + s2;
        #pragma unroll
        for (int nf = 0; nf < 16; nf++) {
            oacc[nf][0] *= f1; oacc[nf][1] *= f1;
            oacc[nf][2] *= f2; oacc[nf][3] *= f2;
        }

        // ---- PV: out += P V (3-term split, dc processed in pairs) ----
        #pragma unroll
        for (int kk = 0; kk < 4; kk++) {
            uint32_t a_h[4], a_l[4];
            #pragma unroll
            for (int half = 0; half < 2; half++) {
                const float p0 = sacc[2 * kk + half][0], p1 = sacc[2 * kk + half][1];
                const float p2 = sacc[2 * kk + half][2], p3 = sacc[2 * kk + half][3];
                const uint32_t h01 = packbf2(p0, p1);
                const uint32_t h23 = packbf2(p2, p3);
                a_h[2 * half]     = h01;
                a_h[2 * half + 1] = h23;
                a_l[2 * half]     = packbf2(p0 - __uint_as_float(h01 << 16),
                                            p1 - __uint_as_float(h01 & 0xffff0000u));
                a_l[2 * half + 1] = packbf2(p2 - __uint_as_float(h23 << 16),
                                            p3 - __uint_as_float(h23 & 0xffff0000u));
            }
            #pragma unroll
            for (int dp = 0; dp < 4; dp++) {    // dc = 2dp, 2dp+1
                uint32_t bvh0[4], bvl0[4], bvh1[4], bvl1[4];
                const uint32_t va0 = kb + 2 * KT_ELE * 2 +
                    (uint32_t)((kk * 16 + (lane & 15)) * AT_LDS + (2 * dp) * 16 + ((lane >> 4) << 3)) * 2;
                const uint32_t va1 = va0 + 32;
                ldsm_x4t(bvh0, va0);
                ldsm_x4t(bvl0, va0 + KT_ELE * 2);
                ldsm_x4t(bvh1, va1);
                ldsm_x4t(bvl1, va1 + KT_ELE * 2);
                // hh
                mma16816(oacc[4 * dp],     a_h, bvh0);
                mma16816(oacc[4 * dp + 1], a_h, bvh0 + 2);
                mma16816(oacc[4 * dp + 2], a_h, bvh1);
                mma16816(oacc[4 * dp + 3], a_h, bvh1 + 2);
                // hl
                mma16816(oacc[4 * dp],     a_h, bvl0);
                mma16816(oacc[4 * dp + 1], a_h, bvl0 + 2);
                mma16816(oacc[4 * dp + 2], a_h, bvl1);
                mma16816(oacc[4 * dp + 3], a_h, bvl1 + 2);
                // lh
                mma16816(oacc[4 * dp],     a_l, bvh0);
                mma16816(oacc[4 * dp + 1], a_l, bvh0 + 2);
                mma16816(oacc[4 * dp + 2], a_l, bvh1);
                mma16816(oacc[4 * dp + 3], a_l, bvh1 + 2);
            }
        }
    }

    // ---- epilogue: /l, * sigmoid(gate), write bf16 hi/lo Ctx ----
    l1 += __shfl_xor_sync(0xffffffffu, l1, 1);
    l1 += __shfl_xor_sync(0xffffffffu, l1, 2);
    l2 += __shfl_xor_sync(0xffffffffu, l2, 1);
    l2 += __shfl_xor_sync(0xffffffffu, l2, 2);
    const float inv1 = 1.0f / l1, inv2 = 1.0f / l2;
    #pragma unroll
    for (int nf = 0; nf < 16; nf++) {
        const int dim = nf * 8 + (lane & 3) * 2;
        #pragma unroll
        for (int rr = 0; rr < 2; rr++) {
            const int q = rr ? r2g : r1g;
            const float invl = rr ? inv2 : inv1;
            const float a0 = oacc[nf][2 * rr], a1 = oacc[nf][2 * rr + 1];
            const float2 gt = *(const float2*)(QG + (((size_t)(b * Sn + q) * Hn + h) * 2 * HD) + HD + dim);
            const float v0 = a0 * invl * (1.0f / (1.0f + expf(-gt.x)));
            const float v1 = a1 * invl * (1.0f / (1.0f + expf(-gt.y)));
            const __nv_bfloat16 h0 = __float2bfloat16(v0);
            const __nv_bfloat16 h1 = __float2bfloat16(v1);
            const size_t off = (size_t)(b * Sn + q) * DOUT + h * HD + dim;
            *(__nv_bfloat162*)(Cxh + off) = __nv_bfloat162(h0, h1);
            *(__nv_bfloat162*)(Cxl + off) =
                __nv_bfloat162(__float2bfloat16(v0 - __bfloat162float(h0)),
                               __float2bfloat16(v1 - __bfloat162float(h1)));
        }
    }
}

// ---------------------------- launcher -------------------------------------
extern "C" void kernel_launch(void* const* d_in, const int* in_sizes, int n_in,
                              void* d_out, int out_size)
{
    const float* x    = (const float*)d_in[0];
    const float* Wq   = (const float*)d_in[1];
    const float* Wk   = (const float*)d_in[2];
    const float* Wv   = (const float*)d_in[3];
    const float* Wo   = (const float*)d_in[4];
    const float* qw   = (const float*)d_in[5];
    const float* kw   = (const float*)d_in[6];
    const float* cosT = (const float*)d_in[7];
    const float* sinT = (const float*)d_in[8];
    float* out = (float*)d_out;

    float *QG, *KV;
    cudaGetSymbolAddress((void**)&QG, g_QG);
    cudaGetSymbolAddress((void**)&KV, g_KV);

    __nv_bfloat16 *Qhp, *Qlp, *Khp, *Klp, *Vhp, *Vlp;
    cudaGetSymbolAddress((void**)&Qhp, g_Qh);
    cudaGetSymbolAddress((void**)&Qlp, g_Ql);
    cudaGetSymbolAddress((void**)&Khp, g_Kh);
    cudaGetSymbolAddress((void**)&Klp, g_Kl);
    cudaGetSymbolAddress((void**)&Vhp, g_Vh);
    cudaGetSymbolAddress((void**)&Vlp, g_Vl);

    __nv_bfloat16 *xh, *xl, *Wqh, *Wql, *Wkvh, *Wkvl, *Woh, *Wol, *Cxh, *Cxl;
    cudaGetSymbolAddress((void**)&xh,   g_xh);
    cudaGetSymbolAddress((void**)&xl,   g_xl);
    cudaGetSymbolAddress((void**)&Wqh,  g_Wqh);
    cudaGetSymbolAddress((void**)&Wql,  g_Wql);
    cudaGetSymbolAddress((void**)&Wkvh, g_Wkvh);
    cudaGetSymbolAddress((void**)&Wkvl, g_Wkvl);
    cudaGetSymbolAddress((void**)&Woh,  g_Woh);
    cudaGetSymbolAddress((void**)&Wol,  g_Wol);
    cudaGetSymbolAddress((void**)&Cxh,  g_Cxh);
    cudaGetSymbolAddress((void**)&Cxl,  g_Cxl);

    cudaFuncSetAttribute(gemm_tc, cudaFuncAttributeMaxDynamicSharedMemorySize, GEMM_SMEM);
    cudaFuncSetAttribute(attn_mma, cudaFuncAttributeMaxDynamicSharedMemorySize, ATT_SMEM);

    const int M = Mrows;          // 4096
    const int NKV = 2 * Gn * HD;  // 1024

    fsplit<<<(M * DIN / 4 + 255) / 256, 256>>>(x, xh, xl, M * DIN);
    tsplit<<<dim3((2 * DOUT) / 32, DIN / 32), dim3(32, 8)>>>(Wq, Wqh, Wql, DIN, 2 * DOUT);
    tsplit<<<dim3((Gn * HD) / 32, DIN / 32), dim3(32, 8)>>>(Wk, Wkvh, Wkvl, DIN, Gn * HD);
    tsplit<<<dim3((Gn * HD) / 32, DIN / 32), dim3(32, 8)>>>(
        Wv, Wkvh + (size_t)(Gn * HD) * DIN, Wkvl + (size_t)(Gn * HD) * DIN, DIN, Gn * HD);
    tsplit<<<dim3(DIN / 32, DOUT / 32), dim3(32, 8)>>>(Wo, Woh, Wol, DOUT, DIN);

    gemm_tc<<<dim3((2 * DOUT) / 128, M / 256), 256, GEMM_SMEM>>>(
        xh, xl, Wqh, Wql, QG, M, 2 * DOUT, DIN);
    gemm_tc<<<dim3(NKV / 128, M / 256), 256, GEMM_SMEM>>>(
        xh, xl, Wkvh, Wkvl, KV, M, NKV, DIN);

    qnorm_rope<<<dim3(Sn, Hn, Bn), 128>>>(QG, qw, cosT, sinT, Qhp, Qlp);
    knorm_rope_vsplit<<<dim3(Sn, Gn, Bn), 128>>>(KV, kw, cosT, sinT,
                                                 Khp, Klp, Vhp, Vlp);

    attn_mma<<<dim3(Sn / 128, Hn, Bn), 256, ATT_SMEM>>>(
        Qhp, Qlp, Khp, Klp, Vhp, Vlp, QG, Cxh, Cxl);

    gemm_tc<<<dim3(DIN / 128, M / 256), 256, GEMM_SMEM>>>(
        Cxh, Cxl, Woh, Wol, out, M, DIN, DOUT);
}

// round 10
// speedup vs baseline: 1.0885x; 1.0029x over previous
#include <cuda_runtime.h>
#include <cuda_bf16.h>
#include <math.h>
#include <stdint.h>

#define Bn    2
#define Sn    2048
#define DIN   2048
#define Hn    16
#define Gn    4
#define HD    128
#define DOUT  2048
#define GROUPn 4          // H / G
#define EPSf  1e-6f
#define Mrows (Bn*Sn)     // 4096
#define NQKV  (2*DOUT + 2*Gn*HD)   // 5120 = Wq(4096) | Wk(512) | Wv(512)

// ---------------- scratch (device globals; no allocation allowed) ----------
__device__ float g_QG  [(size_t)Bn*Sn*Hn*2*HD];   // [b,s,h,2*HD]  (q | gate)
__device__ float g_KV  [(size_t)Bn*Sn*(2*Gn*HD)]; // [b,s, K(512) | V(512)]

// bf16 hi/lo attention operands
__device__ __nv_bfloat16 g_Qh[(size_t)Bn*Hn*Sn*HD];
__device__ __nv_bfloat16 g_Ql[(size_t)Bn*Hn*Sn*HD];
__device__ __nv_bfloat16 g_Kh[(size_t)Bn*Gn*Sn*HD];
__device__ __nv_bfloat16 g_Kl[(size_t)Bn*Gn*Sn*HD];
__device__ __nv_bfloat16 g_Vh[(size_t)Bn*Gn*Sn*HD];
__device__ __nv_bfloat16 g_Vl[(size_t)Bn*Gn*Sn*HD];

// bf16 split scratch for GEMMs
__device__ __nv_bfloat16 g_xh  [(size_t)Mrows*DIN];
__device__ __nv_bfloat16 g_xl  [(size_t)Mrows*DIN];
__device__ __nv_bfloat16 g_Wah [(size_t)NQKV*DIN];   // packed Wq|Wk|Wv, [N][K]
__device__ __nv_bfloat16 g_Wal [(size_t)NQKV*DIN];
__device__ __nv_bfloat16 g_Woh [(size_t)DIN*DOUT];
__device__ __nv_bfloat16 g_Wol [(size_t)DIN*DOUT];
__device__ __nv_bfloat16 g_Cxh [(size_t)Mrows*DOUT];
__device__ __nv_bfloat16 g_Cxl [(size_t)Mrows*DOUT];

// ======================= PTX helpers (compute_103 baseline only) ==========
__device__ __forceinline__ uint32_t smem_u32(const void* p) {
    uint32_t a;
    asm("{ .reg .u64 t; cvta.to.shared.u64 t, %1; cvt.u32.u64 %0, t; }" : "=r"(a) : "l"(p));
    return a;
}
__device__ __forceinline__ void cp16(uint32_t s, const void* g) {
    asm volatile("cp.async.cg.shared.global [%0], [%1], 16;" :: "r"(s), "l"(g));
}
#define CP_COMMIT() asm volatile("cp.async.commit_group;" ::: "memory")
#define CP_WAIT(n)  asm volatile("cp.async.wait_group %0;" :: "n"(n) : "memory")

__device__ __forceinline__ void ldsm_x4(uint32_t* r, uint32_t addr) {
    asm volatile("ldmatrix.sync.aligned.m8n8.x4.shared.b16 {%0,%1,%2,%3}, [%4];"
        : "=r"(r[0]), "=r"(r[1]), "=r"(r[2]), "=r"(r[3]) : "r"(addr));
}
__device__ __forceinline__ void ldsm_x4t(uint32_t* r, uint32_t addr) {
    asm volatile("ldmatrix.sync.aligned.m8n8.x4.trans.shared.b16 {%0,%1,%2,%3}, [%4];"
        : "=r"(r[0]), "=r"(r[1]), "=r"(r[2]), "=r"(r[3]) : "r"(addr));
}
__device__ __forceinline__ void mma16816(float* d, const uint32_t* a, const uint32_t* b) {
    asm volatile(
        "mma.sync.aligned.m16n8k16.row.col.f32.bf16.bf16.f32 "
        "{%0,%1,%2,%3}, {%4,%5,%6,%7}, {%8,%9}, {%0,%1,%2,%3};"
        : "+f"(d[0]), "+f"(d[1]), "+f"(d[2]), "+f"(d[3])
        : "r"(a[0]), "r"(a[1]), "r"(a[2]), "r"(a[3]), "r"(b[0]), "r"(b[1]));
}
__device__ __forceinline__ float ex2f(float x) {
    float r; asm("ex2.approx.f32 %0, %1;" : "=f"(r) : "f"(x)); return r;
}
__device__ __forceinline__ uint32_t packbf2(float lo, float hi) {
    uint32_t r; asm("cvt.rn.bf16x2.f32 %0, %1, %2;" : "=r"(r) : "f"(hi), "f"(lo)); return r;
}

// ======================= split / transpose-split ==========================
__global__ __launch_bounds__(256) void fsplit(const float* __restrict__ in,
                                              __nv_bfloat16* __restrict__ h,
                                              __nv_bfloat16* __restrict__ l, int n)
{
    int i = (blockIdx.x * 256 + threadIdx.x) * 4;
    if (i >= n) return;
    float4 v = *(const float4*)(in + i);
    __nv_bfloat16 h0 = __float2bfloat16(v.x), h1 = __float2bfloat16(v.y);
    __nv_bfloat16 h2 = __float2bfloat16(v.z), h3 = __float2bfloat16(v.w);
    __nv_bfloat16 l0 = __float2bfloat16(v.x - __bfloat162float(h0));
    __nv_bfloat16 l1 = __float2bfloat16(v.y - __bfloat162float(h1));
    __nv_bfloat16 l2 = __float2bfloat16(v.z - __bfloat162float(h2));
    __nv_bfloat16 l3 = __float2bfloat16(v.w - __bfloat162float(h3));
    *(__nv_bfloat162*)(h + i)     = __nv_bfloat162(h0, h1);
    *(__nv_bfloat162*)(h + i + 2) = __nv_bfloat162(h2, h3);
    *(__nv_bfloat162*)(l + i)     = __nv_bfloat162(l0, l1);
    *(__nv_bfloat162*)(l + i + 2) = __nv_bfloat162(l2, l3);
}

// W[K,N] fp32 -> Th/Tl[N,K] bf16 (transpose + split)
__global__ __launch_bounds__(256) void tsplit(const float* __restrict__ W,
                                              __nv_bfloat16* __restrict__ Th,
                                              __nv_bfloat16* __restrict__ Tl,
                                              int K, int N)
{
    __shared__ float t[32][33];
    const int n0 = blockIdx.x * 32, k0 = blockIdx.y * 32;
    const int tx = threadIdx.x, ty = threadIdx.y;  // (32, 8)
    #pragma unroll
    for (int r = 0; r < 4; r++)
        t[ty + r * 8][tx] = W[(size_t)(k0 + ty + r * 8) * N + n0 + tx];
    __syncthreads();
    #pragma unroll
    for (int r = 0; r < 4; r++) {
        int n = n0 + ty + r * 8, k = k0 + tx;
        float v = t[tx][ty + r * 8];
        __nv_bfloat16 h = __float2bfloat16(v);
        __nv_bfloat16 l = __float2bfloat16(v - __bfloat162float(h));
        Th[(size_t)n * K + k] = h;
        Tl[(size_t)n * K + k] = l;
    }
}

// ======================= HMMA split-bf16 GEMM (256x128, 3-stage) ===========
// C[M, N0|N1] = A[M,K] * B^T. Output routed: n-tiles < N0 -> C0 (stride N0),
// else -> C1 (stride N1). A (hi/lo) [M,K], Bt (hi/lo) [N0+N1][K], K-major bf16.
// 256 threads (8 warps as 4m x 2n), warp tile 64x64, K-chunk 32. 1 sync/chunk.
#define GBK    32
#define LDS    40
#define ATILEB (256 * LDS * 2)   // 20480 B
#define BTILEB (128 * LDS * 2)   // 10240 B
#define STAGEB (2 * ATILEB + 2 * BTILEB)  // 61440 B
#define NSTAGE 3
#define GEMM_SMEM (NSTAGE * STAGEB)       // 184320 B
#define OFF_AL  ATILEB
#define OFF_BH  (2 * ATILEB)
#define OFF_BL  (2 * ATILEB + BTILEB)

__device__ __forceinline__ void load_stage(
    uint32_t smb, int stage,
    const __nv_bfloat16* __restrict__ pAh, const __nv_bfloat16* __restrict__ pAl,
    const __nv_bfloat16* __restrict__ pBh, const __nv_bfloat16* __restrict__ pBl,
    int K, int kc, int tid)
{
    const uint32_t sb = smb + stage * STAGEB;
    #pragma unroll
    for (int i = 0; i < 4; i++) {
        const int u = tid + i * 256;
        const int row = u >> 2, col = (u & 3) * 8;
        const uint32_t so = (uint32_t)(row * LDS + col) * 2;
        const size_t g = (size_t)row * K + kc + col;
        cp16(sb + so,          pAh + g);
        cp16(sb + OFF_AL + so, pAl + g);
    }
    #pragma unroll
    for (int i = 0; i < 2; i++) {
        const int u = tid + i * 256;
        const int row = u >> 2, col = (u & 3) * 8;
        const uint32_t so = (uint32_t)(row * LDS + col) * 2;
        const size_t g = (size_t)row * K + kc + col;
        cp16(sb + OFF_BH + so, pBh + g);
        cp16(sb + OFF_BL + so, pBl + g);
    }
}

__global__ __launch_bounds__(256, 1) void gemm_tc(
    const __nv_bfloat16* __restrict__ Ah, const __nv_bfloat16* __restrict__ Al,
    const __nv_bfloat16* __restrict__ Bh, const __nv_bfloat16* __restrict__ Bl,
    float* __restrict__ C0, float* __restrict__ C1,
    int M, int N0, int N1, int K)
{
    extern __shared__ char sm[];
    const uint32_t smb = smem_u32(sm);
    const int tid  = threadIdx.x;
    const int wid  = tid >> 5, lane = tid & 31;
    const int wm   = wid & 3;
    const int wn   = wid >> 2;
    const int mbr  = blockIdx.y * 256, nbr = blockIdx.x * 128;

    // output routing
    float* Cb;
    int Nout, ncol;
    if (nbr < N0) { Cb = C0; Nout = N0; ncol = nbr; }
    else          { Cb = C1; Nout = N1; ncol = nbr - N0; }

    const __nv_bfloat16* pAh = Ah + (size_t)mbr * K;
    const __nv_bfloat16* pAl = Al + (size_t)mbr * K;
    const __nv_bfloat16* pBh = Bh + (size_t)nbr * K;
    const __nv_bfloat16* pBl = Bl + (size_t)nbr * K;

    float acc[4][8][4];
    #pragma unroll
    for (int i = 0; i < 4; i++)
        #pragma unroll
        for (int j = 0; j < 8; j++)
            #pragma unroll
            for (int k = 0; k < 4; k++) acc[i][j][k] = 0.f;

    const uint32_t aoff = (uint32_t)((wm * 64 + (lane & 15)) * LDS + ((lane >> 4) * 8)) * 2;
    const uint32_t boff = (uint32_t)((wn * 64 + (lane & 7) + ((lane >> 4) << 3)) * LDS
                                     + (((lane >> 3) & 1) * 8)) * 2;

    const int NC = K / GBK;
    load_stage(smb, 0, pAh, pAl, pBh, pBl, K, 0, tid);
    CP_COMMIT();
    load_stage(smb, 1, pAh, pAl, pBh, pBl, K, GBK, tid);
    CP_COMMIT();

    int st_idx = 0;
    for (int c = 0; c < NC; c++) {
        if (c + 1 < NC) { CP_WAIT(1); } else { CP_WAIT(0); }
        __syncthreads();
        if (c + 2 < NC) {
            int ns = st_idx + 2; if (ns >= NSTAGE) ns -= NSTAGE;
            load_stage(smb, ns, pAh, pAl, pBh, pBl, K, (c + 2) * GBK, tid);
            CP_COMMIT();
        }

        const uint32_t st = smb + st_idx * STAGEB;
        #pragma unroll
        for (int ks = 0; ks < 2; ks++) {
            const uint32_t kb = ks * 32;
            uint32_t bh[16], bl[16];
            #pragma unroll
            for (int n16 = 0; n16 < 4; n16++) {
                ldsm_x4(bh + 4 * n16, st + OFF_BH + boff + n16 * (16 * LDS * 2) + kb);
                ldsm_x4(bl + 4 * n16, st + OFF_BL + boff + n16 * (16 * LDS * 2) + kb);
            }
            #pragma unroll
            for (int mf = 0; mf < 4; mf++) {
                uint32_t ah[4], al[4];
                ldsm_x4(ah, st + aoff + mf * (16 * LDS * 2) + kb);
                ldsm_x4(al, st + OFF_AL + aoff + mf * (16 * LDS * 2) + kb);
                #pragma unroll
                for (int nf = 0; nf < 8; nf++)
                    mma16816(acc[mf][nf], ah, &bh[(nf >> 1) * 4 + (nf & 1) * 2]);
                #pragma unroll
                for (int nf = 0; nf < 8; nf++)
                    mma16816(acc[mf][nf], ah, &bl[(nf >> 1) * 4 + (nf & 1) * 2]);
                #pragma unroll
                for (int nf = 0; nf < 8; nf++)
                    mma16816(acc[mf][nf], al, &bh[(nf >> 1) * 4 + (nf & 1) * 2]);
            }
        }
        if (++st_idx == NSTAGE) st_idx = 0;
    }

    #pragma unroll
    for (int mf = 0; mf < 4; mf++) {
        const int r0 = mbr + wm * 64 + mf * 16 + (lane >> 2);
        #pragma unroll
        for (int nf = 0; nf < 8; nf++) {
            const int n0 = ncol + wn * 64 + nf * 8 + (lane & 3) * 2;
            *(float2*)(Cb + (size_t)r0 * Nout + n0)       = make_float2(acc[mf][nf][0], acc[mf][nf][1]);
            *(float2*)(Cb + (size_t)(r0 + 8) * Nout + n0) = make_float2(acc[mf][nf][2], acc[mf][nf][3]);
        }
    }
}

// ---------------- rmsnorm + rope for Q -> bf16 hi/lo -----------------------
__global__ __launch_bounds__(128) void qnorm_rope(
    const float* __restrict__ QG, const float* __restrict__ w,
    const float* __restrict__ cosT, const float* __restrict__ sinT,
    __nv_bfloat16* __restrict__ Qh, __nv_bfloat16* __restrict__ Ql)
{
    const int s = blockIdx.x, h = blockIdx.y, b = blockIdx.z;
    const int d = threadIdx.x;
    const float* src = QG + (((size_t)(b * Sn + s) * Hn + h) * 2 * HD);
    float x = src[d];
    float ss = x * x;
    #pragma unroll
    for (int o = 16; o > 0; o >>= 1) ss += __shfl_xor_sync(0xffffffffu, ss, o);
    __shared__ float wsum[4];
    if ((d & 31) == 0) wsum[d >> 5] = ss;
    __syncthreads();
    float tot = wsum[0] + wsum[1] + wsum[2] + wsum[3];
    float inv = rsqrtf(tot * (1.0f / HD) + EPSf);
    float n = x * inv * (1.0f + w[d]);
    __shared__ float nb[HD];
    nb[d] = n;
    __syncthreads();
    float c  = cosT[(size_t)s * HD + d];
    float sn = sinT[(size_t)s * HD + d];
    float rot = (d < HD / 2) ? -nb[d + HD / 2] : nb[d - HD / 2];
    float y = n * c + rot * sn;
    __nv_bfloat16 hh = __float2bfloat16(y);
    const size_t dst = ((size_t)(b * Hn + h) * Sn + s) * HD + d;
    Qh[dst] = hh;
    Ql[dst] = __float2bfloat16(y - __bfloat162float(hh));
}

// ---------------- rmsnorm + rope for K -> hi/lo, plus V split --------------
__global__ __launch_bounds__(128) void knorm_rope_vsplit(
    const float* __restrict__ KV,
    const float* __restrict__ w,
    const float* __restrict__ cosT, const float* __restrict__ sinT,
    __nv_bfloat16* __restrict__ Kh, __nv_bfloat16* __restrict__ Kl,
    __nv_bfloat16* __restrict__ Vh, __nv_bfloat16* __restrict__ Vl)
{
    const int s = blockIdx.x, g = blockIdx.y, b = blockIdx.z;
    const int d = threadIdx.x;
    const float* row = KV + (size_t)(b * Sn + s) * (2 * Gn * HD) + g * HD;
    float x = row[d];
    float ss = x * x;
    #pragma unroll
    for (int o = 16; o > 0; o >>= 1) ss += __shfl_xor_sync(0xffffffffu, ss, o);
    __shared__ float wsum[4];
    if ((d & 31) == 0) wsum[d >> 5] = ss;
    __syncthreads();
    float tot = wsum[0] + wsum[1] + wsum[2] + wsum[3];
    float inv = rsqrtf(tot * (1.0f / HD) + EPSf);
    float n = x * inv * (1.0f + w[d]);
    __shared__ float nb[HD];
    nb[d] = n;
    __syncthreads();
    float c  = cosT[(size_t)s * HD + d];
    float sn = sinT[(size_t)s * HD + d];
    float rot = (d < HD / 2) ? -nb[d + HD / 2] : nb[d - HD / 2];
    float y = n * c + rot * sn;
    const size_t dst = ((size_t)(b * Gn + g) * Sn + s) * HD + d;
    __nv_bfloat16 kh = __float2bfloat16(y);
    Kh[dst] = kh;
    Kl[dst] = __float2bfloat16(y - __bfloat162float(kh));
    float v = row[Gn * HD + d];
    __nv_bfloat16 vh = __float2bfloat16(v);
    Vh[dst] = vh;
    Vl[dst] = __float2bfloat16(v - __bfloat162float(vh));
}

// ================= HMMA causal flash attention + sigmoid gate ==============
// BQ=128 (8 warps x m16), BK=64, HD=128. 3-term split on QK^T and PV.
// Q-hi fragments cached in registers for the whole KV loop (Q-lo via ldsm).
// Single __syncthreads per tile. Epilogue writes bf16 hi/lo Ctx (fused fsplit).
#define AT_LDS  136
#define Q_ELE   (128 * AT_LDS)
#define KT_ELE  (64 * AT_LDS)
#define KVSTAGE_ELE (4 * KT_ELE)
#define ATT_SMEM ((2 * Q_ELE + 2 * KVSTAGE_ELE) * 2)   // 208896 bytes
#define CSC 0.12751666806979654f    // (1/sqrt(128)) * log2(e)
#define NEGINF __int_as_float(0xff800000)

__device__ __forceinline__ void kv_load(
    uint32_t smb, int stage,
    const __nv_bfloat16* kh, const __nv_bfloat16* kl,
    const __nv_bfloat16* vh, const __nv_bfloat16* vl, int tid)
{
    const uint32_t base = smb + (2 * Q_ELE + stage * KVSTAGE_ELE) * 2;
    #pragma unroll
    for (int i = 0; i < 4; i++) {
        int u = tid + i * 256;          // 0..1023
        int row = u >> 4, c8 = (u & 15) * 8;
        uint32_t so = (uint32_t)(row * AT_LDS + c8) * 2;
        size_t go = (size_t)row * HD + c8;
        cp16(base + 0 * KT_ELE * 2 + so, kh + go);
        cp16(base + 1 * KT_ELE * 2 + so, kl + go);
        cp16(base + 2 * KT_ELE * 2 + so, vh + go);
        cp16(base + 3 * KT_ELE * 2 + so, vl + go);
    }
}

__global__ __launch_bounds__(256, 1) void attn_mma(
    const __nv_bfloat16* __restrict__ Qh, const __nv_bfloat16* __restrict__ Ql,
    const __nv_bfloat16* __restrict__ Kh, const __nv_bfloat16* __restrict__ Kl,
    const __nv_bfloat16* __restrict__ Vh, const __nv_bfloat16* __restrict__ Vl,
    const float* __restrict__ QG,
    __nv_bfloat16* __restrict__ Cxh, __nv_bfloat16* __restrict__ Cxl)
{
    extern __shared__ __nv_bfloat16 smem_bf[];
    const uint32_t smb = smem_u32(smem_bf);
    const int qi = blockIdx.x, h = blockIdx.y, b = blockIdx.z;
    const int g  = h / GROUPn;
    const int tid = threadIdx.x, lane = tid & 31, w = tid >> 5;

    const __nv_bfloat16* gQh = Qh + ((size_t)(b * Hn + h) * Sn + (size_t)qi * 128) * HD;
    const __nv_bfloat16* gQl = Ql + ((size_t)(b * Hn + h) * Sn + (size_t)qi * 128) * HD;
    const __nv_bfloat16* gKh = Kh + ((size_t)(b * Gn + g) * Sn) * HD;
    const __nv_bfloat16* gKl = Kl + ((size_t)(b * Gn + g) * Sn) * HD;
    const __nv_bfloat16* gVh = Vh + ((size_t)(b * Gn + g) * Sn) * HD;
    const __nv_bfloat16* gVl = Vl + ((size_t)(b * Gn + g) * Sn) * HD;

    // load Q hi/lo into smem (128 x 128)
    #pragma unroll
    for (int i = 0; i < 8; i++) {
        int u = tid + i * 256;
        int row = u >> 4, c8 = (u & 15) * 8;
        *(uint4*)(smem_bf + row * AT_LDS + c8)         = *(const uint4*)(gQh + (size_t)row * HD + c8);
        *(uint4*)(smem_bf + Q_ELE + row * AT_LDS + c8) = *(const uint4*)(gQl + (size_t)row * HD + c8);
    }

    float m1s = NEGINF, m2s = NEGINF, l1 = 0.f, l2 = 0.f;
    float oacc[16][4];
    #pragma unroll
    for (int nf = 0; nf < 16; nf++)
        #pragma unroll
        for (int k = 0; k < 4; k++) oacc[nf][k] = 0.f;

    const int r1rel = w * 16 + (lane >> 2);   // 0..127
    const int r1g = qi * 128 + r1rel;
    const int r2g = r1g + 8;

    kv_load(smb, 0, gKh, gKl, gVh, gVl, tid);
    CP_COMMIT();
    CP_WAIT(0);
    __syncthreads();   // Q smem + KV stage0 ready

    // cache Q-hi fragments in registers for the whole loop
    uint32_t qh_fr[8][4];
    #pragma unroll
    for (int kq = 0; kq < 8; kq++) {
        const uint32_t qaddr = smb +
            (uint32_t)((w * 16 + (lane & 15)) * AT_LDS + ((lane >> 4) << 3) + kq * 16) * 2;
        ldsm_x4(qh_fr[kq], qaddr);
    }

    const int ntiles = 2 * qi + 2;
    for (int t = 0; t < ntiles; t++) {
        if (t > 0) {
            CP_WAIT(0);
            __syncthreads();  // stage (t&1) ready AND all warps done with it from t-2
        }
        if (t + 1 < ntiles) {
            kv_load(smb, (t + 1) & 1,
                    gKh + (size_t)(t + 1) * 64 * HD, gKl + (size_t)(t + 1) * 64 * HD,
                    gVh + (size_t)(t + 1) * 64 * HD, gVl + (size_t)(t + 1) * 64 * HD, tid);
            CP_COMMIT();
        }

        const uint32_t kb = smb + (2 * Q_ELE + (t & 1) * KVSTAGE_ELE) * 2;

        // ---- scores: S = Q K^T (3-term split, term-major, Q-hi in regs) ----
        float sacc[8][4];
        #pragma unroll
        for (int j = 0; j < 8; j++)
            #pragma unroll
            for (int k = 0; k < 4; k++) sacc[j][k] = 0.f;

        #pragma unroll
        for (int kq = 0; kq < 8; kq++) {
            uint32_t al[4], bh[16], bl[16];
            const uint32_t qaddr = smb +
                (uint32_t)((w * 16 + (lane & 15)) * AT_LDS + ((lane >> 4) << 3) + kq * 16) * 2;
            ldsm_x4(al, qaddr + Q_ELE * 2);
            #pragma unroll
            for (int n16 = 0; n16 < 4; n16++) {
                const uint32_t kaddr = kb +
                    (uint32_t)((n16 * 16 + (lane & 7) + ((lane >> 4) << 3)) * AT_LDS
                               + (((lane >> 3) & 1) << 3) + kq * 16) * 2;
                ldsm_x4(bh + 4 * n16, kaddr);
                ldsm_x4(bl + 4 * n16, kaddr + KT_ELE * 2);
            }
            #pragma unroll
            for (int n16 = 0; n16 < 4; n16++) {
                mma16816(sacc[2 * n16],     qh_fr[kq], bh + 4 * n16);
                mma16816(sacc[2 * n16 + 1], qh_fr[kq], bh + 4 * n16 + 2);
            }
            #pragma unroll
            for (int n16 = 0; n16 < 4; n16++) {
                mma16816(sacc[2 * n16],     qh_fr[kq], bl + 4 * n16);
                mma16816(sacc[2 * n16 + 1], qh_fr[kq], bl + 4 * n16 + 2);
            }
            #pragma unroll
            for (int n16 = 0; n16 < 4; n16++) {
                mma16816(sacc[2 * n16],     al, bh + 4 * n16);
                mma16816(sacc[2 * n16 + 1], al, bh + 4 * n16 + 2);
            }
        }

        // ---- online softmax (log2 domain) ----
        const bool needmask = (t >= 2 * qi);
        float mt1 = m1s, mt2 = m2s;
        #pragma unroll
        for (int j = 0; j < 8; j++) {
            const int c0 = t * 64 + j * 8 + (lane & 3) * 2;
            #pragma unroll
            for (int k = 0; k < 4; k++) sacc[j][k] *= CSC;
            if (needmask) {
                if (c0     > r1g) sacc[j][0] = NEGINF;
                if (c0 + 1 > r1g) sacc[j][1] = NEGINF;
                if (c0     > r2g) sacc[j][2] = NEGINF;
                if (c0 + 1 > r2g) sacc[j][3] = NEGINF;
            }
            mt1 = fmaxf(mt1, fmaxf(sacc[j][0], sacc[j][1]));
            mt2 = fmaxf(mt2, fmaxf(sacc[j][2], sacc[j][3]));
        }
        mt1 = fmaxf(mt1, __shfl_xor_sync(0xffffffffu, mt1, 1));
        mt1 = fmaxf(mt1, __shfl_xor_sync(0xffffffffu, mt1, 2));
        mt2 = fmaxf(mt2, __shfl_xor_sync(0xffffffffu, mt2, 1));
        mt2 = fmaxf(mt2, __shfl_xor_sync(0xffffffffu, mt2, 2));
        const float f1 = ex2f(m1s - mt1), f2 = ex2f(m2s - mt2);
        m1s = mt1; m2s = mt2;
        float s1 = 0.f, s2 = 0.f;
        #pragma unroll
        for (int j = 0; j < 8; j++) {
            sacc[j][0] = ex2f(sacc[j][0] - mt1);
            sacc[j][1] = ex2f(sacc[j][1] - mt1);
            sacc[j][2] = ex2f(sacc[j][2] - mt2);
            sacc[j][3] = ex2f(sacc[j][3] - mt2);
            s1 += sacc[j][0] + sacc[j][1];
            s2 += sacc[j][2] + sacc[j][3];
        }
        l1 = l1 * f1 + s1;
        l2 = l2 * f2 + s2;
        #pragma unroll
        for (int nf = 0; nf < 16; nf++) {
            oacc[nf][0] *= f1; oacc[nf][1] *= f1;
            oacc[nf][2] *= f2; oacc[nf][3] *= f2;
        }

        // ---- PV: out += P V (3-term split, dc processed in pairs) ----
        #pragma unroll
        for (int kk = 0; kk < 4; kk++) {
            uint32_t a_h[4], a_l[4];
            #pragma unroll
            for (int half = 0; half < 2; half++) {
                const float p0 = sacc[2 * kk + half][0], p1 = sacc[2 * kk + half][1];
                const float p2 = sacc[2 * kk + half][2], p3 = sacc[2 * kk + half][3];
                const uint32_t h01 = packbf2(p0, p1);
                const uint32_t h23 = packbf2(p2, p3);
                a_h[2 * half]     = h01;
                a_h[2 * half + 1] = h23;
                a_l[2 * half]     = packbf2(p0 - __uint_as_float(h01 << 16),
                                            p1 - __uint_as_float(h01 & 0xffff0000u));
                a_l[2 * half + 1] = packbf2(p2 - __uint_as_float(h23 << 16),
                                            p3 - __uint_as_float(h23 & 0xffff0000u));
            }
            #pragma unroll
            for (int dp = 0; dp < 4; dp++) {    // dc = 2dp, 2dp+1
                uint32_t bvh0[4], bvl0[4], bvh1[4], bvl1[4];
                const uint32_t va0 = kb + 2 * KT_ELE * 2 +
                    (uint32_t)((kk * 16 + (lane & 15)) * AT_LDS + (2 * dp) * 16 + ((lane >> 4) << 3)) * 2;
                const uint32_t va1 = va0 + 32;
                ldsm_x4t(bvh0, va0);
                ldsm_x4t(bvl0, va0 + KT_ELE * 2);
                ldsm_x4t(bvh1, va1);
                ldsm_x4t(bvl1, va1 + KT_ELE * 2);
                // hh
                mma16816(oacc[4 * dp],     a_h, bvh0);
                mma16816(oacc[4 * dp + 1], a_h, bvh0 + 2);
                mma16816(oacc[4 * dp + 2], a_h, bvh1);
                mma16816(oacc[4 * dp + 3], a_h, bvh1 + 2);
                // hl
                mma16816(oacc[4 * dp],     a_h, bvl0);
                mma16816(oacc[4 * dp + 1], a_h, bvl0 + 2);
                mma16816(oacc[4 * dp + 2], a_h, bvl1);
                mma16816(oacc[4 * dp + 3], a_h, bvl1 + 2);
                // lh
                mma16816(oacc[4 * dp],     a_l, bvh0);
                mma16816(oacc[4 * dp + 1], a_l, bvh0 + 2);
                mma16816(oacc[4 * dp + 2], a_l, bvh1);
                mma16816(oacc[4 * dp + 3], a_l, bvh1 + 2);
            }
        }
    }

    // ---- epilogue: /l, * sigmoid(gate), write bf16 hi/lo Ctx ----
    l1 += __shfl_xor_sync(0xffffffffu, l1, 1);
    l1 += __shfl_xor_sync(0xffffffffu, l1, 2);
    l2 += __shfl_xor_sync(0xffffffffu, l2, 1);
    l2 += __shfl_xor_sync(0xffffffffu, l2, 2);
    const float inv1 = 1.0f / l1, inv2 = 1.0f / l2;
    #pragma unroll
    for (int nf = 0; nf < 16; nf++) {
        const int dim = nf * 8 + (lane & 3) * 2;
        #pragma unroll
        for (int rr = 0; rr < 2; rr++) {
            const int q = rr ? r2g : r1g;
            const float invl = rr ? inv2 : inv1;
            const float a0 = oacc[nf][2 * rr], a1 = oacc[nf][2 * rr + 1];
            const float2 gt = *(const float2*)(QG + (((size_t)(b * Sn + q) * Hn + h) * 2 * HD) + HD + dim);
            const float v0 = a0 * invl * (1.0f / (1.0f + expf(-gt.x)));
            const float v1 = a1 * invl * (1.0f / (1.0f + expf(-gt.y)));
            const __nv_bfloat16 h0 = __float2bfloat16(v0);
            const __nv_bfloat16 h1 = __float2bfloat16(v1);
            const size_t off = (size_t)(b * Sn + q) * DOUT + h * HD + dim;
            *(__nv_bfloat162*)(Cxh + off) = __nv_bfloat162(h0, h1);
            *(__nv_bfloat162*)(Cxl + off) =
                __nv_bfloat162(__float2bfloat16(v0 - __bfloat162float(h0)),
                               __float2bfloat16(v1 - __bfloat162float(h1)));
        }
    }
}

// ---------------------------- launcher -------------------------------------
extern "C" void kernel_launch(void* const* d_in, const int* in_sizes, int n_in,
                              void* d_out, int out_size)
{
    const float* x    = (const float*)d_in[0];
    const float* Wq   = (const float*)d_in[1];
    const float* Wk   = (const float*)d_in[2];
    const float* Wv   = (const float*)d_in[3];
    const float* Wo   = (const float*)d_in[4];
    const float* qw   = (const float*)d_in[5];
    const float* kw   = (const float*)d_in[6];
    const float* cosT = (const float*)d_in[7];
    const float* sinT = (const float*)d_in[8];
    float* out = (float*)d_out;

    float *QG, *KV;
    cudaGetSymbolAddress((void**)&QG, g_QG);
    cudaGetSymbolAddress((void**)&KV, g_KV);

    __nv_bfloat16 *Qhp, *Qlp, *Khp, *Klp, *Vhp, *Vlp;
    cudaGetSymbolAddress((void**)&Qhp, g_Qh);
    cudaGetSymbolAddress((void**)&Qlp, g_Ql);
    cudaGetSymbolAddress((void**)&Khp, g_Kh);
    cudaGetSymbolAddress((void**)&Klp, g_Kl);
    cudaGetSymbolAddress((void**)&Vhp, g_Vh);
    cudaGetSymbolAddress((void**)&Vlp, g_Vl);

    __nv_bfloat16 *xh, *xl, *Wah, *Wal, *Woh, *Wol, *Cxh, *Cxl;
    cudaGetSymbolAddress((void**)&xh,  g_xh);
    cudaGetSymbolAddress((void**)&xl,  g_xl);
    cudaGetSymbolAddress((void**)&Wah, g_Wah);
    cudaGetSymbolAddress((void**)&Wal, g_Wal);
    cudaGetSymbolAddress((void**)&Woh, g_Woh);
    cudaGetSymbolAddress((void**)&Wol, g_Wol);
    cudaGetSymbolAddress((void**)&Cxh, g_Cxh);
    cudaGetSymbolAddress((void**)&Cxl, g_Cxl);

    cudaFuncSetAttribute(gemm_tc, cudaFuncAttributeMaxDynamicSharedMemorySize, GEMM_SMEM);
    cudaFuncSetAttribute(attn_mma, cudaFuncAttributeMaxDynamicSharedMemorySize, ATT_SMEM);

    const int M = Mrows;          // 4096
    const int NKV = 2 * Gn * HD;  // 1024

    // (1) split x; (2-4) transpose+split Wq|Wk|Wv into packed buffer
    fsplit<<<(M * DIN / 4 + 255) / 256, 256>>>(x, xh, xl, M * DIN);
    tsplit<<<dim3((2 * DOUT) / 32, DIN / 32), dim3(32, 8)>>>(Wq, Wah, Wal, DIN, 2 * DOUT);
    tsplit<<<dim3((Gn * HD) / 32, DIN / 32), dim3(32, 8)>>>(
        Wk, Wah + (size_t)(2 * DOUT) * DIN, Wal + (size_t)(2 * DOUT) * DIN, DIN, Gn * HD);
    tsplit<<<dim3((Gn * HD) / 32, DIN / 32), dim3(32, 8)>>>(
        Wv, Wah + (size_t)(2 * DOUT + Gn * HD) * DIN, Wal + (size_t)(2 * DOUT + Gn * HD) * DIN,
        DIN, Gn * HD);

    // (5) merged QKV projection  [profiled launch]
    gemm_tc<<<dim3(NQKV / 128, M / 256), 256, GEMM_SMEM>>>(
        xh, xl, Wah, Wal, QG, KV, M, 2 * DOUT, NKV, DIN);

    // (6) Wo transpose+split
    tsplit<<<dim3(DIN / 32, DOUT / 32), dim3(32, 8)>>>(Wo, Woh, Wol, DOUT, DIN);

    // (7-8) norm + rope -> bf16 hi/lo
    qnorm_rope<<<dim3(Sn, Hn, Bn), 128>>>(QG, qw, cosT, sinT, Qhp, Qlp);
    knorm_rope_vsplit<<<dim3(Sn, Gn, Bn), 128>>>(KV, kw, cosT, sinT,
                                                 Khp, Klp, Vhp, Vlp);

    // (9) HMMA causal attention + gate, fused bf16 split epilogue
    attn_mma<<<dim3(Sn / 128, Hn, Bn), 256, ATT_SMEM>>>(
        Qhp, Qlp, Khp, Klp, Vhp, Vlp, QG, Cxh, Cxl);

    // (10) output projection
    gemm_tc<<<dim3(DIN / 128, M / 256), 256, GEMM_SMEM>>>(
        Cxh, Cxl, Woh, Wol, out, (float*)nullptr, M, DIN, 0, DOUT);
}

// round 11
// speedup vs baseline: 1.1969x; 1.0996x over previous
#include <cuda_runtime.h>
#include <cuda_bf16.h>
#include <math.h>
#include <stdint.h>

#define Bn    2
#define Sn    2048
#define DIN   2048
#define Hn    16
#define Gn    4
#define HD    128
#define DOUT  2048
#define GROUPn 4          // H / G
#define EPSf  1e-6f
#define Mrows (Bn*Sn)     // 4096
#define NQKV  (2*DOUT + 2*Gn*HD)   // 5120 = Wq(4096) | Wk(512) | Wv(512)

// ---------------- scratch (device globals; no allocation allowed) ----------
__device__ float g_QG  [(size_t)Bn*Sn*Hn*2*HD];   // [b,s,h,2*HD]  (q | gate)
__device__ float g_KV  [(size_t)Bn*Sn*(2*Gn*HD)]; // [b,s, K(512) | V(512)]

// bf16 hi/lo attention operands
__device__ __nv_bfloat16 g_Qh[(size_t)Bn*Hn*Sn*HD];
__device__ __nv_bfloat16 g_Ql[(size_t)Bn*Hn*Sn*HD];
__device__ __nv_bfloat16 g_Kh[(size_t)Bn*Gn*Sn*HD];
__device__ __nv_bfloat16 g_Kl[(size_t)Bn*Gn*Sn*HD];
__device__ __nv_bfloat16 g_Vh[(size_t)Bn*Gn*Sn*HD];
__device__ __nv_bfloat16 g_Vl[(size_t)Bn*Gn*Sn*HD];

// bf16 split scratch for GEMMs
__device__ __nv_bfloat16 g_xh  [(size_t)Mrows*DIN];
__device__ __nv_bfloat16 g_xl  [(size_t)Mrows*DIN];
__device__ __nv_bfloat16 g_Wah [(size_t)NQKV*DIN];   // packed Wq|Wk|Wv, [N][K]
__device__ __nv_bfloat16 g_Wal [(size_t)NQKV*DIN];
__device__ __nv_bfloat16 g_Woh [(size_t)DIN*DOUT];
__device__ __nv_bfloat16 g_Wol [(size_t)DIN*DOUT];
__device__ __nv_bfloat16 g_Cxh [(size_t)Mrows*DOUT];
__device__ __nv_bfloat16 g_Cxl [(size_t)Mrows*DOUT];

// ======================= PTX helpers (compute_103 baseline only) ==========
__device__ __forceinline__ uint32_t smem_u32(const void* p) {
    uint32_t a;
    asm("{ .reg .u64 t; cvta.to.shared.u64 t, %1; cvt.u32.u64 %0, t; }" : "=r"(a) : "l"(p));
    return a;
}
__device__ __forceinline__ void cp16(uint32_t s, const void* g) {
    asm volatile("cp.async.cg.shared.global [%0], [%1], 16;" :: "r"(s), "l"(g));
}
#define CP_COMMIT() asm volatile("cp.async.commit_group;" ::: "memory")
#define CP_WAIT(n)  asm volatile("cp.async.wait_group %0;" :: "n"(n) : "memory")

__device__ __forceinline__ void ldsm_x4(uint32_t* r, uint32_t addr) {
    asm volatile("ldmatrix.sync.aligned.m8n8.x4.shared.b16 {%0,%1,%2,%3}, [%4];"
        : "=r"(r[0]), "=r"(r[1]), "=r"(r[2]), "=r"(r[3]) : "r"(addr));
}
__device__ __forceinline__ void ldsm_x4t(uint32_t* r, uint32_t addr) {
    asm volatile("ldmatrix.sync.aligned.m8n8.x4.trans.shared.b16 {%0,%1,%2,%3}, [%4];"
        : "=r"(r[0]), "=r"(r[1]), "=r"(r[2]), "=r"(r[3]) : "r"(addr));
}
__device__ __forceinline__ void mma16816(float* d, const uint32_t* a, const uint32_t* b) {
    asm volatile(
        "mma.sync.aligned.m16n8k16.row.col.f32.bf16.bf16.f32 "
        "{%0,%1,%2,%3}, {%4,%5,%6,%7}, {%8,%9}, {%0,%1,%2,%3};"
        : "+f"(d[0]), "+f"(d[1]), "+f"(d[2]), "+f"(d[3])
        : "r"(a[0]), "r"(a[1]), "r"(a[2]), "r"(a[3]), "r"(b[0]), "r"(b[1]));
}
__device__ __forceinline__ float ex2f(float x) {
    float r; asm("ex2.approx.f32 %0, %1;" : "=f"(r) : "f"(x)); return r;
}
__device__ __forceinline__ uint32_t packbf2(float lo, float hi) {
    uint32_t r; asm("cvt.rn.bf16x2.f32 %0, %1, %2;" : "=r"(r) : "f"(hi), "f"(lo)); return r;
}

// ======================= split / transpose-split ==========================
__global__ __launch_bounds__(256) void fsplit(const float* __restrict__ in,
                                              __nv_bfloat16* __restrict__ h,
                                              __nv_bfloat16* __restrict__ l, int n)
{
    int i = (blockIdx.x * 256 + threadIdx.x) * 4;
    if (i >= n) return;
    float4 v = *(const float4*)(in + i);
    __nv_bfloat16 h0 = __float2bfloat16(v.x), h1 = __float2bfloat16(v.y);
    __nv_bfloat16 h2 = __float2bfloat16(v.z), h3 = __float2bfloat16(v.w);
    __nv_bfloat16 l0 = __float2bfloat16(v.x - __bfloat162float(h0));
    __nv_bfloat16 l1 = __float2bfloat16(v.y - __bfloat162float(h1));
    __nv_bfloat16 l2 = __float2bfloat16(v.z - __bfloat162float(h2));
    __nv_bfloat16 l3 = __float2bfloat16(v.w - __bfloat162float(h3));
    *(__nv_bfloat162*)(h + i)     = __nv_bfloat162(h0, h1);
    *(__nv_bfloat162*)(h + i + 2) = __nv_bfloat162(h2, h3);
    *(__nv_bfloat162*)(l + i)     = __nv_bfloat162(l0, l1);
    *(__nv_bfloat162*)(l + i + 2) = __nv_bfloat162(l2, l3);
}

// W[K,N] fp32 -> Th/Tl[N,K] bf16 (transpose + split)
__global__ __launch_bounds__(256) void tsplit(const float* __restrict__ W,
                                              __nv_bfloat16* __restrict__ Th,
                                              __nv_bfloat16* __restrict__ Tl,
                                              int K, int N)
{
    __shared__ float t[32][33];
    const int n0 = blockIdx.x * 32, k0 = blockIdx.y * 32;
    const int tx = threadIdx.x, ty = threadIdx.y;  // (32, 8)
    #pragma unroll
    for (int r = 0; r < 4; r++)
        t[ty + r * 8][tx] = W[(size_t)(k0 + ty + r * 8) * N + n0 + tx];
    __syncthreads();
    #pragma unroll
    for (int r = 0; r < 4; r++) {
        int n = n0 + ty + r * 8, k = k0 + tx;
        float v = t[tx][ty + r * 8];
        __nv_bfloat16 h = __float2bfloat16(v);
        __nv_bfloat16 l = __float2bfloat16(v - __bfloat162float(h));
        Th[(size_t)n * K + k] = h;
        Tl[(size_t)n * K + k] = l;
    }
}

// ======================= HMMA split-bf16 GEMM (256x128, 3-stage) ===========
// C[M, N0|N1] = A[M,K] * B^T. Output routed: n-tiles < N0 -> C0 (stride N0),
// else -> C1 (stride N1). A (hi/lo) [M,K], Bt (hi/lo) [N0+N1][K], K-major bf16.
// 256 threads (8 warps as 4m x 2n), warp tile 64x64, K-chunk 32. 1 sync/chunk.
// enable_gate: odd 128-tiles within [0,N0) are sigmoid-gate columns -> 1-term.
#define GBK    32
#define LDS    40
#define ATILEB (256 * LDS * 2)   // 20480 B
#define BTILEB (128 * LDS * 2)   // 10240 B
#define STAGEB (2 * ATILEB + 2 * BTILEB)  // 61440 B
#define NSTAGE 3
#define GEMM_SMEM (NSTAGE * STAGEB)       // 184320 B
#define OFF_AL  ATILEB
#define OFF_BH  (2 * ATILEB)
#define OFF_BL  (2 * ATILEB + BTILEB)

__device__ __forceinline__ void load_stage(
    uint32_t smb, int stage,
    const __nv_bfloat16* __restrict__ pAh, const __nv_bfloat16* __restrict__ pAl,
    const __nv_bfloat16* __restrict__ pBh, const __nv_bfloat16* __restrict__ pBl,
    int K, int kc, int tid, bool skip_bl)
{
    const uint32_t sb = smb + stage * STAGEB;
    #pragma unroll
    for (int i = 0; i < 4; i++) {
        const int u = tid + i * 256;
        const int row = u >> 2, col = (u & 3) * 8;
        const uint32_t so = (uint32_t)(row * LDS + col) * 2;
        const size_t g = (size_t)row * K + kc + col;
        cp16(sb + so,          pAh + g);
        cp16(sb + OFF_AL + so, pAl + g);
    }
    #pragma unroll
    for (int i = 0; i < 2; i++) {
        const int u = tid + i * 256;
        const int row = u >> 2, col = (u & 3) * 8;
        const uint32_t so = (uint32_t)(row * LDS + col) * 2;
        const size_t g = (size_t)row * K + kc + col;
        cp16(sb + OFF_BH + so, pBh + g);
        if (!skip_bl) cp16(sb + OFF_BL + so, pBl + g);
    }
}

__global__ __launch_bounds__(256, 1) void gemm_tc(
    const __nv_bfloat16* __restrict__ Ah, const __nv_bfloat16* __restrict__ Al,
    const __nv_bfloat16* __restrict__ Bh, const __nv_bfloat16* __restrict__ Bl,
    float* __restrict__ C0, float* __restrict__ C1,
    int M, int N0, int N1, int K, int enable_gate)
{
    extern __shared__ char sm[];
    const uint32_t smb = smem_u32(sm);
    const int tid  = threadIdx.x;
    const int wid  = tid >> 5, lane = tid & 31;
    const int wm   = wid & 3;
    const int wn   = wid >> 2;
    const int mbr  = blockIdx.y * 256, nbr = blockIdx.x * 128;

    // output routing
    float* Cb;
    int Nout, ncol;
    if (nbr < N0) { Cb = C0; Nout = N0; ncol = nbr; }
    else          { Cb = C1; Nout = N1; ncol = nbr - N0; }
    // gate tiles: odd 128-tile within the Wq region -> 1-term (hh only)
    const bool gate = enable_gate && (nbr < N0) && ((nbr >> 7) & 1);

    const __nv_bfloat16* pAh = Ah + (size_t)mbr * K;
    const __nv_bfloat16* pAl = Al + (size_t)mbr * K;
    const __nv_bfloat16* pBh = Bh + (size_t)nbr * K;
    const __nv_bfloat16* pBl = Bl + (size_t)nbr * K;

    float acc[4][8][4];
    #pragma unroll
    for (int i = 0; i < 4; i++)
        #pragma unroll
        for (int j = 0; j < 8; j++)
            #pragma unroll
            for (int k = 0; k < 4; k++) acc[i][j][k] = 0.f;

    const uint32_t aoff = (uint32_t)((wm * 64 + (lane & 15)) * LDS + ((lane >> 4) * 8)) * 2;
    const uint32_t boff = (uint32_t)((wn * 64 + (lane & 7) + ((lane >> 4) << 3)) * LDS
                                     + (((lane >> 3) & 1) * 8)) * 2;

    const int NC = K / GBK;
    load_stage(smb, 0, pAh, pAl, pBh, pBl, K, 0, tid, gate);
    CP_COMMIT();
    load_stage(smb, 1, pAh, pAl, pBh, pBl, K, GBK, tid, gate);
    CP_COMMIT();

    int st_idx = 0;
    if (!gate) {
        for (int c = 0; c < NC; c++) {
            if (c + 1 < NC) { CP_WAIT(1); } else { CP_WAIT(0); }
            __syncthreads();
            if (c + 2 < NC) {
                int ns = st_idx + 2; if (ns >= NSTAGE) ns -= NSTAGE;
                load_stage(smb, ns, pAh, pAl, pBh, pBl, K, (c + 2) * GBK, tid, false);
                CP_COMMIT();
            }
            const uint32_t st = smb + st_idx * STAGEB;
            #pragma unroll
            for (int ks = 0; ks < 2; ks++) {
                const uint32_t kb = ks * 32;
                uint32_t bh[16], bl[16];
                #pragma unroll
                for (int n16 = 0; n16 < 4; n16++) {
                    ldsm_x4(bh + 4 * n16, st + OFF_BH + boff + n16 * (16 * LDS * 2) + kb);
                    ldsm_x4(bl + 4 * n16, st + OFF_BL + boff + n16 * (16 * LDS * 2) + kb);
                }
                #pragma unroll
                for (int mf = 0; mf < 4; mf++) {
                    uint32_t ah[4], al[4];
                    ldsm_x4(ah, st + aoff + mf * (16 * LDS * 2) + kb);
                    ldsm_x4(al, st + OFF_AL + aoff + mf * (16 * LDS * 2) + kb);
                    #pragma unroll
                    for (int nf = 0; nf < 8; nf++)
                        mma16816(acc[mf][nf], ah, &bh[(nf >> 1) * 4 + (nf & 1) * 2]);
                    #pragma unroll
                    for (int nf = 0; nf < 8; nf++)
                        mma16816(acc[mf][nf], ah, &bl[(nf >> 1) * 4 + (nf & 1) * 2]);
                    #pragma unroll
                    for (int nf = 0; nf < 8; nf++)
                        mma16816(acc[mf][nf], al, &bh[(nf >> 1) * 4 + (nf & 1) * 2]);
                }
            }
            if (++st_idx == NSTAGE) st_idx = 0;
        }
    } else {
        // 1-term gate path: hh only, no Bl traffic
        for (int c = 0; c < NC; c++) {
            if (c + 1 < NC) { CP_WAIT(1); } else { CP_WAIT(0); }
            __syncthreads();
            if (c + 2 < NC) {
                int ns = st_idx + 2; if (ns >= NSTAGE) ns -= NSTAGE;
                load_stage(smb, ns, pAh, pAl, pBh, pBl, K, (c + 2) * GBK, tid, true);
                CP_COMMIT();
            }
            const uint32_t st = smb + st_idx * STAGEB;
            #pragma unroll
            for (int ks = 0; ks < 2; ks++) {
                const uint32_t kb = ks * 32;
                uint32_t bh[16];
                #pragma unroll
                for (int n16 = 0; n16 < 4; n16++)
                    ldsm_x4(bh + 4 * n16, st + OFF_BH + boff + n16 * (16 * LDS * 2) + kb);
                #pragma unroll
                for (int mf = 0; mf < 4; mf++) {
                    uint32_t ah[4];
                    ldsm_x4(ah, st + aoff + mf * (16 * LDS * 2) + kb);
                    #pragma unroll
                    for (int nf = 0; nf < 8; nf++)
                        mma16816(acc[mf][nf], ah, &bh[(nf >> 1) * 4 + (nf & 1) * 2]);
                }
            }
            if (++st_idx == NSTAGE) st_idx = 0;
        }
    }

    #pragma unroll
    for (int mf = 0; mf < 4; mf++) {
        const int r0 = mbr + wm * 64 + mf * 16 + (lane >> 2);
        #pragma unroll
        for (int nf = 0; nf < 8; nf++) {
            const int n0 = ncol + wn * 64 + nf * 8 + (lane & 3) * 2;
            *(float2*)(Cb + (size_t)r0 * Nout + n0)       = make_float2(acc[mf][nf][0], acc[mf][nf][1]);
            *(float2*)(Cb + (size_t)(r0 + 8) * Nout + n0) = make_float2(acc[mf][nf][2], acc[mf][nf][3]);
        }
    }
}

// ---------------- rmsnorm + rope for Q -> bf16 hi/lo -----------------------
__global__ __launch_bounds__(128) void qnorm_rope(
    const float* __restrict__ QG, const float* __restrict__ w,
    const float* __restrict__ cosT, const float* __restrict__ sinT,
    __nv_bfloat16* __restrict__ Qh, __nv_bfloat16* __restrict__ Ql)
{
    const int s = blockIdx.x, h = blockIdx.y, b = blockIdx.z;
    const int d = threadIdx.x;
    const float* src = QG + (((size_t)(b * Sn + s) * Hn + h) * 2 * HD);
    float x = src[d];
    float ss = x * x;
    #pragma unroll
    for (int o = 16; o > 0; o >>= 1) ss += __shfl_xor_sync(0xffffffffu, ss, o);
    __shared__ float wsum[4];
    if ((d & 31) == 0) wsum[d >> 5] = ss;
    __syncthreads();
    float tot = wsum[0] + wsum[1] + wsum[2] + wsum[3];
    float inv = rsqrtf(tot * (1.0f / HD) + EPSf);
    float n = x * inv * (1.0f + w[d]);
    __shared__ float nb[HD];
    nb[d] = n;
    __syncthreads();
    float c  = cosT[(size_t)s * HD + d];
    float sn = sinT[(size_t)s * HD + d];
    float rot = (d < HD / 2) ? -nb[d + HD / 2] : nb[d - HD / 2];
    float y = n * c + rot * sn;
    __nv_bfloat16 hh = __float2bfloat16(y);
    const size_t dst = ((size_t)(b * Hn + h) * Sn + s) * HD + d;
    Qh[dst] = hh;
    Ql[dst] = __float2bfloat16(y - __bfloat162float(hh));
}

// ---------------- rmsnorm + rope for K -> hi/lo, plus V split --------------
__global__ __launch_bounds__(128) void knorm_rope_vsplit(
    const float* __restrict__ KV,
    const float* __restrict__ w,
    const float* __restrict__ cosT, const float* __restrict__ sinT,
    __nv_bfloat16* __restrict__ Kh, __nv_bfloat16* __restrict__ Kl,
    __nv_bfloat16* __restrict__ Vh, __nv_bfloat16* __restrict__ Vl)
{
    const int s = blockIdx.x, g = blockIdx.y, b = blockIdx.z;
    const int d = threadIdx.x;
    const float* row = KV + (size_t)(b * Sn + s) * (2 * Gn * HD) + g * HD;
    float x = row[d];
    float ss = x * x;
    #pragma unroll
    for (int o = 16; o > 0; o >>= 1) ss += __shfl_xor_sync(0xffffffffu, ss, o);
    __shared__ float wsum[4];
    if ((d & 31) == 0) wsum[d >> 5] = ss;
    __syncthreads();
    float tot = wsum[0] + wsum[1] + wsum[2] + wsum[3];
    float inv = rsqrtf(tot * (1.0f / HD) + EPSf);
    float n = x * inv * (1.0f + w[d]);
    __shared__ float nb[HD];
    nb[d] = n;
    __syncthreads();
    float c  = cosT[(size_t)s * HD + d];
    float sn = sinT[(size_t)s * HD + d];
    float rot = (d < HD / 2) ? -nb[d + HD / 2] : nb[d - HD / 2];
    float y = n * c + rot * sn;
    const size_t dst = ((size_t)(b * Gn + g) * Sn + s) * HD + d;
    __nv_bfloat16 kh = __float2bfloat16(y);
    Kh[dst] = kh;
    Kl[dst] = __float2bfloat16(y - __bfloat162float(kh));
    float v = row[Gn * HD + d];
    __nv_bfloat16 vh = __float2bfloat16(v);
    Vh[dst] = vh;
    Vl[dst] = __float2bfloat16(v - __bfloat162float(vh));
}

// ================= HMMA causal flash attention + sigmoid gate ==============
// BQ=128 (8 warps x m16), BK=64, HD=128. 3-term split on QK^T and PV.
// Q-hi fragments cached in registers for the whole KV loop (Q-lo via ldsm).
// Single __syncthreads per tile. Epilogue writes bf16 hi/lo Ctx (fused fsplit).
#define AT_LDS  136
#define Q_ELE   (128 * AT_LDS)
#define KT_ELE  (64 * AT_LDS)
#define KVSTAGE_ELE (4 * KT_ELE)
#define ATT_SMEM ((2 * Q_ELE + 2 * KVSTAGE_ELE) * 2)   // 208896 bytes
#define CSC 0.12751666806979654f    // (1/sqrt(128)) * log2(e)
#define NEGINF __int_as_float(0xff800000)

__device__ __forceinline__ void kv_load(
    uint32_t smb, int stage,
    const __nv_bfloat16* kh, const __nv_bfloat16* kl,
    const __nv_bfloat16* vh, const __nv_bfloat16* vl, int tid)
{
    const uint32_t base = smb + (2 * Q_ELE + stage * KVSTAGE_ELE) * 2;
    #pragma unroll
    for (int i = 0; i < 4; i++) {
        int u = tid + i * 256;          // 0..1023
        int row = u >> 4, c8 = (u & 15) * 8;
        uint32_t so = (uint32_t)(row * AT_LDS + c8) * 2;
        size_t go = (size_t)row * HD + c8;
        cp16(base + 0 * KT_ELE * 2 + so, kh + go);
        cp16(base + 1 * KT_ELE * 2 + so, kl + go);
        cp16(base + 2 * KT_ELE * 2 + so, vh + go);
        cp16(base + 3 * KT_ELE * 2 + so, vl + go);
    }
}

__global__ __launch_bounds__(256, 1) void attn_mma(
    const __nv_bfloat16* __restrict__ Qh, const __nv_bfloat16* __restrict__ Ql,
    const __nv_bfloat16* __restrict__ Kh, const __nv_bfloat16* __restrict__ Kl,
    const __nv_bfloat16* __restrict__ Vh, const __nv_bfloat16* __restrict__ Vl,
    const float* __restrict__ QG,
    __nv_bfloat16* __restrict__ Cxh, __nv_bfloat16* __restrict__ Cxl)
{
    extern __shared__ __nv_bfloat16 smem_bf[];
    const uint32_t smb = smem_u32(smem_bf);
    const int qi = blockIdx.x, h = blockIdx.y, b = blockIdx.z;
    const int g  = h / GROUPn;
    const int tid = threadIdx.x, lane = tid & 31, w = tid >> 5;

    const __nv_bfloat16* gQh = Qh + ((size_t)(b * Hn + h) * Sn + (size_t)qi * 128) * HD;
    const __nv_bfloat16* gQl = Ql + ((size_t)(b * Hn + h) * Sn + (size_t)qi * 128) * HD;
    const __nv_bfloat16* gKh = Kh + ((size_t)(b * Gn + g) * Sn) * HD;
    const __nv_bfloat16* gKl = Kl + ((size_t)(b * Gn + g) * Sn) * HD;
    const __nv_bfloat16* gVh = Vh + ((size_t)(b * Gn + g) * Sn) * HD;
    const __nv_bfloat16* gVl = Vl + ((size_t)(b * Gn + g) * Sn) * HD;

    // load Q hi/lo into smem (128 x 128)
    #pragma unroll
    for (int i = 0; i < 8; i++) {
        int u = tid + i * 256;
        int row = u >> 4, c8 = (u & 15) * 8;
        *(uint4*)(smem_bf + row * AT_LDS + c8)         = *(const uint4*)(gQh + (size_t)row * HD + c8);
        *(uint4*)(smem_bf + Q_ELE + row * AT_LDS + c8) = *(const uint4*)(gQl + (size_t)row * HD + c8);
    }

    float m1s = NEGINF, m2s = NEGINF, l1 = 0.f, l2 = 0.f;
    float oacc[16][4];
    #pragma unroll
    for (int nf = 0; nf < 16; nf++)
        #pragma unroll
        for (int k = 0; k < 4; k++) oacc[nf][k] = 0.f;

    const int r1rel = w * 16 + (lane >> 2);   // 0..127
    const int r1g = qi * 128 + r1rel;
    const int r2g = r1g + 8;

    kv_load(smb, 0, gKh, gKl, gVh, gVl, tid);
    CP_COMMIT();
    CP_WAIT(0);
    __syncthreads();   // Q smem + KV stage0 ready

    // cache Q-hi fragments in registers for the whole loop
    uint32_t qh_fr[8][4];
    #pragma unroll
    for (int kq = 0; kq < 8; kq++) {
        const uint32_t qaddr = smb +
            (uint32_t)((w * 16 + (lane & 15)) * AT_LDS + ((lane >> 4) << 3) + kq * 16) * 2;
        ldsm_x4(qh_fr[kq], qaddr);
    }

    const int ntiles = 2 * qi + 2;
    for (int t = 0; t < ntiles; t++) {
        if (t > 0) {
            CP_WAIT(0);
            __syncthreads();  // stage (t&1) ready AND all warps done with it from t-2
        }
        if (t + 1 < ntiles) {
            kv_load(smb, (t + 1) & 1,
                    gKh + (size_t)(t + 1) * 64 * HD, gKl + (size_t)(t + 1) * 64 * HD,
                    gVh + (size_t)(t + 1) * 64 * HD, gVl + (size_t)(t + 1) * 64 * HD, tid);
            CP_COMMIT();
        }

        const uint32_t kb = smb + (2 * Q_ELE + (t & 1) * KVSTAGE_ELE) * 2;

        // ---- scores: S = Q K^T (3-term split, term-major, Q-hi in regs) ----
        float sacc[8][4];
        #pragma unroll
        for (int j = 0; j < 8; j++)
            #pragma unroll
            for (int k = 0; k < 4; k++) sacc[j][k] = 0.f;

        #pragma unroll
        for (int kq = 0; kq < 8; kq++) {
            uint32_t al[4], bh[16], bl[16];
            const uint32_t qaddr = smb +
                (uint32_t)((w * 16 + (lane & 15)) * AT_LDS + ((lane >> 4) << 3) + kq * 16) * 2;
            ldsm_x4(al, qaddr + Q_ELE * 2);
            #pragma unroll
            for (int n16 = 0; n16 < 4; n16++) {
                const uint32_t kaddr = kb +
                    (uint32_t)((n16 * 16 + (lane & 7) + ((lane >> 4) << 3)) * AT_LDS
                               + (((lane >> 3) & 1) << 3) + kq * 16) * 2;
                ldsm_x4(bh + 4 * n16, kaddr);
                ldsm_x4(bl + 4 * n16, kaddr + KT_ELE * 2);
            }
            #pragma unroll
            for (int n16 = 0; n16 < 4; n16++) {
                mma16816(sacc[2 * n16],     qh_fr[kq], bh + 4 * n16);
                mma16816(sacc[2 * n16 + 1], qh_fr[kq], bh + 4 * n16 + 2);
            }
            #pragma unroll
            for (int n16 = 0; n16 < 4; n16++) {
                mma16816(sacc[2 * n16],     qh_fr[kq], bl + 4 * n16);
                mma16816(sacc[2 * n16 + 1], qh_fr[kq], bl + 4 * n16 + 2);
            }
            #pragma unroll
            for (int n16 = 0; n16 < 4; n16++) {
                mma16816(sacc[2 * n16],     al, bh + 4 * n16);
                mma16816(sacc[2 * n16 + 1], al, bh + 4 * n16 + 2);
            }
        }

        // ---- online softmax (log2 domain) ----
        const bool needmask = (t >= 2 * qi);
        float mt1 = m1s, mt2 = m2s;
        #pragma unroll
        for (int j = 0; j < 8; j++) {
            const int c0 = t * 64 + j * 8 + (lane & 3) * 2;
            #pragma unroll
            for (int k = 0; k < 4; k++) sacc[j][k] *= CSC;
            if (needmask) {
                if (c0     > r1g) sacc[j][0] = NEGINF;
                if (c0 + 1 > r1g) sacc[j][1] = NEGINF;
                if (c0     > r2g) sacc[j][2] = NEGINF;
                if (c0 + 1 > r2g) sacc[j][3] = NEGINF;
            }
            mt1 = fmaxf(mt1, fmaxf(sacc[j][0], sacc[j][1]));
            mt2 = fmaxf(mt2, fmaxf(sacc[j][2], sacc[j][3]));
        }
        mt1 = fmaxf(mt1, __shfl_xor_sync(0xffffffffu, mt1, 1));
        mt1 = fmaxf(mt1, __shfl_xor_sync(0xffffffffu, mt1, 2));
        mt2 = fmaxf(mt2, __shfl_xor_sync(0xffffffffu, mt2, 1));
        mt2 = fmaxf(mt2, __shfl_xor_sync(0xffffffffu, mt2, 2));
        const float f1 = ex2f(m1s - mt1), f2 = ex2f(m2s - mt2);
        m1s = mt1; m2s = mt2;
        float s1 = 0.f, s2 = 0.f;
        #pragma unroll
        for (int j = 0; j < 8; j++) {
            sacc[j][0] = ex2f(sacc[j][0] - mt1);
            sacc[j][1] = ex2f(sacc[j][1] - mt1);
            sacc[j][2] = ex2f(sacc[j][2] - mt2);
            sacc[j][3] = ex2f(sacc[j][3] - mt2);
            s1 += sacc[j][0] + sacc[j][1];
            s2 += sacc[j][2] + sacc[j][3];
        }
        l1 = l1 * f1 + s1;
        l2 = l2 * f2 + s2;
        #pragma unroll
        for (int nf = 0; nf < 16; nf++) {
            oacc[nf][0] *= f1; oacc[nf][1] *= f1;
            oacc[nf][2] *= f2; oacc[nf][3] *= f2;
        }

        // ---- PV: out += P V (3-term split, dc processed in pairs) ----
        #pragma unroll
        for (int kk = 0; kk < 4; kk++) {
            uint32_t a_h[4], a_l[4];
            #pragma unroll
            for (int half = 0; half < 2; half++) {
                const float p0 = sacc[2 * kk + half][0], p1 = sacc[2 * kk + half][1];
                const float p2 = sacc[2 * kk + half][2], p3 = sacc[2 * kk + half][3];
                const uint32_t h01 = packbf2(p0, p1);
                const uint32_t h23 = packbf2(p2, p3);
                a_h[2 * half]     = h01;
                a_h[2 * half + 1] = h23;
                a_l[2 * half]     = packbf2(p0 - __uint_as_float(h01 << 16),
                                            p1 - __uint_as_float(h01 & 0xffff0000u));
                a_l[2 * half + 1] = packbf2(p2 - __uint_as_float(h23 << 16),
                                            p3 - __uint_as_float(h23 & 0xffff0000u));
            }
            #pragma unroll
            for (int dp = 0; dp < 4; dp++) {    // dc = 2dp, 2dp+1
                uint32_t bvh0[4], bvl0[4], bvh1[4], bvl1[4];
                const uint32_t va0 = kb + 2 * KT_ELE * 2 +
                    (uint32_t)((kk * 16 + (lane & 15)) * AT_LDS + (2 * dp) * 16 + ((lane >> 4) << 3)) * 2;
                const uint32_t va1 = va0 + 32;
                ldsm_x4t(bvh0, va0);
                ldsm_x4t(bvl0, va0 + KT_ELE * 2);
                ldsm_x4t(bvh1, va1);
                ldsm_x4t(bvl1, va1 + KT_ELE * 2);
                // hh
                mma16816(oacc[4 * dp],     a_h, bvh0);
                mma16816(oacc[4 * dp + 1], a_h, bvh0 + 2);
                mma16816(oacc[4 * dp + 2], a_h, bvh1);
                mma16816(oacc[4 * dp + 3], a_h, bvh1 + 2);
                // hl
                mma16816(oacc[4 * dp],     a_h, bvl0);
                mma16816(oacc[4 * dp + 1], a_h, bvl0 + 2);
                mma16816(oacc[4 * dp + 2], a_h, bvl1);
                mma16816(oacc[4 * dp + 3], a_h, bvl1 + 2);
                // lh
                mma16816(oacc[4 * dp],     a_l, bvh0);
                mma16816(oacc[4 * dp + 1], a_l, bvh0 + 2);
                mma16816(oacc[4 * dp + 2], a_l, bvh1);
                mma16816(oacc[4 * dp + 3], a_l, bvh1 + 2);
            }
        }
    }

    // ---- epilogue: /l, * sigmoid(gate), write bf16 hi/lo Ctx ----
    l1 += __shfl_xor_sync(0xffffffffu, l1, 1);
    l1 += __shfl_xor_sync(0xffffffffu, l1, 2);
    l2 += __shfl_xor_sync(0xffffffffu, l2, 1);
    l2 += __shfl_xor_sync(0xffffffffu, l2, 2);
    const float inv1 = 1.0f / l1, inv2 = 1.0f / l2;
    #pragma unroll
    for (int nf = 0; nf < 16; nf++) {
        const int dim = nf * 8 + (lane & 3) * 2;
        #pragma unroll
        for (int rr = 0; rr < 2; rr++) {
            const int q = rr ? r2g : r1g;
            const float invl = rr ? inv2 : inv1;
            const float a0 = oacc[nf][2 * rr], a1 = oacc[nf][2 * rr + 1];
            const float2 gt = *(const float2*)(QG + (((size_t)(b * Sn + q) * Hn + h) * 2 * HD) + HD + dim);
            const float v0 = a0 * invl * (1.0f / (1.0f + expf(-gt.x)));
            const float v1 = a1 * invl * (1.0f / (1.0f + expf(-gt.y)));
            const __nv_bfloat16 h0 = __float2bfloat16(v0);
            const __nv_bfloat16 h1 = __float2bfloat16(v1);
            const size_t off = (size_t)(b * Sn + q) * DOUT + h * HD + dim;
            *(__nv_bfloat162*)(Cxh + off) = __nv_bfloat162(h0, h1);
            *(__nv_bfloat162*)(Cxl + off) =
                __nv_bfloat162(__float2bfloat16(v0 - __bfloat162float(h0)),
                               __float2bfloat16(v1 - __bfloat162float(h1)));
        }
    }
}

// ---------------------------- launcher -------------------------------------
extern "C" void kernel_launch(void* const* d_in, const int* in_sizes, int n_in,
                              void* d_out, int out_size)
{
    const float* x    = (const float*)d_in[0];
    const float* Wq   = (const float*)d_in[1];
    const float* Wk   = (const float*)d_in[2];
    const float* Wv   = (const float*)d_in[3];
    const float* Wo   = (const float*)d_in[4];
    const float* qw   = (const float*)d_in[5];
    const float* kw   = (const float*)d_in[6];
    const float* cosT = (const float*)d_in[7];
    const float* sinT = (const float*)d_in[8];
    float* out = (float*)d_out;

    float *QG, *KV;
    cudaGetSymbolAddress((void**)&QG, g_QG);
    cudaGetSymbolAddress((void**)&KV, g_KV);

    __nv_bfloat16 *Qhp, *Qlp, *Khp, *Klp, *Vhp, *Vlp;
    cudaGetSymbolAddress((void**)&Qhp, g_Qh);
    cudaGetSymbolAddress((void**)&Qlp, g_Ql);
    cudaGetSymbolAddress((void**)&Khp, g_Kh);
    cudaGetSymbolAddress((void**)&Klp, g_Kl);
    cudaGetSymbolAddress((void**)&Vhp, g_Vh);
    cudaGetSymbolAddress((void**)&Vlp, g_Vl);

    __nv_bfloat16 *xh, *xl, *Wah, *Wal, *Woh, *Wol, *Cxh, *Cxl;
    cudaGetSymbolAddress((void**)&xh,  g_xh);
    cudaGetSymbolAddress((void**)&xl,  g_xl);
    cudaGetSymbolAddress((void**)&Wah, g_Wah);
    cudaGetSymbolAddress((void**)&Wal, g_Wal);
    cudaGetSymbolAddress((void**)&Woh, g_Woh);
    cudaGetSymbolAddress((void**)&Wol, g_Wol);
    cudaGetSymbolAddress((void**)&Cxh, g_Cxh);
    cudaGetSymbolAddress((void**)&Cxl, g_Cxl);

    cudaFuncSetAttribute(gemm_tc, cudaFuncAttributeMaxDynamicSharedMemorySize, GEMM_SMEM);
    cudaFuncSetAttribute(attn_mma, cudaFuncAttributeMaxDynamicSharedMemorySize, ATT_SMEM);

    const int M = Mrows;          // 4096
    const int NKV = 2 * Gn * HD;  // 1024

    // (1) split x; (2-5) transpose+split all weights
    fsplit<<<(M * DIN / 4 + 255) / 256, 256>>>(x, xh, xl, M * DIN);
    tsplit<<<dim3((2 * DOUT) / 32, DIN / 32), dim3(32, 8)>>>(Wq, Wah, Wal, DIN, 2 * DOUT);
    tsplit<<<dim3((Gn * HD) / 32, DIN / 32), dim3(32, 8)>>>(
        Wk, Wah + (size_t)(2 * DOUT) * DIN, Wal + (size_t)(2 * DOUT) * DIN, DIN, Gn * HD);
    tsplit<<<dim3((Gn * HD) / 32, DIN / 32), dim3(32, 8)>>>(
        Wv, Wah + (size_t)(2 * DOUT + Gn * HD) * DIN, Wal + (size_t)(2 * DOUT + Gn * HD) * DIN,
        DIN, Gn * HD);
    tsplit<<<dim3(DIN / 32, DOUT / 32), dim3(32, 8)>>>(Wo, Woh, Wol, DOUT, DIN);

    // (6) merged QKV projection, 1-term gate tiles  [profiled launch: -s 5]
    gemm_tc<<<dim3(NQKV / 128, M / 256), 256, GEMM_SMEM>>>(
        xh, xl, Wah, Wal, QG, KV, M, 2 * DOUT, NKV, DIN, 1);

    // (7-8) norm + rope -> bf16 hi/lo
    qnorm_rope<<<dim3(Sn, Hn, Bn), 128>>>(QG, qw, cosT, sinT, Qhp, Qlp);
    knorm_rope_vsplit<<<dim3(Sn, Gn, Bn), 128>>>(KV, kw, cosT, sinT,
                                                 Khp, Klp, Vhp, Vlp);

    // (9) HMMA causal attention + gate, fused bf16 split epilogue
    attn_mma<<<dim3(Sn / 128, Hn, Bn), 256, ATT_SMEM>>>(
        Qhp, Qlp, Khp, Klp, Vhp, Vlp, QG, Cxh, Cxl);

    // (10) output projection
    gemm_tc<<<dim3(DIN / 128, M / 256), 256, GEMM_SMEM>>>(
        Cxh, Cxl, Woh, Wol, out, (float*)nullptr, M, DIN, 0, DOUT, 0);
}

// round 12
// speedup vs baseline: 1.5017x; 1.2547x over previous
#include <cuda_runtime.h>
#include <cuda_fp16.h>
#include <math.h>
#include <stdint.h>

#define Bn    2
#define Sn    2048
#define DIN   2048
#define Hn    16
#define Gn    4
#define HD    128
#define DOUT  2048
#define GROUPn 4          // H / G
#define EPSf  1e-6f
#define Mrows (Bn*Sn)     // 4096
#define NQKV  (2*DOUT + 2*Gn*HD)   // 5120 = Wq(4096) | Wk(512) | Wv(512)

// ---------------- scratch (device globals; no allocation allowed) ----------
__device__ float g_QG  [(size_t)Bn*Sn*Hn*2*HD];   // [b,s,h,2*HD]  (q | gate)
__device__ float g_KV  [(size_t)Bn*Sn*(2*Gn*HD)]; // [b,s, K(512) | V(512)]

// fp16 attention operands (Q needs hi/lo; K,V hi only)
__device__ __half g_Qh[(size_t)Bn*Hn*Sn*HD];
__device__ __half g_Ql[(size_t)Bn*Hn*Sn*HD];
__device__ __half g_Kh[(size_t)Bn*Gn*Sn*HD];
__device__ __half g_Vh[(size_t)Bn*Gn*Sn*HD];

// fp16 split scratch for GEMMs (A side hi/lo; B side hi only)
__device__ __half g_xh [(size_t)Mrows*DIN];
__device__ __half g_xl [(size_t)Mrows*DIN];
__device__ __half g_Wah[(size_t)NQKV*DIN];   // packed Wq|Wk|Wv, [N][K], hi only
__device__ __half g_Woh[(size_t)DIN*DOUT];   // hi only
__device__ __half g_Cxh[(size_t)Mrows*DOUT];
__device__ __half g_Cxl[(size_t)Mrows*DOUT];

// ======================= PTX helpers (compute_103 baseline only) ==========
__device__ __forceinline__ uint32_t smem_u32(const void* p) {
    uint32_t a;
    asm("{ .reg .u64 t; cvta.to.shared.u64 t, %1; cvt.u32.u64 %0, t; }" : "=r"(a) : "l"(p));
    return a;
}
__device__ __forceinline__ void cp16(uint32_t s, const void* g) {
    asm volatile("cp.async.cg.shared.global [%0], [%1], 16;" :: "r"(s), "l"(g));
}
#define CP_COMMIT() asm volatile("cp.async.commit_group;" ::: "memory")
#define CP_WAIT(n)  asm volatile("cp.async.wait_group %0;" :: "n"(n) : "memory")

__device__ __forceinline__ void ldsm_x4(uint32_t* r, uint32_t addr) {
    asm volatile("ldmatrix.sync.aligned.m8n8.x4.shared.b16 {%0,%1,%2,%3}, [%4];"
        : "=r"(r[0]), "=r"(r[1]), "=r"(r[2]), "=r"(r[3]) : "r"(addr));
}
__device__ __forceinline__ void ldsm_x4t(uint32_t* r, uint32_t addr) {
    asm volatile("ldmatrix.sync.aligned.m8n8.x4.trans.shared.b16 {%0,%1,%2,%3}, [%4];"
        : "=r"(r[0]), "=r"(r[1]), "=r"(r[2]), "=r"(r[3]) : "r"(addr));
}
__device__ __forceinline__ void mma16816(float* d, const uint32_t* a, const uint32_t* b) {
    asm volatile(
        "mma.sync.aligned.m16n8k16.row.col.f32.f16.f16.f32 "
        "{%0,%1,%2,%3}, {%4,%5,%6,%7}, {%8,%9}, {%0,%1,%2,%3};"
        : "+f"(d[0]), "+f"(d[1]), "+f"(d[2]), "+f"(d[3])
        : "r"(a[0]), "r"(a[1]), "r"(a[2]), "r"(a[3]), "r"(b[0]), "r"(b[1]));
}
__device__ __forceinline__ float ex2f(float x) {
    float r; asm("ex2.approx.f32 %0, %1;" : "=f"(r) : "f"(x)); return r;
}
__device__ __forceinline__ uint32_t packh2(float lo, float hi) {
    uint32_t r; asm("cvt.rn.f16x2.f32 %0, %1, %2;" : "=r"(r) : "f"(hi), "f"(lo)); return r;
}

// ======================= split / transpose-split ==========================
__global__ __launch_bounds__(256) void fsplit(const float* __restrict__ in,
                                              __half* __restrict__ h,
                                              __half* __restrict__ l, int n)
{
    int i = (blockIdx.x * 256 + threadIdx.x) * 4;
    if (i >= n) return;
    float4 v = *(const float4*)(in + i);
    __half h0 = __float2half_rn(v.x), h1 = __float2half_rn(v.y);
    __half h2 = __float2half_rn(v.z), h3 = __float2half_rn(v.w);
    __half l0 = __float2half_rn(v.x - __half2float(h0));
    __half l1 = __float2half_rn(v.y - __half2float(h1));
    __half l2 = __float2half_rn(v.z - __half2float(h2));
    __half l3 = __float2half_rn(v.w - __half2float(h3));
    *(__half2*)(h + i)     = __halves2half2(h0, h1);
    *(__half2*)(h + i + 2) = __halves2half2(h2, h3);
    *(__half2*)(l + i)     = __halves2half2(l0, l1);
    *(__half2*)(l + i + 2) = __halves2half2(l2, l3);
}

// W[K,N] fp32 -> Th[N,K] fp16 hi (transpose, B-side needs hi only)
__global__ __launch_bounds__(256) void tsplit(const float* __restrict__ W,
                                              __half* __restrict__ Th,
                                              int K, int N)
{
    __shared__ float t[32][33];
    const int n0 = blockIdx.x * 32, k0 = blockIdx.y * 32;
    const int tx = threadIdx.x, ty = threadIdx.y;  // (32, 8)
    #pragma unroll
    for (int r = 0; r < 4; r++)
        t[ty + r * 8][tx] = W[(size_t)(k0 + ty + r * 8) * N + n0 + tx];
    __syncthreads();
    #pragma unroll
    for (int r = 0; r < 4; r++) {
        int n = n0 + ty + r * 8, k = k0 + tx;
        Th[(size_t)n * K + k] = __float2half_rn(t[tx][ty + r * 8]);
    }
}

// ======================= HMMA 2-term fp16 GEMM (256x128, 3-stage) ==========
// C = (Ah+Al) * Bh^T.  A hi/lo [M,K], B hi [N0+N1][K], K-major fp16.
// Output routing: n-tile < N0 -> C0 else C1. Gate tiles (odd 128-tile in Wq
// region): 1-term Ah*Bh only.
#define GBK    32
#define LDS    40
#define ATILEB (256 * LDS * 2)   // 20480 B
#define BTILEB (128 * LDS * 2)   // 10240 B
#define STAGEB (2 * ATILEB + BTILEB)      // 51200 B
#define NSTAGE 3
#define GEMM_SMEM (NSTAGE * STAGEB)       // 153600 B
#define OFF_AL  ATILEB
#define OFF_BH  (2 * ATILEB)

__device__ __forceinline__ void load_stage(
    uint32_t smb, int stage,
    const __half* __restrict__ pAh, const __half* __restrict__ pAl,
    const __half* __restrict__ pBh,
    int K, int kc, int tid)
{
    const uint32_t sb = smb + stage * STAGEB;
    #pragma unroll
    for (int i = 0; i < 4; i++) {
        const int u = tid + i * 256;
        const int row = u >> 2, col = (u & 3) * 8;
        const uint32_t so = (uint32_t)(row * LDS + col) * 2;
        const size_t g = (size_t)row * K + kc + col;
        cp16(sb + so,          pAh + g);
        cp16(sb + OFF_AL + so, pAl + g);
    }
    #pragma unroll
    for (int i = 0; i < 2; i++) {
        const int u = tid + i * 256;
        const int row = u >> 2, col = (u & 3) * 8;
        const uint32_t so = (uint32_t)(row * LDS + col) * 2;
        cp16(sb + OFF_BH + so, pBh + (size_t)row * K + kc + col);
    }
}

__global__ __launch_bounds__(256, 1) void gemm_tc(
    const __half* __restrict__ Ah, const __half* __restrict__ Al,
    const __half* __restrict__ Bh,
    float* __restrict__ C0, float* __restrict__ C1,
    int M, int N0, int N1, int K, int enable_gate)
{
    extern __shared__ char sm[];
    const uint32_t smb = smem_u32(sm);
    const int tid  = threadIdx.x;
    const int wid  = tid >> 5, lane = tid & 31;
    const int wm   = wid & 3;
    const int wn   = wid >> 2;
    const int mbr  = blockIdx.y * 256, nbr = blockIdx.x * 128;

    float* Cb;
    int Nout, ncol;
    if (nbr < N0) { Cb = C0; Nout = N0; ncol = nbr; }
    else          { Cb = C1; Nout = N1; ncol = nbr - N0; }
    const bool gate = enable_gate && (nbr < N0) && ((nbr >> 7) & 1);

    const __half* pAh = Ah + (size_t)mbr * K;
    const __half* pAl = Al + (size_t)mbr * K;
    const __half* pBh = Bh + (size_t)nbr * K;

    float acc[4][8][4];
    #pragma unroll
    for (int i = 0; i < 4; i++)
        #pragma unroll
        for (int j = 0; j < 8; j++)
            #pragma unroll
            for (int k = 0; k < 4; k++) acc[i][j][k] = 0.f;

    const uint32_t aoff = (uint32_t)((wm * 64 + (lane & 15)) * LDS + ((lane >> 4) * 8)) * 2;
    const uint32_t boff = (uint32_t)((wn * 64 + (lane & 7) + ((lane >> 4) << 3)) * LDS
                                     + (((lane >> 3) & 1) * 8)) * 2;

    const int NC = K / GBK;
    load_stage(smb, 0, pAh, pAl, pBh, K, 0, tid);
    CP_COMMIT();
    load_stage(smb, 1, pAh, pAl, pBh, K, GBK, tid);
    CP_COMMIT();

    int st_idx = 0;
    for (int c = 0; c < NC; c++) {
        if (c + 1 < NC) { CP_WAIT(1); } else { CP_WAIT(0); }
        __syncthreads();
        if (c + 2 < NC) {
            int ns = st_idx + 2; if (ns >= NSTAGE) ns -= NSTAGE;
            load_stage(smb, ns, pAh, pAl, pBh, K, (c + 2) * GBK, tid);
            CP_COMMIT();
        }

        const uint32_t st = smb + st_idx * STAGEB;
        #pragma unroll
        for (int ks = 0; ks < 2; ks++) {
            const uint32_t kb = ks * 32;
            uint32_t bh[16];
            #pragma unroll
            for (int n16 = 0; n16 < 4; n16++)
                ldsm_x4(bh + 4 * n16, st + OFF_BH + boff + n16 * (16 * LDS * 2) + kb);
            #pragma unroll
            for (int mf = 0; mf < 4; mf++) {
                uint32_t ah[4];
                ldsm_x4(ah, st + aoff + mf * (16 * LDS * 2) + kb);
                #pragma unroll
                for (int nf = 0; nf < 8; nf++)
                    mma16816(acc[mf][nf], ah, &bh[(nf >> 1) * 4 + (nf & 1) * 2]);
                if (!gate) {
                    uint32_t al[4];
                    ldsm_x4(al, st + OFF_AL + aoff + mf * (16 * LDS * 2) + kb);
                    #pragma unroll
                    for (int nf = 0; nf < 8; nf++)
                        mma16816(acc[mf][nf], al, &bh[(nf >> 1) * 4 + (nf & 1) * 2]);
                }
            }
        }
        if (++st_idx == NSTAGE) st_idx = 0;
    }

    #pragma unroll
    for (int mf = 0; mf < 4; mf++) {
        const int r0 = mbr + wm * 64 + mf * 16 + (lane >> 2);
        #pragma unroll
        for (int nf = 0; nf < 8; nf++) {
            const int n0 = ncol + wn * 64 + nf * 8 + (lane & 3) * 2;
            *(float2*)(Cb + (size_t)r0 * Nout + n0)       = make_float2(acc[mf][nf][0], acc[mf][nf][1]);
            *(float2*)(Cb + (size_t)(r0 + 8) * Nout + n0) = make_float2(acc[mf][nf][2], acc[mf][nf][3]);
        }
    }
}

// ---------------- rmsnorm + rope for Q -> fp16 hi/lo -----------------------
__global__ __launch_bounds__(128) void qnorm_rope(
    const float* __restrict__ QG, const float* __restrict__ w,
    const float* __restrict__ cosT, const float* __restrict__ sinT,
    __half* __restrict__ Qh, __half* __restrict__ Ql)
{
    const int s = blockIdx.x, h = blockIdx.y, b = blockIdx.z;
    const int d = threadIdx.x;
    const float* src = QG + (((size_t)(b * Sn + s) * Hn + h) * 2 * HD);
    float x = src[d];
    float ss = x * x;
    #pragma unroll
    for (int o = 16; o > 0; o >>= 1) ss += __shfl_xor_sync(0xffffffffu, ss, o);
    __shared__ float wsum[4];
    if ((d & 31) == 0) wsum[d >> 5] = ss;
    __syncthreads();
    float tot = wsum[0] + wsum[1] + wsum[2] + wsum[3];
    float inv = rsqrtf(tot * (1.0f / HD) + EPSf);
    float n = x * inv * (1.0f + w[d]);
    __shared__ float nb[HD];
    nb[d] = n;
    __syncthreads();
    float c  = cosT[(size_t)s * HD + d];
    float sn = sinT[(size_t)s * HD + d];
    float rot = (d < HD / 2) ? -nb[d + HD / 2] : nb[d - HD / 2];
    float y = n * c + rot * sn;
    __half hh = __float2half_rn(y);
    const size_t dst = ((size_t)(b * Hn + h) * Sn + s) * HD + d;
    Qh[dst] = hh;
    Ql[dst] = __float2half_rn(y - __half2float(hh));
}

// ---------------- rmsnorm + rope for K -> fp16 hi, V -> fp16 hi ------------
__global__ __launch_bounds__(128) void knorm_rope_v(
    const float* __restrict__ KV,
    const float* __restrict__ w,
    const float* __restrict__ cosT, const float* __restrict__ sinT,
    __half* __restrict__ Kh, __half* __restrict__ Vh)
{
    const int s = blockIdx.x, g = blockIdx.y, b = blockIdx.z;
    const int d = threadIdx.x;
    const float* row = KV + (size_t)(b * Sn + s) * (2 * Gn * HD) + g * HD;
    float x = row[d];
    float ss = x * x;
    #pragma unroll
    for (int o = 16; o > 0; o >>= 1) ss += __shfl_xor_sync(0xffffffffu, ss, o);
    __shared__ float wsum[4];
    if ((d & 31) == 0) wsum[d >> 5] = ss;
    __syncthreads();
    float tot = wsum[0] + wsum[1] + wsum[2] + wsum[3];
    float inv = rsqrtf(tot * (1.0f / HD) + EPSf);
    float n = x * inv * (1.0f + w[d]);
    __shared__ float nb[HD];
    nb[d] = n;
    __syncthreads();
    float c  = cosT[(size_t)s * HD + d];
    float sn = sinT[(size_t)s * HD + d];
    float rot = (d < HD / 2) ? -nb[d + HD / 2] : nb[d - HD / 2];
    float y = n * c + rot * sn;
    const size_t dst = ((size_t)(b * Gn + g) * Sn + s) * HD + d;
    Kh[dst] = __float2half_rn(y);
    Vh[dst] = __float2half_rn(row[Gn * HD + d]);
}

// ================= HMMA causal flash attention + sigmoid gate ==============
// BQ=128 (8 warps x m16), BK=64, HD=128. fp16 2-term: (Qh+Ql)*Kh, (Ph+Pl)*Vh.
// Q-hi fragments cached in registers. Single __syncthreads per tile.
// Epilogue writes fp16 hi/lo Ctx (A side of Wo GEMM).
#define AT_LDS  136
#define Q_ELE   (128 * AT_LDS)
#define KT_ELE  (64 * AT_LDS)
#define KVSTAGE_ELE (2 * KT_ELE)
#define ATT_SMEM ((2 * Q_ELE + 2 * KVSTAGE_ELE) * 2)   // 139264 bytes
#define CSC 0.12751666806979654f    // (1/sqrt(128)) * log2(e)
#define NEGINF __int_as_float(0xff800000)

__device__ __forceinline__ void kv_load(
    uint32_t smb, int stage,
    const __half* kh, const __half* vh, int tid)
{
    const uint32_t base = smb + (2 * Q_ELE + stage * KVSTAGE_ELE) * 2;
    #pragma unroll
    for (int i = 0; i < 4; i++) {
        int u = tid + i * 256;          // 0..1023
        int til = u >> 9;               // 0: Kh, 1: Vh
        int uu = u & 511;
        int row = uu >> 3, c8 = (uu & 7) * 16;
        uint32_t so = (uint32_t)(row * AT_LDS + c8) * 2;
        const __half* src = til ? vh : kh;
        cp16(base + (uint32_t)til * (KT_ELE * 2) + so, src + (size_t)row * HD + c8);
        cp16(base + (uint32_t)til * (KT_ELE * 2) + so + 16, src + (size_t)row * HD + c8 + 8);
    }
}

__global__ __launch_bounds__(256, 1) void attn_mma(
    const __half* __restrict__ Qh, const __half* __restrict__ Ql,
    const __half* __restrict__ Kh, const __half* __restrict__ Vh,
    const float* __restrict__ QG,
    __half* __restrict__ Cxh, __half* __restrict__ Cxl)
{
    extern __shared__ __half smem_h[];
    const uint32_t smb = smem_u32(smem_h);
    const int qi = blockIdx.x, h = blockIdx.y, b = blockIdx.z;
    const int g  = h / GROUPn;
    const int tid = threadIdx.x, lane = tid & 31, w = tid >> 5;

    const __half* gQh = Qh + ((size_t)(b * Hn + h) * Sn + (size_t)qi * 128) * HD;
    const __half* gQl = Ql + ((size_t)(b * Hn + h) * Sn + (size_t)qi * 128) * HD;
    const __half* gKh = Kh + ((size_t)(b * Gn + g) * Sn) * HD;
    const __half* gVh = Vh + ((size_t)(b * Gn + g) * Sn) * HD;

    // load Q hi/lo into smem (128 x 128)
    #pragma unroll
    for (int i = 0; i < 8; i++) {
        int u = tid + i * 256;
        int row = u >> 4, c8 = (u & 15) * 8;
        *(uint4*)(smem_h + row * AT_LDS + c8)         = *(const uint4*)(gQh + (size_t)row * HD + c8);
        *(uint4*)(smem_h + Q_ELE + row * AT_LDS + c8) = *(const uint4*)(gQl + (size_t)row * HD + c8);
    }

    float m1s = NEGINF, m2s = NEGINF, l1 = 0.f, l2 = 0.f;
    float oacc[16][4];
    #pragma unroll
    for (int nf = 0; nf < 16; nf++)
        #pragma unroll
        for (int k = 0; k < 4; k++) oacc[nf][k] = 0.f;

    const int r1rel = w * 16 + (lane >> 2);   // 0..127
    const int r1g = qi * 128 + r1rel;
    const int r2g = r1g + 8;

    kv_load(smb, 0, gKh, gVh, tid);
    CP_COMMIT();
    CP_WAIT(0);
    __syncthreads();   // Q smem + KV stage0 ready

    // cache Q-hi fragments in registers for the whole loop
    uint32_t qh_fr[8][4];
    #pragma unroll
    for (int kq = 0; kq < 8; kq++) {
        const uint32_t qaddr = smb +
            (uint32_t)((w * 16 + (lane & 15)) * AT_LDS + ((lane >> 4) << 3) + kq * 16) * 2;
        ldsm_x4(qh_fr[kq], qaddr);
    }

    const int ntiles = 2 * qi + 2;
    for (int t = 0; t < ntiles; t++) {
        if (t > 0) {
            CP_WAIT(0);
            __syncthreads();  // stage (t&1) ready AND all warps done with it from t-2
        }
        if (t + 1 < ntiles) {
            kv_load(smb, (t + 1) & 1,
                    gKh + (size_t)(t + 1) * 64 * HD, gVh + (size_t)(t + 1) * 64 * HD, tid);
            CP_COMMIT();
        }

        const uint32_t kb = smb + (2 * Q_ELE + (t & 1) * KVSTAGE_ELE) * 2;

        // ---- scores: S = (Qh+Ql) Kh^T ----
        float sacc[8][4];
        #pragma unroll
        for (int j = 0; j < 8; j++)
            #pragma unroll
            for (int k = 0; k < 4; k++) sacc[j][k] = 0.f;

        #pragma unroll
        for (int kq = 0; kq < 8; kq++) {
            uint32_t al[4], bh[16];
            const uint32_t qaddr = smb +
                (uint32_t)((w * 16 + (lane & 15)) * AT_LDS + ((lane >> 4) << 3) + kq * 16) * 2;
            ldsm_x4(al, qaddr + Q_ELE * 2);
            #pragma unroll
            for (int n16 = 0; n16 < 4; n16++) {
                const uint32_t kaddr = kb +
                    (uint32_t)((n16 * 16 + (lane & 7) + ((lane >> 4) << 3)) * AT_LDS
                               + (((lane >> 3) & 1) << 3) + kq * 16) * 2;
                ldsm_x4(bh + 4 * n16, kaddr);
            }
            #pragma unroll
            for (int n16 = 0; n16 < 4; n16++) {
                mma16816(sacc[2 * n16],     qh_fr[kq], bh + 4 * n16);
                mma16816(sacc[2 * n16 + 1], qh_fr[kq], bh + 4 * n16 + 2);
            }
            #pragma unroll
            for (int n16 = 0; n16 < 4; n16++) {
                mma16816(sacc[2 * n16],     al, bh + 4 * n16);
                mma16816(sacc[2 * n16 + 1], al, bh + 4 * n16 + 2);
            }
        }

        // ---- online softmax (log2 domain) ----
        const bool needmask = (t >= 2 * qi);
        float mt1 = m1s, mt2 = m2s;
        #pragma unroll
        for (int j = 0; j < 8; j++) {
            const int c0 = t * 64 + j * 8 + (lane & 3) * 2;
            #pragma unroll
            for (int k = 0; k < 4; k++) sacc[j][k] *= CSC;
            if (needmask) {
                if (c0     > r1g) sacc[j][0] = NEGINF;
                if (c0 + 1 > r1g) sacc[j][1] = NEGINF;
                if (c0     > r2g) sacc[j][2] = NEGINF;
                if (c0 + 1 > r2g) sacc[j][3] = NEGINF;
            }
            mt1 = fmaxf(mt1, fmaxf(sacc[j][0], sacc[j][1]));
            mt2 = fmaxf(mt2, fmaxf(sacc[j][2], sacc[j][3]));
        }
        mt1 = fmaxf(mt1, __shfl_xor_sync(0xffffffffu, mt1, 1));
        mt1 = fmaxf(mt1, __shfl_xor_sync(0xffffffffu, mt1, 2));
        mt2 = fmaxf(mt2, __shfl_xor_sync(0xffffffffu, mt2, 1));
        mt2 = fmaxf(mt2, __shfl_xor_sync(0xffffffffu, mt2, 2));
        const float f1 = ex2f(m1s - mt1), f2 = ex2f(m2s - mt2);
        m1s = mt1; m2s = mt2;
        float s1 = 0.f, s2 = 0.f;
        #pragma unroll
        for (int j = 0; j < 8; j++) {
            sacc[j][0] = ex2f(sacc[j][0] - mt1);
            sacc[j][1] = ex2f(sacc[j][1] - mt1);
            sacc[j][2] = ex2f(sacc[j][2] - mt2);
            sacc[j][3] = ex2f(sacc[j][3] - mt2);
            s1 += sacc[j][0] + sacc[j][1];
            s2 += sacc[j][2] + sacc[j][3];
        }
        l1 = l1 * f1 + s1;
        l2 = l2 * f2 + s2;
        #pragma unroll
        for (int nf = 0; nf < 16; nf++) {
            oacc[nf][0] *= f1; oacc[nf][1] *= f1;
            oacc[nf][2] *= f2; oacc[nf][3] *= f2;
        }

        // ---- PV: out += (Ph+Pl) Vh ----
        #pragma unroll
        for (int kk = 0; kk < 4; kk++) {
            uint32_t a_h[4], a_l[4];
            #pragma unroll
            for (int half = 0; half < 2; half++) {
                const float p0 = sacc[2 * kk + half][0], p1 = sacc[2 * kk + half][1];
                const float p2 = sacc[2 * kk + half][2], p3 = sacc[2 * kk + half][3];
                const uint32_t h01 = packh2(p0, p1);
                const uint32_t h23 = packh2(p2, p3);
                a_h[2 * half]     = h01;
                a_h[2 * half + 1] = h23;
                const __half2 v01 = *(const __half2*)&h01;
                const __half2 v23 = *(const __half2*)&h23;
                a_l[2 * half]     = packh2(p0 - __low2float(v01), p1 - __high2float(v01));
                a_l[2 * half + 1] = packh2(p2 - __low2float(v23), p3 - __high2float(v23));
            }
            #pragma unroll
            for (int dp = 0; dp < 4; dp++) {    // dc = 2dp, 2dp+1
                uint32_t bvh0[4], bvh1[4];
                const uint32_t va0 = kb + KT_ELE * 2 +
                    (uint32_t)((kk * 16 + (lane & 15)) * AT_LDS + (2 * dp) * 16 + ((lane >> 4) << 3)) * 2;
                const uint32_t va1 = va0 + 32;
                ldsm_x4t(bvh0, va0);
                ldsm_x4t(bvh1, va1);
                mma16816(oacc[4 * dp],     a_h, bvh0);
                mma16816(oacc[4 * dp + 1], a_h, bvh0 + 2);
                mma16816(oacc[4 * dp + 2], a_h, bvh1);
                mma16816(oacc[4 * dp + 3], a_h, bvh1 + 2);
                mma16816(oacc[4 * dp],     a_l, bvh0);
                mma16816(oacc[4 * dp + 1], a_l, bvh0 + 2);
                mma16816(oacc[4 * dp + 2], a_l, bvh1);
                mma16816(oacc[4 * dp + 3], a_l, bvh1 + 2);
            }
        }
    }

    // ---- epilogue: /l, * sigmoid(gate), write fp16 hi/lo Ctx ----
    l1 += __shfl_xor_sync(0xffffffffu, l1, 1);
    l1 += __shfl_xor_sync(0xffffffffu, l1, 2);
    l2 += __shfl_xor_sync(0xffffffffu, l2, 1);
    l2 += __shfl_xor_sync(0xffffffffu, l2, 2);
    const float inv1 = 1.0f / l1, inv2 = 1.0f / l2;
    #pragma unroll
    for (int nf = 0; nf < 16; nf++) {
        const int dim = nf * 8 + (lane & 3) * 2;
        #pragma unroll
        for (int rr = 0; rr < 2; rr++) {
            const int q = rr ? r2g : r1g;
            const float invl = rr ? inv2 : inv1;
            const float a0 = oacc[nf][2 * rr], a1 = oacc[nf][2 * rr + 1];
            const float2 gt = *(const float2*)(QG + (((size_t)(b * Sn + q) * Hn + h) * 2 * HD) + HD + dim);
            const float v0 = a0 * invl * (1.0f / (1.0f + expf(-gt.x)));
            const float v1 = a1 * invl * (1.0f / (1.0f + expf(-gt.y)));
            const __half h0 = __float2half_rn(v0);
            const __half h1 = __float2half_rn(v1);
            const size_t off = (size_t)(b * Sn + q) * DOUT + h * HD + dim;
            *(__half2*)(Cxh + off) = __halves2half2(h0, h1);
            *(__half2*)(Cxl + off) =
                __halves2half2(__float2half_rn(v0 - __half2float(h0)),
                               __float2half_rn(v1 - __half2float(h1)));
        }
    }
}

// ---------------------------- launcher -------------------------------------
extern "C" void kernel_launch(void* const* d_in, const int* in_sizes, int n_in,
                              void* d_out, int out_size)
{
    const float* x    = (const float*)d_in[0];
    const float* Wq   = (const float*)d_in[1];
    const float* Wk   = (const float*)d_in[2];
    const float* Wv   = (const float*)d_in[3];
    const float* Wo   = (const float*)d_in[4];
    const float* qw   = (const float*)d_in[5];
    const float* kw   = (const float*)d_in[6];
    const float* cosT = (const float*)d_in[7];
    const float* sinT = (const float*)d_in[8];
    float* out = (float*)d_out;

    float *QG, *KV;
    cudaGetSymbolAddress((void**)&QG, g_QG);
    cudaGetSymbolAddress((void**)&KV, g_KV);

    __half *Qhp, *Qlp, *Khp, *Vhp;
    cudaGetSymbolAddress((void**)&Qhp, g_Qh);
    cudaGetSymbolAddress((void**)&Qlp, g_Ql);
    cudaGetSymbolAddress((void**)&Khp, g_Kh);
    cudaGetSymbolAddress((void**)&Vhp, g_Vh);

    __half *xh, *xl, *Wah, *Woh, *Cxh, *Cxl;
    cudaGetSymbolAddress((void**)&xh,  g_xh);
    cudaGetSymbolAddress((void**)&xl,  g_xl);
    cudaGetSymbolAddress((void**)&Wah, g_Wah);
    cudaGetSymbolAddress((void**)&Woh, g_Woh);
    cudaGetSymbolAddress((void**)&Cxh, g_Cxh);
    cudaGetSymbolAddress((void**)&Cxl, g_Cxl);

    cudaFuncSetAttribute(gemm_tc, cudaFuncAttributeMaxDynamicSharedMemorySize, GEMM_SMEM);
    cudaFuncSetAttribute(attn_mma, cudaFuncAttributeMaxDynamicSharedMemorySize, ATT_SMEM);

    const int M = Mrows;          // 4096
    const int NKV = 2 * Gn * HD;  // 1024

    // (1) split x; (2-5) transpose weights (hi only)
    fsplit<<<(M * DIN / 4 + 255) / 256, 256>>>(x, xh, xl, M * DIN);
    tsplit<<<dim3((2 * DOUT) / 32, DIN / 32), dim3(32, 8)>>>(Wq, Wah, DIN, 2 * DOUT);
    tsplit<<<dim3((Gn * HD) / 32, DIN / 32), dim3(32, 8)>>>(
        Wk, Wah + (size_t)(2 * DOUT) * DIN, DIN, Gn * HD);
    tsplit<<<dim3((Gn * HD) / 32, DIN / 32), dim3(32, 8)>>>(
        Wv, Wah + (size_t)(2 * DOUT + Gn * HD) * DIN, DIN, Gn * HD);
    tsplit<<<dim3(DIN / 32, DOUT / 32), dim3(32, 8)>>>(Wo, Woh, DOUT, DIN);

    // (6) merged QKV projection, 1-term gate tiles  [profiled launch: -s 5]
    gemm_tc<<<dim3(NQKV / 128, M / 256), 256, GEMM_SMEM>>>(
        xh, xl, Wah, QG, KV, M, 2 * DOUT, NKV, DIN, 1);

    // (7-8) norm + rope -> fp16
    qnorm_rope<<<dim3(Sn, Hn, Bn), 128>>>(QG, qw, cosT, sinT, Qhp, Qlp);
    knorm_rope_v<<<dim3(Sn, Gn, Bn), 128>>>(KV, kw, cosT, sinT, Khp, Vhp);

    // (9) HMMA causal attention + gate, fused fp16 split epilogue
    attn_mma<<<dim3(Sn / 128, Hn, Bn), 256, ATT_SMEM>>>(
        Qhp, Qlp, Khp, Vhp, QG, Cxh, Cxl);

    // (10) output projection
    gemm_tc<<<dim3(DIN / 128, M / 256), 256, GEMM_SMEM>>>(
        Cxh, Cxl, Woh, out, (float*)nullptr, M, DIN, 0, DOUT, 0);
}

// round 13
// speedup vs baseline: 1.6296x; 1.0852x over previous
#include <cuda_runtime.h>
#include <cuda_fp16.h>
#include <math.h>
#include <stdint.h>

#define Bn    2
#define Sn    2048
#define DIN   2048
#define Hn    16
#define Gn    4
#define HD    128
#define DOUT  2048
#define GROUPn 4          // H / G
#define EPSf  1e-6f
#define Mrows (Bn*Sn)     // 4096
#define NQKV  (2*DOUT + 2*Gn*HD)   // 5120 = Wq(4096) | Wk(512) | Wv(512)

// ---------------- scratch (device globals; no allocation allowed) ----------
__device__ float g_QG  [(size_t)Bn*Sn*Hn*2*HD];   // [b,s,h,2*HD]  (q | gate)
__device__ float g_KV  [(size_t)Bn*Sn*(2*Gn*HD)]; // [b,s, K(512) | V(512)]

// fp16 attention operands (all hi only now)
__device__ __half g_Qh[(size_t)Bn*Hn*Sn*HD];
__device__ __half g_Kh[(size_t)Bn*Gn*Sn*HD];
__device__ __half g_Vh[(size_t)Bn*Gn*Sn*HD];

// fp16 split scratch for GEMMs (A side hi/lo; B side hi only)
__device__ __half g_xh [(size_t)Mrows*DIN];
__device__ __half g_xl [(size_t)Mrows*DIN];
__device__ __half g_Wah[(size_t)NQKV*DIN];   // packed Wq|Wk|Wv, [N][K], hi only
__device__ __half g_Woh[(size_t)DIN*DOUT];   // hi only
__device__ __half g_Cxh[(size_t)Mrows*DOUT];
__device__ __half g_Cxl[(size_t)Mrows*DOUT];

// ======================= PTX helpers (compute_103 baseline only) ==========
__device__ __forceinline__ uint32_t smem_u32(const void* p) {
    uint32_t a;
    asm("{ .reg .u64 t; cvta.to.shared.u64 t, %1; cvt.u32.u64 %0, t; }" : "=r"(a) : "l"(p));
    return a;
}
__device__ __forceinline__ void cp16(uint32_t s, const void* g) {
    asm volatile("cp.async.cg.shared.global [%0], [%1], 16;" :: "r"(s), "l"(g));
}
#define CP_COMMIT() asm volatile("cp.async.commit_group;" ::: "memory")
#define CP_WAIT(n)  asm volatile("cp.async.wait_group %0;" :: "n"(n) : "memory")

__device__ __forceinline__ void ldsm_x4(uint32_t* r, uint32_t addr) {
    asm volatile("ldmatrix.sync.aligned.m8n8.x4.shared.b16 {%0,%1,%2,%3}, [%4];"
        : "=r"(r[0]), "=r"(r[1]), "=r"(r[2]), "=r"(r[3]) : "r"(addr));
}
__device__ __forceinline__ void ldsm_x4t(uint32_t* r, uint32_t addr) {
    asm volatile("ldmatrix.sync.aligned.m8n8.x4.trans.shared.b16 {%0,%1,%2,%3}, [%4];"
        : "=r"(r[0]), "=r"(r[1]), "=r"(r[2]), "=r"(r[3]) : "r"(addr));
}
__device__ __forceinline__ void mma16816(float* d, const uint32_t* a, const uint32_t* b) {
    asm volatile(
        "mma.sync.aligned.m16n8k16.row.col.f32.f16.f16.f32 "
        "{%0,%1,%2,%3}, {%4,%5,%6,%7}, {%8,%9}, {%0,%1,%2,%3};"
        : "+f"(d[0]), "+f"(d[1]), "+f"(d[2]), "+f"(d[3])
        : "r"(a[0]), "r"(a[1]), "r"(a[2]), "r"(a[3]), "r"(b[0]), "r"(b[1]));
}
__device__ __forceinline__ float ex2f(float x) {
    float r; asm("ex2.approx.f32 %0, %1;" : "=f"(r) : "f"(x)); return r;
}
__device__ __forceinline__ uint32_t packh2(float lo, float hi) {
    uint32_t r; asm("cvt.rn.f16x2.f32 %0, %1, %2;" : "=r"(r) : "f"(hi), "f"(lo)); return r;
}

// ======================= split / transpose ==========================
__global__ __launch_bounds__(256) void fsplit(const float* __restrict__ in,
                                              __half* __restrict__ h,
                                              __half* __restrict__ l, int n)
{
    int i = (blockIdx.x * 256 + threadIdx.x) * 4;
    if (i >= n) return;
    float4 v = *(const float4*)(in + i);
    __half h0 = __float2half_rn(v.x), h1 = __float2half_rn(v.y);
    __half h2 = __float2half_rn(v.z), h3 = __float2half_rn(v.w);
    __half l0 = __float2half_rn(v.x - __half2float(h0));
    __half l1 = __float2half_rn(v.y - __half2float(h1));
    __half l2 = __float2half_rn(v.z - __half2float(h2));
    __half l3 = __float2half_rn(v.w - __half2float(h3));
    *(__half2*)(h + i)     = __halves2half2(h0, h1);
    *(__half2*)(h + i + 2) = __halves2half2(h2, h3);
    *(__half2*)(l + i)     = __halves2half2(l0, l1);
    *(__half2*)(l + i + 2) = __halves2half2(l2, l3);
}

// W[K,N] fp32 -> Th[N,K] fp16 hi (transpose, B-side needs hi only)
__global__ __launch_bounds__(256) void tsplit(const float* __restrict__ W,
                                              __half* __restrict__ Th,
                                              int K, int N)
{
    __shared__ float t[32][33];
    const int n0 = blockIdx.x * 32, k0 = blockIdx.y * 32;
    const int tx = threadIdx.x, ty = threadIdx.y;  // (32, 8)
    #pragma unroll
    for (int r = 0; r < 4; r++)
        t[ty + r * 8][tx] = W[(size_t)(k0 + ty + r * 8) * N + n0 + tx];
    __syncthreads();
    #pragma unroll
    for (int r = 0; r < 4; r++) {
        int n = n0 + ty + r * 8, k = k0 + tx;
        Th[(size_t)n * K + k] = __float2half_rn(t[tx][ty + r * 8]);
    }
}

// ======================= HMMA 2-term fp16 GEMM (256x128, 3-stage) ==========
// C = (Ah+Al) * Bh^T.  A hi/lo [M,K], B hi [N0+N1][K], K-major fp16.
// Output routing: n-tile < N0 -> C0 else C1. Gate tiles (odd 128-tile in Wq
// region): 1-term Ah*Bh only.
#define GBK    32
#define LDS    40
#define ATILEB (256 * LDS * 2)   // 20480 B
#define BTILEB (128 * LDS * 2)   // 10240 B
#define STAGEB (2 * ATILEB + BTILEB)      // 51200 B
#define NSTAGE 3
#define GEMM_SMEM (NSTAGE * STAGEB)       // 153600 B
#define OFF_AL  ATILEB
#define OFF_BH  (2 * ATILEB)

__device__ __forceinline__ void load_stage(
    uint32_t smb, int stage,
    const __half* __restrict__ pAh, const __half* __restrict__ pAl,
    const __half* __restrict__ pBh,
    int K, int kc, int tid)
{
    const uint32_t sb = smb + stage * STAGEB;
    #pragma unroll
    for (int i = 0; i < 4; i++) {
        const int u = tid + i * 256;
        const int row = u >> 2, col = (u & 3) * 8;
        const uint32_t so = (uint32_t)(row * LDS + col) * 2;
        const size_t g = (size_t)row * K + kc + col;
        cp16(sb + so,          pAh + g);
        cp16(sb + OFF_AL + so, pAl + g);
    }
    #pragma unroll
    for (int i = 0; i < 2; i++) {
        const int u = tid + i * 256;
        const int row = u >> 2, col = (u & 3) * 8;
        const uint32_t so = (uint32_t)(row * LDS + col) * 2;
        cp16(sb + OFF_BH + so, pBh + (size_t)row * K + kc + col);
    }
}

__global__ __launch_bounds__(256, 1) void gemm_tc(
    const __half* __restrict__ Ah, const __half* __restrict__ Al,
    const __half* __restrict__ Bh,
    float* __restrict__ C0, float* __restrict__ C1,
    int M, int N0, int N1, int K, int enable_gate)
{
    extern __shared__ char sm[];
    const uint32_t smb = smem_u32(sm);
    const int tid  = threadIdx.x;
    const int wid  = tid >> 5, lane = tid & 31;
    const int wm   = wid & 3;
    const int wn   = wid >> 2;
    const int mbr  = blockIdx.y * 256, nbr = blockIdx.x * 128;

    float* Cb;
    int Nout, ncol;
    if (nbr < N0) { Cb = C0; Nout = N0; ncol = nbr; }
    else          { Cb = C1; Nout = N1; ncol = nbr - N0; }
    const bool gate = enable_gate && (nbr < N0) && ((nbr >> 7) & 1);

    const __half* pAh = Ah + (size_t)mbr * K;
    const __half* pAl = Al + (size_t)mbr * K;
    const __half* pBh = Bh + (size_t)nbr * K;

    float acc[4][8][4];
    #pragma unroll
    for (int i = 0; i < 4; i++)
        #pragma unroll
        for (int j = 0; j < 8; j++)
            #pragma unroll
            for (int k = 0; k < 4; k++) acc[i][j][k] = 0.f;

    const uint32_t aoff = (uint32_t)((wm * 64 + (lane & 15)) * LDS + ((lane >> 4) * 8)) * 2;
    const uint32_t boff = (uint32_t)((wn * 64 + (lane & 7) + ((lane >> 4) << 3)) * LDS
                                     + (((lane >> 3) & 1) * 8)) * 2;

    const int NC = K / GBK;
    load_stage(smb, 0, pAh, pAl, pBh, K, 0, tid);
    CP_COMMIT();
    load_stage(smb, 1, pAh, pAl, pBh, K, GBK, tid);
    CP_COMMIT();

    int st_idx = 0;
    for (int c = 0; c < NC; c++) {
        if (c + 1 < NC) { CP_WAIT(1); } else { CP_WAIT(0); }
        __syncthreads();
        if (c + 2 < NC) {
            int ns = st_idx + 2; if (ns >= NSTAGE) ns -= NSTAGE;
            load_stage(smb, ns, pAh, pAl, pBh, K, (c + 2) * GBK, tid);
            CP_COMMIT();
        }

        const uint32_t st = smb + st_idx * STAGEB;
        #pragma unroll
        for (int ks = 0; ks < 2; ks++) {
            const uint32_t kb = ks * 32;
            uint32_t bh[16];
            #pragma unroll
            for (int n16 = 0; n16 < 4; n16++)
                ldsm_x4(bh + 4 * n16, st + OFF_BH + boff + n16 * (16 * LDS * 2) + kb);
            #pragma unroll
            for (int mf = 0; mf < 4; mf++) {
                uint32_t ah[4];
                ldsm_x4(ah, st + aoff + mf * (16 * LDS * 2) + kb);
                #pragma unroll
                for (int nf = 0; nf < 8; nf++)
                    mma16816(acc[mf][nf], ah, &bh[(nf >> 1) * 4 + (nf & 1) * 2]);
                if (!gate) {
                    uint32_t al[4];
                    ldsm_x4(al, st + OFF_AL + aoff + mf * (16 * LDS * 2) + kb);
                    #pragma unroll
                    for (int nf = 0; nf < 8; nf++)
                        mma16816(acc[mf][nf], al, &bh[(nf >> 1) * 4 + (nf & 1) * 2]);
                }
            }
        }
        if (++st_idx == NSTAGE) st_idx = 0;
    }

    #pragma unroll
    for (int mf = 0; mf < 4; mf++) {
        const int r0 = mbr + wm * 64 + mf * 16 + (lane >> 2);
        #pragma unroll
        for (int nf = 0; nf < 8; nf++) {
            const int n0 = ncol + wn * 64 + nf * 8 + (lane & 3) * 2;
            *(float2*)(Cb + (size_t)r0 * Nout + n0)       = make_float2(acc[mf][nf][0], acc[mf][nf][1]);
            *(float2*)(Cb + (size_t)(r0 + 8) * Nout + n0) = make_float2(acc[mf][nf][2], acc[mf][nf][3]);
        }
    }
}

// ---------------- rmsnorm + rope for Q -> fp16 hi --------------------------
__global__ __launch_bounds__(128) void qnorm_rope(
    const float* __restrict__ QG, const float* __restrict__ w,
    const float* __restrict__ cosT, const float* __restrict__ sinT,
    __half* __restrict__ Qh)
{
    const int s = blockIdx.x, h = blockIdx.y, b = blockIdx.z;
    const int d = threadIdx.x;
    const float* src = QG + (((size_t)(b * Sn + s) * Hn + h) * 2 * HD);
    float x = src[d];
    float ss = x * x;
    #pragma unroll
    for (int o = 16; o > 0; o >>= 1) ss += __shfl_xor_sync(0xffffffffu, ss, o);
    __shared__ float wsum[4];
    if ((d & 31) == 0) wsum[d >> 5] = ss;
    __syncthreads();
    float tot = wsum[0] + wsum[1] + wsum[2] + wsum[3];
    float inv = rsqrtf(tot * (1.0f / HD) + EPSf);
    float n = x * inv * (1.0f + w[d]);
    __shared__ float nb[HD];
    nb[d] = n;
    __syncthreads();
    float c  = cosT[(size_t)s * HD + d];
    float sn = sinT[(size_t)s * HD + d];
    float rot = (d < HD / 2) ? -nb[d + HD / 2] : nb[d - HD / 2];
    float y = n * c + rot * sn;
    Qh[((size_t)(b * Hn + h) * Sn + s) * HD + d] = __float2half_rn(y);
}

// ---------------- rmsnorm + rope for K -> fp16 hi, V -> fp16 hi ------------
__global__ __launch_bounds__(128) void knorm_rope_v(
    const float* __restrict__ KV,
    const float* __restrict__ w,
    const float* __restrict__ cosT, const float* __restrict__ sinT,
    __half* __restrict__ Kh, __half* __restrict__ Vh)
{
    const int s = blockIdx.x, g = blockIdx.y, b = blockIdx.z;
    const int d = threadIdx.x;
    const float* row = KV + (size_t)(b * Sn + s) * (2 * Gn * HD) + g * HD;
    float x = row[d];
    float ss = x * x;
    #pragma unroll
    for (int o = 16; o > 0; o >>= 1) ss += __shfl_xor_sync(0xffffffffu, ss, o);
    __shared__ float wsum[4];
    if ((d & 31) == 0) wsum[d >> 5] = ss;
    __syncthreads();
    float tot = wsum[0] + wsum[1] + wsum[2] + wsum[3];
    float inv = rsqrtf(tot * (1.0f / HD) + EPSf);
    float n = x * inv * (1.0f + w[d]);
    __shared__ float nb[HD];
    nb[d] = n;
    __syncthreads();
    float c  = cosT[(size_t)s * HD + d];
    float sn = sinT[(size_t)s * HD + d];
    float rot = (d < HD / 2) ? -nb[d + HD / 2] : nb[d - HD / 2];
    float y = n * c + rot * sn;
    const size_t dst = ((size_t)(b * Gn + g) * Sn + s) * HD + d;
    Kh[dst] = __float2half_rn(y);
    Vh[dst] = __float2half_rn(row[Gn * HD + d]);
}

// ================= HMMA causal flash attention + sigmoid gate ==============
// BQ=128 (8 warps x m16), BK=64, HD=128. 1-term fp16: Qh*Kh, Ph*Vh.
// Q-hi fragments cached in registers. Single __syncthreads per tile.
// Epilogue writes fp16 hi/lo Ctx (A side of Wo GEMM).
#define AT_LDS  136
#define Q_ELE   (128 * AT_LDS)
#define KT_ELE  (64 * AT_LDS)
#define KVSTAGE_ELE (2 * KT_ELE)
#define ATT_SMEM ((Q_ELE + 2 * KVSTAGE_ELE) * 2)   // 104448 bytes
#define CSC 0.12751666806979654f    // (1/sqrt(128)) * log2(e)
#define NEGINF __int_as_float(0xff800000)

__device__ __forceinline__ void kv_load(
    uint32_t smb, int stage,
    const __half* kh, const __half* vh, int tid)
{
    const uint32_t base = smb + (Q_ELE + stage * KVSTAGE_ELE) * 2;
    #pragma unroll
    for (int i = 0; i < 4; i++) {
        int u = tid + i * 256;          // 0..1023
        int til = u >> 9;               // 0: Kh, 1: Vh
        int uu = u & 511;
        int row = uu >> 3, c8 = (uu & 7) * 16;
        uint32_t so = (uint32_t)(row * AT_LDS + c8) * 2;
        const __half* src = til ? vh : kh;
        cp16(base + (uint32_t)til * (KT_ELE * 2) + so, src + (size_t)row * HD + c8);
        cp16(base + (uint32_t)til * (KT_ELE * 2) + so + 16, src + (size_t)row * HD + c8 + 8);
    }
}

__global__ __launch_bounds__(256, 1) void attn_mma(
    const __half* __restrict__ Qh,
    const __half* __restrict__ Kh, const __half* __restrict__ Vh,
    const float* __restrict__ QG,
    __half* __restrict__ Cxh, __half* __restrict__ Cxl)
{
    extern __shared__ __half smem_h[];
    const uint32_t smb = smem_u32(smem_h);
    const int qi = blockIdx.x, h = blockIdx.y, b = blockIdx.z;
    const int g  = h / GROUPn;
    const int tid = threadIdx.x, lane = tid & 31, w = tid >> 5;

    const __half* gQh = Qh + ((size_t)(b * Hn + h) * Sn + (size_t)qi * 128) * HD;
    const __half* gKh = Kh + ((size_t)(b * Gn + g) * Sn) * HD;
    const __half* gVh = Vh + ((size_t)(b * Gn + g) * Sn) * HD;

    // load Q hi into smem (128 x 128)
    #pragma unroll
    for (int i = 0; i < 8; i++) {
        int u = tid + i * 256;
        int row = u >> 4, c8 = (u & 15) * 8;
        *(uint4*)(smem_h + row * AT_LDS + c8) = *(const uint4*)(gQh + (size_t)row * HD + c8);
    }

    float m1s = NEGINF, m2s = NEGINF, l1 = 0.f, l2 = 0.f;
    float oacc[16][4];
    #pragma unroll
    for (int nf = 0; nf < 16; nf++)
        #pragma unroll
        for (int k = 0; k < 4; k++) oacc[nf][k] = 0.f;

    const int r1rel = w * 16 + (lane >> 2);   // 0..127
    const int r1g = qi * 128 + r1rel;
    const int r2g = r1g + 8;

    kv_load(smb, 0, gKh, gVh, tid);
    CP_COMMIT();
    CP_WAIT(0);
    __syncthreads();   // Q smem + KV stage0 ready

    // cache Q fragments in registers for the whole loop
    uint32_t qh_fr[8][4];
    #pragma unroll
    for (int kq = 0; kq < 8; kq++) {
        const uint32_t qaddr = smb +
            (uint32_t)((w * 16 + (lane & 15)) * AT_LDS + ((lane >> 4) << 3) + kq * 16) * 2;
        ldsm_x4(qh_fr[kq], qaddr);
    }

    const int ntiles = 2 * qi + 2;
    for (int t = 0; t < ntiles; t++) {
        if (t > 0) {
            CP_WAIT(0);
            __syncthreads();  // stage (t&1) ready AND all warps done with it from t-2
        }
        if (t + 1 < ntiles) {
            kv_load(smb, (t + 1) & 1,
                    gKh + (size_t)(t + 1) * 64 * HD, gVh + (size_t)(t + 1) * 64 * HD, tid);
            CP_COMMIT();
        }

        const uint32_t kb = smb + (Q_ELE + (t & 1) * KVSTAGE_ELE) * 2;

        // ---- scores: S = Qh Kh^T (1-term) ----
        float sacc[8][4];
        #pragma unroll
        for (int j = 0; j < 8; j++)
            #pragma unroll
            for (int k = 0; k < 4; k++) sacc[j][k] = 0.f;

        #pragma unroll
        for (int kq = 0; kq < 8; kq++) {
            uint32_t bh[16];
            #pragma unroll
            for (int n16 = 0; n16 < 4; n16++) {
                const uint32_t kaddr = kb +
                    (uint32_t)((n16 * 16 + (lane & 7) + ((lane >> 4) << 3)) * AT_LDS
                               + (((lane >> 3) & 1) << 3) + kq * 16) * 2;
                ldsm_x4(bh + 4 * n16, kaddr);
            }
            #pragma unroll
            for (int n16 = 0; n16 < 4; n16++) {
                mma16816(sacc[2 * n16],     qh_fr[kq], bh + 4 * n16);
                mma16816(sacc[2 * n16 + 1], qh_fr[kq], bh + 4 * n16 + 2);
            }
        }

        // ---- online softmax (log2 domain) ----
        const bool needmask = (t >= 2 * qi);
        float mt1 = m1s, mt2 = m2s;
        #pragma unroll
        for (int j = 0; j < 8; j++) {
            const int c0 = t * 64 + j * 8 + (lane & 3) * 2;
            #pragma unroll
            for (int k = 0; k < 4; k++) sacc[j][k] *= CSC;
            if (needmask) {
                if (c0     > r1g) sacc[j][0] = NEGINF;
                if (c0 + 1 > r1g) sacc[j][1] = NEGINF;
                if (c0     > r2g) sacc[j][2] = NEGINF;
                if (c0 + 1 > r2g) sacc[j][3] = NEGINF;
            }
            mt1 = fmaxf(mt1, fmaxf(sacc[j][0], sacc[j][1]));
            mt2 = fmaxf(mt2, fmaxf(sacc[j][2], sacc[j][3]));
        }
        mt1 = fmaxf(mt1, __shfl_xor_sync(0xffffffffu, mt1, 1));
        mt1 = fmaxf(mt1, __shfl_xor_sync(0xffffffffu, mt1, 2));
        mt2 = fmaxf(mt2, __shfl_xor_sync(0xffffffffu, mt2, 1));
        mt2 = fmaxf(mt2, __shfl_xor_sync(0xffffffffu, mt2, 2));
        const float f1 = ex2f(m1s - mt1), f2 = ex2f(m2s - mt2);
        m1s = mt1; m2s = mt2;
        float s1 = 0.f, s2 = 0.f;
        #pragma unroll
        for (int j = 0; j < 8; j++) {
            sacc[j][0] = ex2f(sacc[j][0] - mt1);
            sacc[j][1] = ex2f(sacc[j][1] - mt1);
            sacc[j][2] = ex2f(sacc[j][2] - mt2);
            sacc[j][3] = ex2f(sacc[j][3] - mt2);
            s1 += sacc[j][0] + sacc[j][1];
            s2 += sacc[j][2] + sacc[j][3];
        }
        l1 = l1 * f1 + s1;
        l2 = l2 * f2 + s2;
        #pragma unroll
        for (int nf = 0; nf < 16; nf++) {
            oacc[nf][0] *= f1; oacc[nf][1] *= f1;
            oacc[nf][2] *= f2; oacc[nf][3] *= f2;
        }

        // ---- PV: out += Ph Vh (1-term) ----
        #pragma unroll
        for (int kk = 0; kk < 4; kk++) {
            uint32_t a_h[4];
            #pragma unroll
            for (int half = 0; half < 2; half++) {
                a_h[2 * half]     = packh2(sacc[2 * kk + half][0], sacc[2 * kk + half][1]);
                a_h[2 * half + 1] = packh2(sacc[2 * kk + half][2], sacc[2 * kk + half][3]);
            }
            #pragma unroll
            for (int dp = 0; dp < 4; dp++) {    // dc = 2dp, 2dp+1
                uint32_t bvh0[4], bvh1[4];
                const uint32_t va0 = kb + KT_ELE * 2 +
                    (uint32_t)((kk * 16 + (lane & 15)) * AT_LDS + (2 * dp) * 16 + ((lane >> 4) << 3)) * 2;
                const uint32_t va1 = va0 + 32;
                ldsm_x4t(bvh0, va0);
                ldsm_x4t(bvh1, va1);
                mma16816(oacc[4 * dp],     a_h, bvh0);
                mma16816(oacc[4 * dp + 1], a_h, bvh0 + 2);
                mma16816(oacc[4 * dp + 2], a_h, bvh1);
                mma16816(oacc[4 * dp + 3], a_h, bvh1 + 2);
            }
        }
    }

    // ---- epilogue: /l, * sigmoid(gate), write fp16 hi/lo Ctx ----
    l1 += __shfl_xor_sync(0xffffffffu, l1, 1);
    l1 += __shfl_xor_sync(0xffffffffu, l1, 2);
    l2 += __shfl_xor_sync(0xffffffffu, l2, 1);
    l2 += __shfl_xor_sync(0xffffffffu, l2, 2);
    const float inv1 = 1.0f / l1, inv2 = 1.0f / l2;
    #pragma unroll
    for (int nf = 0; nf < 16; nf++) {
        const int dim = nf * 8 + (lane & 3) * 2;
        #pragma unroll
        for (int rr = 0; rr < 2; rr++) {
            const int q = rr ? r2g : r1g;
            const float invl = rr ? inv2 : inv1;
            const float a0 = oacc[nf][2 * rr], a1 = oacc[nf][2 * rr + 1];
            const float2 gt = *(const float2*)(QG + (((size_t)(b * Sn + q) * Hn + h) * 2 * HD) + HD + dim);
            const float v0 = a0 * invl * (1.0f / (1.0f + expf(-gt.x)));
            const float v1 = a1 * invl * (1.0f / (1.0f + expf(-gt.y)));
            const __half h0 = __float2half_rn(v0);
            const __half h1 = __float2half_rn(v1);
            const size_t off = (size_t)(b * Sn + q) * DOUT + h * HD + dim;
            *(__half2*)(Cxh + off) = __halves2half2(h0, h1);
            *(__half2*)(Cxl + off) =
                __halves2half2(__float2half_rn(v0 - __half2float(h0)),
                               __float2half_rn(v1 - __half2float(h1)));
        }
    }
}

// ---------------------------- launcher -------------------------------------
extern "C" void kernel_launch(void* const* d_in, const int* in_sizes, int n_in,
                              void* d_out, int out_size)
{
    const float* x    = (const float*)d_in[0];
    const float* Wq   = (const float*)d_in[1];
    const float* Wk   = (const float*)d_in[2];
    const float* Wv   = (const float*)d_in[3];
    const float* Wo   = (const float*)d_in[4];
    const float* qw   = (const float*)d_in[5];
    const float* kw   = (const float*)d_in[6];
    const float* cosT = (const float*)d_in[7];
    const float* sinT = (const float*)d_in[8];
    float* out = (float*)d_out;

    float *QG, *KV;
    cudaGetSymbolAddress((void**)&QG, g_QG);
    cudaGetSymbolAddress((void**)&KV, g_KV);

    __half *Qhp, *Khp, *Vhp;
    cudaGetSymbolAddress((void**)&Qhp, g_Qh);
    cudaGetSymbolAddress((void**)&Khp, g_Kh);
    cudaGetSymbolAddress((void**)&Vhp, g_Vh);

    __half *xh, *xl, *Wah, *Woh, *Cxh, *Cxl;
    cudaGetSymbolAddress((void**)&xh,  g_xh);
    cudaGetSymbolAddress((void**)&xl,  g_xl);
    cudaGetSymbolAddress((void**)&Wah, g_Wah);
    cudaGetSymbolAddress((void**)&Woh, g_Woh);
    cudaGetSymbolAddress((void**)&Cxh, g_Cxh);
    cudaGetSymbolAddress((void**)&Cxl, g_Cxl);

    cudaFuncSetAttribute(gemm_tc, cudaFuncAttributeMaxDynamicSharedMemorySize, GEMM_SMEM);
    cudaFuncSetAttribute(attn_mma, cudaFuncAttributeMaxDynamicSharedMemorySize, ATT_SMEM);

    const int M = Mrows;          // 4096
    const int NKV = 2 * Gn * HD;  // 1024

    // (1) split x; (2-4) transpose Wq|Wk|Wv (hi only)
    fsplit<<<(M * DIN / 4 + 255) / 256, 256>>>(x, xh, xl, M * DIN);
    tsplit<<<dim3((2 * DOUT) / 32, DIN / 32), dim3(32, 8)>>>(Wq, Wah, DIN, 2 * DOUT);
    tsplit<<<dim3((Gn * HD) / 32, DIN / 32), dim3(32, 8)>>>(
        Wk, Wah + (size_t)(2 * DOUT) * DIN, DIN, Gn * HD);
    tsplit<<<dim3((Gn * HD) / 32, DIN / 32), dim3(32, 8)>>>(
        Wv, Wah + (size_t)(2 * DOUT + Gn * HD) * DIN, DIN, Gn * HD);

    // (5) merged QKV projection, 1-term gate tiles  [profiled launch]
    gemm_tc<<<dim3(NQKV / 128, M / 256), 256, GEMM_SMEM>>>(
        xh, xl, Wah, QG, KV, M, 2 * DOUT, NKV, DIN, 1);

    // (6) Wo transpose
    tsplit<<<dim3(DIN / 32, DOUT / 32), dim3(32, 8)>>>(Wo, Woh, DOUT, DIN);

    // (7-8) norm + rope -> fp16
    qnorm_rope<<<dim3(Sn, Hn, Bn), 128>>>(QG, qw, cosT, sinT, Qhp);
    knorm_rope_v<<<dim3(Sn, Gn, Bn), 128>>>(KV, kw, cosT, sinT, Khp, Vhp);

    // (9) HMMA causal attention + gate (1-term), fused fp16 split epilogue
    attn_mma<<<dim3(Sn / 128, Hn, Bn), 256, ATT_SMEM>>>(
        Qhp, Khp, Vhp, QG, Cxh, Cxl);

    // (10) output projection (2-term)
    gemm_tc<<<dim3(DIN / 128, M / 256), 256, GEMM_SMEM>>>(
        Cxh, Cxl, Woh, out, (float*)nullptr, M, DIN, 0, DOUT, 0);
}

// round 14
// speedup vs baseline: 1.9651x; 1.2058x over previous
#include <cuda_runtime.h>
#include <cuda_fp16.h>
#include <math.h>
#include <stdint.h>

#define Bn    2
#define Sn    2048
#define DIN   2048
#define Hn    16
#define Gn    4
#define HD    128
#define DOUT  2048
#define GROUPn 4          // H / G
#define EPSf  1e-6f
#define Mrows (Bn*Sn)     // 4096
#define NQKV  (2*DOUT + 2*Gn*HD)   // 5120 = Wq(4096) | Wk(512) | Wv(512)

// ---------------- scratch (device globals; no allocation allowed) ----------
__device__ float g_QG  [(size_t)Bn*Sn*Hn*2*HD];   // [b,s,h,2*HD]  (q | gate)
__device__ float g_KV  [(size_t)Bn*Sn*(2*Gn*HD)]; // [b,s, K(512) | V(512)]

// fp16 attention operands (hi only)
__device__ __half g_Qh[(size_t)Bn*Hn*Sn*HD];
__device__ __half g_Kh[(size_t)Bn*Gn*Sn*HD];
__device__ __half g_Vh[(size_t)Bn*Gn*Sn*HD];

// fp16 scratch for GEMMs
__device__ __half g_xh [(size_t)Mrows*DIN];          // x hi (1-term QKV)
__device__ __half g_Wah[(size_t)NQKV*DIN];           // packed Wq|Wk|Wv, [N][K]
__device__ __half g_Woh[(size_t)DIN*DOUT];           // hi only
__device__ __half g_Cxh[(size_t)Mrows*DOUT];         // ctx hi
__device__ __half g_Cxl[(size_t)Mrows*DOUT];         // ctx lo (Wo stays 2-term)

// ======================= PTX helpers (compute_103 baseline only) ==========
__device__ __forceinline__ uint32_t smem_u32(const void* p) {
    uint32_t a;
    asm("{ .reg .u64 t; cvta.to.shared.u64 t, %1; cvt.u32.u64 %0, t; }" : "=r"(a) : "l"(p));
    return a;
}
__device__ __forceinline__ void cp16(uint32_t s, const void* g) {
    asm volatile("cp.async.cg.shared.global [%0], [%1], 16;" :: "r"(s), "l"(g));
}
#define CP_COMMIT() asm volatile("cp.async.commit_group;" ::: "memory")
#define CP_WAIT(n)  asm volatile("cp.async.wait_group %0;" :: "n"(n) : "memory")

__device__ __forceinline__ void ldsm_x4(uint32_t* r, uint32_t addr) {
    asm volatile("ldmatrix.sync.aligned.m8n8.x4.shared.b16 {%0,%1,%2,%3}, [%4];"
        : "=r"(r[0]), "=r"(r[1]), "=r"(r[2]), "=r"(r[3]) : "r"(addr));
}
__device__ __forceinline__ void ldsm_x4t(uint32_t* r, uint32_t addr) {
    asm volatile("ldmatrix.sync.aligned.m8n8.x4.trans.shared.b16 {%0,%1,%2,%3}, [%4];"
        : "=r"(r[0]), "=r"(r[1]), "=r"(r[2]), "=r"(r[3]) : "r"(addr));
}
__device__ __forceinline__ void mma16816(float* d, const uint32_t* a, const uint32_t* b) {
    asm volatile(
        "mma.sync.aligned.m16n8k16.row.col.f32.f16.f16.f32 "
        "{%0,%1,%2,%3}, {%4,%5,%6,%7}, {%8,%9}, {%0,%1,%2,%3};"
        : "+f"(d[0]), "+f"(d[1]), "+f"(d[2]), "+f"(d[3])
        : "r"(a[0]), "r"(a[1]), "r"(a[2]), "r"(a[3]), "r"(b[0]), "r"(b[1]));
}
__device__ __forceinline__ float ex2f(float x) {
    float r; asm("ex2.approx.f32 %0, %1;" : "=f"(r) : "f"(x)); return r;
}
__device__ __forceinline__ uint32_t packh2(float lo, float hi) {
    uint32_t r; asm("cvt.rn.f16x2.f32 %0, %1, %2;" : "=r"(r) : "f"(hi), "f"(lo)); return r;
}

// ======================= convert / transpose ==========================
__global__ __launch_bounds__(256) void fconv(const float* __restrict__ in,
                                             __half* __restrict__ h, int n)
{
    int i = (blockIdx.x * 256 + threadIdx.x) * 4;
    if (i >= n) return;
    float4 v = *(const float4*)(in + i);
    *(__half2*)(h + i)     = __halves2half2(__float2half_rn(v.x), __float2half_rn(v.y));
    *(__half2*)(h + i + 2) = __halves2half2(__float2half_rn(v.z), __float2half_rn(v.w));
}

// W[K,N] fp32 -> Th[N,K] fp16 hi (transpose)
__global__ __launch_bounds__(256) void tsplit(const float* __restrict__ W,
                                              __half* __restrict__ Th,
                                              int K, int N)
{
    __shared__ float t[32][33];
    const int n0 = blockIdx.x * 32, k0 = blockIdx.y * 32;
    const int tx = threadIdx.x, ty = threadIdx.y;  // (32, 8)
    #pragma unroll
    for (int r = 0; r < 4; r++)
        t[ty + r * 8][tx] = W[(size_t)(k0 + ty + r * 8) * N + n0 + tx];
    __syncthreads();
    #pragma unroll
    for (int r = 0; r < 4; r++) {
        int n = n0 + ty + r * 8, k = k0 + tx;
        Th[(size_t)n * K + k] = __float2half_rn(t[tx][ty + r * 8]);
    }
}

// ======================= HMMA fp16 GEMM (256x128, 3-stage) =================
// mode 0: C = (Ah+Al)*Bh^T (2-term).  mode 2: C = Ah*Bh^T (1-term, Al unused).
// A [M,K], B hi [N0+N1][K], K-major fp16. Output: n-tile < N0 -> C0 else C1.
#define GBK    32
#define LDS    40
#define ATILEB (256 * LDS * 2)   // 20480 B
#define BTILEB (128 * LDS * 2)   // 10240 B
#define STAGEB (2 * ATILEB + BTILEB)      // 51200 B
#define NSTAGE 3
#define GEMM_SMEM (NSTAGE * STAGEB)       // 153600 B
#define OFF_AL  ATILEB
#define OFF_BH  (2 * ATILEB)

__device__ __forceinline__ void load_stage(
    uint32_t smb, int stage,
    const __half* __restrict__ pAh, const __half* __restrict__ pAl,
    const __half* __restrict__ pBh,
    int K, int kc, int tid, bool skip_al)
{
    const uint32_t sb = smb + stage * STAGEB;
    #pragma unroll
    for (int i = 0; i < 4; i++) {
        const int u = tid + i * 256;
        const int row = u >> 2, col = (u & 3) * 8;
        const uint32_t so = (uint32_t)(row * LDS + col) * 2;
        const size_t g = (size_t)row * K + kc + col;
        cp16(sb + so, pAh + g);
        if (!skip_al) cp16(sb + OFF_AL + so, pAl + g);
    }
    #pragma unroll
    for (int i = 0; i < 2; i++) {
        const int u = tid + i * 256;
        const int row = u >> 2, col = (u & 3) * 8;
        const uint32_t so = (uint32_t)(row * LDS + col) * 2;
        cp16(sb + OFF_BH + so, pBh + (size_t)row * K + kc + col);
    }
}

__global__ __launch_bounds__(256, 1) void gemm_tc(
    const __half* __restrict__ Ah, const __half* __restrict__ Al,
    const __half* __restrict__ Bh,
    float* __restrict__ C0, float* __restrict__ C1,
    int M, int N0, int N1, int K, int mode)
{
    extern __shared__ char sm[];
    const uint32_t smb = smem_u32(sm);
    const int tid  = threadIdx.x;
    const int wid  = tid >> 5, lane = tid & 31;
    const int wm   = wid & 3;
    const int wn   = wid >> 2;
    const int mbr  = blockIdx.y * 256, nbr = blockIdx.x * 128;

    float* Cb;
    int Nout, ncol;
    if (nbr < N0) { Cb = C0; Nout = N0; ncol = nbr; }
    else          { Cb = C1; Nout = N1; ncol = nbr - N0; }
    const bool one_term = (mode == 2);

    const __half* pAh = Ah + (size_t)mbr * K;
    const __half* pAl = Al + (size_t)mbr * K;
    const __half* pBh = Bh + (size_t)nbr * K;

    float acc[4][8][4];
    #pragma unroll
    for (int i = 0; i < 4; i++)
        #pragma unroll
        for (int j = 0; j < 8; j++)
            #pragma unroll
            for (int k = 0; k < 4; k++) acc[i][j][k] = 0.f;

    const uint32_t aoff = (uint32_t)((wm * 64 + (lane & 15)) * LDS + ((lane >> 4) * 8)) * 2;
    const uint32_t boff = (uint32_t)((wn * 64 + (lane & 7) + ((lane >> 4) << 3)) * LDS
                                     + (((lane >> 3) & 1) * 8)) * 2;

    const int NC = K / GBK;
    load_stage(smb, 0, pAh, pAl, pBh, K, 0, tid, one_term);
    CP_COMMIT();
    load_stage(smb, 1, pAh, pAl, pBh, K, GBK, tid, one_term);
    CP_COMMIT();

    int st_idx = 0;
    for (int c = 0; c < NC; c++) {
        if (c + 1 < NC) { CP_WAIT(1); } else { CP_WAIT(0); }
        __syncthreads();
        if (c + 2 < NC) {
            int ns = st_idx + 2; if (ns >= NSTAGE) ns -= NSTAGE;
            load_stage(smb, ns, pAh, pAl, pBh, K, (c + 2) * GBK, tid, one_term);
            CP_COMMIT();
        }

        const uint32_t st = smb + st_idx * STAGEB;
        #pragma unroll
        for (int ks = 0; ks < 2; ks++) {
            const uint32_t kb = ks * 32;
            uint32_t bh[16];
            #pragma unroll
            for (int n16 = 0; n16 < 4; n16++)
                ldsm_x4(bh + 4 * n16, st + OFF_BH + boff + n16 * (16 * LDS * 2) + kb);
            #pragma unroll
            for (int mf = 0; mf < 4; mf++) {
                uint32_t ah[4];
                ldsm_x4(ah, st + aoff + mf * (16 * LDS * 2) + kb);
                #pragma unroll
                for (int nf = 0; nf < 8; nf++)
                    mma16816(acc[mf][nf], ah, &bh[(nf >> 1) * 4 + (nf & 1) * 2]);
                if (!one_term) {
                    uint32_t al[4];
                    ldsm_x4(al, st + OFF_AL + aoff + mf * (16 * LDS * 2) + kb);
                    #pragma unroll
                    for (int nf = 0; nf < 8; nf++)
                        mma16816(acc[mf][nf], al, &bh[(nf >> 1) * 4 + (nf & 1) * 2]);
                }
            }
        }
        if (++st_idx == NSTAGE) st_idx = 0;
    }

    #pragma unroll
    for (int mf = 0; mf < 4; mf++) {
        const int r0 = mbr + wm * 64 + mf * 16 + (lane >> 2);
        #pragma unroll
        for (int nf = 0; nf < 8; nf++) {
            const int n0 = ncol + wn * 64 + nf * 8 + (lane & 3) * 2;
            *(float2*)(Cb + (size_t)r0 * Nout + n0)       = make_float2(acc[mf][nf][0], acc[mf][nf][1]);
            *(float2*)(Cb + (size_t)(r0 + 8) * Nout + n0) = make_float2(acc[mf][nf][2], acc[mf][nf][3]);
        }
    }
}

// ---------------- rmsnorm + rope for Q -> fp16 hi --------------------------
__global__ __launch_bounds__(128) void qnorm_rope(
    const float* __restrict__ QG, const float* __restrict__ w,
    const float* __restrict__ cosT, const float* __restrict__ sinT,
    __half* __restrict__ Qh)
{
    const int s = blockIdx.x, h = blockIdx.y, b = blockIdx.z;
    const int d = threadIdx.x;
    const float* src = QG + (((size_t)(b * Sn + s) * Hn + h) * 2 * HD);
    float x = src[d];
    float ss = x * x;
    #pragma unroll
    for (int o = 16; o > 0; o >>= 1) ss += __shfl_xor_sync(0xffffffffu, ss, o);
    __shared__ float wsum[4];
    if ((d & 31) == 0) wsum[d >> 5] = ss;
    __syncthreads();
    float tot = wsum[0] + wsum[1] + wsum[2] + wsum[3];
    float inv = rsqrtf(tot * (1.0f / HD) + EPSf);
    float n = x * inv * (1.0f + w[d]);
    __shared__ float nb[HD];
    nb[d] = n;
    __syncthreads();
    float c  = cosT[(size_t)s * HD + d];
    float sn = sinT[(size_t)s * HD + d];
    float rot = (d < HD / 2) ? -nb[d + HD / 2] : nb[d - HD / 2];
    float y = n * c + rot * sn;
    Qh[((size_t)(b * Hn + h) * Sn + s) * HD + d] = __float2half_rn(y);
}

// ---------------- rmsnorm + rope for K -> fp16 hi, V -> fp16 hi ------------
__global__ __launch_bounds__(128) void knorm_rope_v(
    const float* __restrict__ KV,
    const float* __restrict__ w,
    const float* __restrict__ cosT, const float* __restrict__ sinT,
    __half* __restrict__ Kh, __half* __restrict__ Vh)
{
    const int s = blockIdx.x, g = blockIdx.y, b = blockIdx.z;
    const int d = threadIdx.x;
    const float* row = KV + (size_t)(b * Sn + s) * (2 * Gn * HD) + g * HD;
    float x = row[d];
    float ss = x * x;
    #pragma unroll
    for (int o = 16; o > 0; o >>= 1) ss += __shfl_xor_sync(0xffffffffu, ss, o);
    __shared__ float wsum[4];
    if ((d & 31) == 0) wsum[d >> 5] = ss;
    __syncthreads();
    float tot = wsum[0] + wsum[1] + wsum[2] + wsum[3];
    float inv = rsqrtf(tot * (1.0f / HD) + EPSf);
    float n = x * inv * (1.0f + w[d]);
    __shared__ float nb[HD];
    nb[d] = n;
    __syncthreads();
    float c  = cosT[(size_t)s * HD + d];
    float sn = sinT[(size_t)s * HD + d];
    float rot = (d < HD / 2) ? -nb[d + HD / 2] : nb[d - HD / 2];
    float y = n * c + rot * sn;
    const size_t dst = ((size_t)(b * Gn + g) * Sn + s) * HD + d;
    Kh[dst] = __float2half_rn(y);
    Vh[dst] = __float2half_rn(row[Gn * HD + d]);
}

// ================= HMMA causal flash attention + sigmoid gate ==============
// BQ=128 (8 warps x m16), BK=64, HD=128. 1-term fp16: Qh*Kh, Ph*Vh.
// Q fragments cached in registers. Single __syncthreads per tile.
// Epilogue writes fp16 hi/lo Ctx (A side of Wo GEMM).
#define AT_LDS  136
#define Q_ELE   (128 * AT_LDS)
#define KT_ELE  (64 * AT_LDS)
#define KVSTAGE_ELE (2 * KT_ELE)
#define ATT_SMEM ((Q_ELE + 2 * KVSTAGE_ELE) * 2)   // 104448 bytes
#define CSC 0.12751666806979654f    // (1/sqrt(128)) * log2(e)
#define NEGINF __int_as_float(0xff800000)

__device__ __forceinline__ void kv_load(
    uint32_t smb, int stage,
    const __half* kh, const __half* vh, int tid)
{
    const uint32_t base = smb + (Q_ELE + stage * KVSTAGE_ELE) * 2;
    #pragma unroll
    for (int i = 0; i < 4; i++) {
        int u = tid + i * 256;          // 0..1023
        int til = u >> 9;               // 0: Kh, 1: Vh
        int uu = u & 511;
        int row = uu >> 3, c8 = (uu & 7) * 16;
        uint32_t so = (uint32_t)(row * AT_LDS + c8) * 2;
        const __half* src = til ? vh : kh;
        cp16(base + (uint32_t)til * (KT_ELE * 2) + so, src + (size_t)row * HD + c8);
        cp16(base + (uint32_t)til * (KT_ELE * 2) + so + 16, src + (size_t)row * HD + c8 + 8);
    }
}

__global__ __launch_bounds__(256, 1) void attn_mma(
    const __half* __restrict__ Qh,
    const __half* __restrict__ Kh, const __half* __restrict__ Vh,
    const float* __restrict__ QG,
    __half* __restrict__ Cxh, __half* __restrict__ Cxl)
{
    extern __shared__ __half smem_h[];
    const uint32_t smb = smem_u32(smem_h);
    const int qi = blockIdx.x, h = blockIdx.y, b = blockIdx.z;
    const int g  = h / GROUPn;
    const int tid = threadIdx.x, lane = tid & 31, w = tid >> 5;

    const __half* gQh = Qh + ((size_t)(b * Hn + h) * Sn + (size_t)qi * 128) * HD;
    const __half* gKh = Kh + ((size_t)(b * Gn + g) * Sn) * HD;
    const __half* gVh = Vh + ((size_t)(b * Gn + g) * Sn) * HD;

    // load Q hi into smem (128 x 128)
    #pragma unroll
    for (int i = 0; i < 8; i++) {
        int u = tid + i * 256;
        int row = u >> 4, c8 = (u & 15) * 8;
        *(uint4*)(smem_h + row * AT_LDS + c8) = *(const uint4*)(gQh + (size_t)row * HD + c8);
    }

    float m1s = NEGINF, m2s = NEGINF, l1 = 0.f, l2 = 0.f;
    float oacc[16][4];
    #pragma unroll
    for (int nf = 0; nf < 16; nf++)
        #pragma unroll
        for (int k = 0; k < 4; k++) oacc[nf][k] = 0.f;

    const int r1rel = w * 16 + (lane >> 2);   // 0..127
    const int r1g = qi * 128 + r1rel;
    const int r2g = r1g + 8;

    kv_load(smb, 0, gKh, gVh, tid);
    CP_COMMIT();
    CP_WAIT(0);
    __syncthreads();   // Q smem + KV stage0 ready

    // cache Q fragments in registers for the whole loop
    uint32_t qh_fr[8][4];
    #pragma unroll
    for (int kq = 0; kq < 8; kq++) {
        const uint32_t qaddr = smb +
            (uint32_t)((w * 16 + (lane & 15)) * AT_LDS + ((lane >> 4) << 3) + kq * 16) * 2;
        ldsm_x4(qh_fr[kq], qaddr);
    }

    const int ntiles = 2 * qi + 2;
    for (int t = 0; t < ntiles; t++) {
        if (t > 0) {
            CP_WAIT(0);
            __syncthreads();
        }
        if (t + 1 < ntiles) {
            kv_load(smb, (t + 1) & 1,
                    gKh + (size_t)(t + 1) * 64 * HD, gVh + (size_t)(t + 1) * 64 * HD, tid);
            CP_COMMIT();
        }

        const uint32_t kb = smb + (Q_ELE + (t & 1) * KVSTAGE_ELE) * 2;

        // ---- scores: S = Qh Kh^T (1-term) ----
        float sacc[8][4];
        #pragma unroll
        for (int j = 0; j < 8; j++)
            #pragma unroll
            for (int k = 0; k < 4; k++) sacc[j][k] = 0.f;

        #pragma unroll
        for (int kq = 0; kq < 8; kq++) {
            uint32_t bh[16];
            #pragma unroll
            for (int n16 = 0; n16 < 4; n16++) {
                const uint32_t kaddr = kb +
                    (uint32_t)((n16 * 16 + (lane & 7) + ((lane >> 4) << 3)) * AT_LDS
                               + (((lane >> 3) & 1) << 3) + kq * 16) * 2;
                ldsm_x4(bh + 4 * n16, kaddr);
            }
            #pragma unroll
            for (int n16 = 0; n16 < 4; n16++) {
                mma16816(sacc[2 * n16],     qh_fr[kq], bh + 4 * n16);
                mma16816(sacc[2 * n16 + 1], qh_fr[kq], bh + 4 * n16 + 2);
            }
        }

        // ---- online softmax (log2 domain) ----
        const bool needmask = (t >= 2 * qi);
        float mt1 = m1s, mt2 = m2s;
        #pragma unroll
        for (int j = 0; j < 8; j++) {
            const int c0 = t * 64 + j * 8 + (lane & 3) * 2;
            #pragma unroll
            for (int k = 0; k < 4; k++) sacc[j][k] *= CSC;
            if (needmask) {
                if (c0     > r1g) sacc[j][0] = NEGINF;
                if (c0 + 1 > r1g) sacc[j][1] = NEGINF;
                if (c0     > r2g) sacc[j][2] = NEGINF;
                if (c0 + 1 > r2g) sacc[j][3] = NEGINF;
            }
            mt1 = fmaxf(mt1, fmaxf(sacc[j][0], sacc[j][1]));
            mt2 = fmaxf(mt2, fmaxf(sacc[j][2], sacc[j][3]));
        }
        mt1 = fmaxf(mt1, __shfl_xor_sync(0xffffffffu, mt1, 1));
        mt1 = fmaxf(mt1, __shfl_xor_sync(0xffffffffu, mt1, 2));
        mt2 = fmaxf(mt2, __shfl_xor_sync(0xffffffffu, mt2, 1));
        mt2 = fmaxf(mt2, __shfl_xor_sync(0xffffffffu, mt2, 2));
        const float f1 = ex2f(m1s - mt1), f2 = ex2f(m2s - mt2);
        m1s = mt1; m2s = mt2;
        float s1 = 0.f, s2 = 0.f;
        #pragma unroll
        for (int j = 0; j < 8; j++) {
            sacc[j][0] = ex2f(sacc[j][0] - mt1);
            sacc[j][1] = ex2f(sacc[j][1] - mt1);
            sacc[j][2] = ex2f(sacc[j][2] - mt2);
            sacc[j][3] = ex2f(sacc[j][3] - mt2);
            s1 += sacc[j][0] + sacc[j][1];
            s2 += sacc[j][2] + sacc[j][3];
        }
        l1 = l1 * f1 + s1;
        l2 = l2 * f2 + s2;
        #pragma unroll
        for (int nf = 0; nf < 16; nf++) {
            oacc[nf][0] *= f1; oacc[nf][1] *= f1;
            oacc[nf][2] *= f2; oacc[nf][3] *= f2;
        }

        // ---- PV: out += Ph Vh (1-term) ----
        #pragma unroll
        for (int kk = 0; kk < 4; kk++) {
            uint32_t a_h[4];
            #pragma unroll
            for (int half = 0; half < 2; half++) {
                a_h[2 * half]     = packh2(sacc[2 * kk + half][0], sacc[2 * kk + half][1]);
                a_h[2 * half + 1] = packh2(sacc[2 * kk + half][2], sacc[2 * kk + half][3]);
            }
            #pragma unroll
            for (int dp = 0; dp < 4; dp++) {    // dc = 2dp, 2dp+1
                uint32_t bvh0[4], bvh1[4];
                const uint32_t va0 = kb + KT_ELE * 2 +
                    (uint32_t)((kk * 16 + (lane & 15)) * AT_LDS + (2 * dp) * 16 + ((lane >> 4) << 3)) * 2;
                const uint32_t va1 = va0 + 32;
                ldsm_x4t(bvh0, va0);
                ldsm_x4t(bvh1, va1);
                mma16816(oacc[4 * dp],     a_h, bvh0);
                mma16816(oacc[4 * dp + 1], a_h, bvh0 + 2);
                mma16816(oacc[4 * dp + 2], a_h, bvh1);
                mma16816(oacc[4 * dp + 3], a_h, bvh1 + 2);
            }
        }
    }

    // ---- epilogue: /l, * sigmoid(gate), write fp16 hi/lo Ctx ----
    l1 += __shfl_xor_sync(0xffffffffu, l1, 1);
    l1 += __shfl_xor_sync(0xffffffffu, l1, 2);
    l2 += __shfl_xor_sync(0xffffffffu, l2, 1);
    l2 += __shfl_xor_sync(0xffffffffu, l2, 2);
    const float inv1 = 1.0f / l1, inv2 = 1.0f / l2;
    #pragma unroll
    for (int nf = 0; nf < 16; nf++) {
        const int dim = nf * 8 + (lane & 3) * 2;
        #pragma unroll
        for (int rr = 0; rr < 2; rr++) {
            const int q = rr ? r2g : r1g;
            const float invl = rr ? inv2 : inv1;
            const float a0 = oacc[nf][2 * rr], a1 = oacc[nf][2 * rr + 1];
            const float2 gt = *(const float2*)(QG + (((size_t)(b * Sn + q) * Hn + h) * 2 * HD) + HD + dim);
            const float v0 = a0 * invl * (1.0f / (1.0f + expf(-gt.x)));
            const float v1 = a1 * invl * (1.0f / (1.0f + expf(-gt.y)));
            const __half h0 = __float2half_rn(v0);
            const __half h1 = __float2half_rn(v1);
            const size_t off = (size_t)(b * Sn + q) * DOUT + h * HD + dim;
            *(__half2*)(Cxh + off) = __halves2half2(h0, h1);
            *(__half2*)(Cxl + off) =
                __halves2half2(__float2half_rn(v0 - __half2float(h0)),
                               __float2half_rn(v1 - __half2float(h1)));
        }
    }
}

// ---------------------------- launcher -------------------------------------
extern "C" void kernel_launch(void* const* d_in, const int* in_sizes, int n_in,
                              void* d_out, int out_size)
{
    const float* x    = (const float*)d_in[0];
    const float* Wq   = (const float*)d_in[1];
    const float* Wk   = (const float*)d_in[2];
    const float* Wv   = (const float*)d_in[3];
    const float* Wo   = (const float*)d_in[4];
    const float* qw   = (const float*)d_in[5];
    const float* kw   = (const float*)d_in[6];
    const float* cosT = (const float*)d_in[7];
    const float* sinT = (const float*)d_in[8];
    float* out = (float*)d_out;

    float *QG, *KV;
    cudaGetSymbolAddress((void**)&QG, g_QG);
    cudaGetSymbolAddress((void**)&KV, g_KV);

    __half *Qhp, *Khp, *Vhp;
    cudaGetSymbolAddress((void**)&Qhp, g_Qh);
    cudaGetSymbolAddress((void**)&Khp, g_Kh);
    cudaGetSymbolAddress((void**)&Vhp, g_Vh);

    __half *xh, *Wah, *Woh, *Cxh, *Cxl;
    cudaGetSymbolAddress((void**)&xh,  g_xh);
    cudaGetSymbolAddress((void**)&Wah, g_Wah);
    cudaGetSymbolAddress((void**)&Woh, g_Woh);
    cudaGetSymbolAddress((void**)&Cxh, g_Cxh);
    cudaGetSymbolAddress((void**)&Cxl, g_Cxl);

    cudaFuncSetAttribute(gemm_tc, cudaFuncAttributeMaxDynamicSharedMemorySize, GEMM_SMEM);
    cudaFuncSetAttribute(attn_mma, cudaFuncAttributeMaxDynamicSharedMemorySize, ATT_SMEM);

    const int M = Mrows;          // 4096
    const int NKV = 2 * Gn * HD;  // 1024

    // (1) convert x to fp16; (2-4) transpose Wq|Wk|Wv
    fconv<<<(M * DIN / 4 + 255) / 256, 256>>>(x, xh, M * DIN);
    tsplit<<<dim3((2 * DOUT) / 32, DIN / 32), dim3(32, 8)>>>(Wq, Wah, DIN, 2 * DOUT);
    tsplit<<<dim3((Gn * HD) / 32, DIN / 32), dim3(32, 8)>>>(
        Wk, Wah + (size_t)(2 * DOUT) * DIN, DIN, Gn * HD);
    tsplit<<<dim3((Gn * HD) / 32, DIN / 32), dim3(32, 8)>>>(
        Wv, Wah + (size_t)(2 * DOUT + Gn * HD) * DIN, DIN, Gn * HD);

    // (5) merged QKV projection, all 1-term  [profiled launch]
    gemm_tc<<<dim3(NQKV / 128, M / 256), 256, GEMM_SMEM>>>(
        xh, xh, Wah, QG, KV, M, 2 * DOUT, NKV, DIN, 2);

    // (6) Wo transpose
    tsplit<<<dim3(DIN / 32, DOUT / 32), dim3(32, 8)>>>(Wo, Woh, DOUT, DIN);

    // (7-8) norm + rope -> fp16
    qnorm_rope<<<dim3(Sn, Hn, Bn), 128>>>(QG, qw, cosT, sinT, Qhp);
    knorm_rope_v<<<dim3(Sn, Gn, Bn), 128>>>(KV, kw, cosT, sinT, Khp, Vhp);

    // (9) HMMA causal attention + gate (1-term), fused fp16 split epilogue
    attn_mma<<<dim3(Sn / 128, Hn, Bn), 256, ATT_SMEM>>>(
        Qhp, Khp, Vhp, QG, Cxh, Cxl);

    // (10) output projection (2-term: Cx hi/lo)
    gemm_tc<<<dim3(DIN / 128, M / 256), 256, GEMM_SMEM>>>(
        Cxh, Cxl, Woh, out, (float*)nullptr, M, DIN, 0, DOUT, 0);
}

// round 15
// speedup vs baseline: 2.2439x; 1.1419x over previous
#include <cuda_runtime.h>
#include <cuda_fp16.h>
#include <math.h>
#include <stdint.h>

#define Bn    2
#define Sn    2048
#define DIN   2048
#define Hn    16
#define Gn    4
#define HD    128
#define DOUT  2048
#define GROUPn 4          // H / G
#define EPSf  1e-6f
#define Mrows (Bn*Sn)     // 4096
#define NQKV  (2*DOUT + 2*Gn*HD)   // 5120 = Wq(4096) | Wk(512) | Wv(512)

// ---------------- scratch (device globals; no allocation allowed) ----------
__device__ float g_QG  [(size_t)Bn*Sn*Hn*2*HD];   // [b,s,h,2*HD]  (q | gate)
__device__ float g_KV  [(size_t)Bn*Sn*(2*Gn*HD)]; // [b,s, K(512) | V(512)]

// fp16 attention operands (hi only)
__device__ __half g_Qh[(size_t)Bn*Hn*Sn*HD];
__device__ __half g_Kh[(size_t)Bn*Gn*Sn*HD];
__device__ __half g_Vh[(size_t)Bn*Gn*Sn*HD];

// fp16 scratch for GEMMs
__device__ __half g_xh [(size_t)Mrows*DIN];          // x hi (1-term QKV)
__device__ __half g_Wah[(size_t)NQKV*DIN];           // packed Wq|Wk|Wv, [N][K]
__device__ __half g_Woh[(size_t)DIN*DOUT];           // hi only
__device__ __half g_Cxh[(size_t)Mrows*DOUT];         // ctx (1-term Wo)

// ======================= PTX helpers (compute_103 baseline only) ==========
__device__ __forceinline__ uint32_t smem_u32(const void* p) {
    uint32_t a;
    asm("{ .reg .u64 t; cvta.to.shared.u64 t, %1; cvt.u32.u64 %0, t; }" : "=r"(a) : "l"(p));
    return a;
}
__device__ __forceinline__ void cp16(uint32_t s, const void* g) {
    asm volatile("cp.async.cg.shared.global [%0], [%1], 16;" :: "r"(s), "l"(g));
}
#define CP_COMMIT() asm volatile("cp.async.commit_group;" ::: "memory")
#define CP_WAIT(n)  asm volatile("cp.async.wait_group %0;" :: "n"(n) : "memory")

__device__ __forceinline__ void ldsm_x4(uint32_t* r, uint32_t addr) {
    asm volatile("ldmatrix.sync.aligned.m8n8.x4.shared.b16 {%0,%1,%2,%3}, [%4];"
        : "=r"(r[0]), "=r"(r[1]), "=r"(r[2]), "=r"(r[3]) : "r"(addr));
}
__device__ __forceinline__ void ldsm_x4t(uint32_t* r, uint32_t addr) {
    asm volatile("ldmatrix.sync.aligned.m8n8.x4.trans.shared.b16 {%0,%1,%2,%3}, [%4];"
        : "=r"(r[0]), "=r"(r[1]), "=r"(r[2]), "=r"(r[3]) : "r"(addr));
}
__device__ __forceinline__ void mma16816(float* d, const uint32_t* a, const uint32_t* b) {
    asm volatile(
        "mma.sync.aligned.m16n8k16.row.col.f32.f16.f16.f32 "
        "{%0,%1,%2,%3}, {%4,%5,%6,%7}, {%8,%9}, {%0,%1,%2,%3};"
        : "+f"(d[0]), "+f"(d[1]), "+f"(d[2]), "+f"(d[3])
        : "r"(a[0]), "r"(a[1]), "r"(a[2]), "r"(a[3]), "r"(b[0]), "r"(b[1]));
}
__device__ __forceinline__ float ex2f(float x) {
    float r; asm("ex2.approx.f32 %0, %1;" : "=f"(r) : "f"(x)); return r;
}
__device__ __forceinline__ uint32_t packh2(float lo, float hi) {
    uint32_t r; asm("cvt.rn.f16x2.f32 %0, %1, %2;" : "=r"(r) : "f"(hi), "f"(lo)); return r;
}

// ======================= convert / transpose ==========================
__global__ __launch_bounds__(256) void fconv(const float* __restrict__ in,
                                             __half* __restrict__ h, int n)
{
    int i = (blockIdx.x * 256 + threadIdx.x) * 4;
    if (i >= n) return;
    float4 v = *(const float4*)(in + i);
    *(__half2*)(h + i)     = __halves2half2(__float2half_rn(v.x), __float2half_rn(v.y));
    *(__half2*)(h + i + 2) = __halves2half2(__float2half_rn(v.z), __float2half_rn(v.w));
}

// W[K,N] fp32 -> Th[N,K] fp16 hi (transpose)
__global__ __launch_bounds__(256) void tsplit(const float* __restrict__ W,
                                              __half* __restrict__ Th,
                                              int K, int N)
{
    __shared__ float t[32][33];
    const int n0 = blockIdx.x * 32, k0 = blockIdx.y * 32;
    const int tx = threadIdx.x, ty = threadIdx.y;  // (32, 8)
    #pragma unroll
    for (int r = 0; r < 4; r++)
        t[ty + r * 8][tx] = W[(size_t)(k0 + ty + r * 8) * N + n0 + tx];
    __syncthreads();
    #pragma unroll
    for (int r = 0; r < 4; r++) {
        int n = n0 + ty + r * 8, k = k0 + tx;
        Th[(size_t)n * K + k] = __float2half_rn(t[tx][ty + r * 8]);
    }
}

// ======================= HMMA fp16 GEMM (256x128, 3-stage) =================
// mode 0: C = (Ah+Al)*Bh^T (2-term).  mode 2: C = Ah*Bh^T (1-term, Al unused).
// A [M,K], B hi [N0+N1][K], K-major fp16. Output: n-tile < N0 -> C0 else C1.
#define GBK    32
#define LDS    40
#define ATILEB (256 * LDS * 2)   // 20480 B
#define BTILEB (128 * LDS * 2)   // 10240 B
#define STAGEB (2 * ATILEB + BTILEB)      // 51200 B
#define NSTAGE 3
#define GEMM_SMEM (NSTAGE * STAGEB)       // 153600 B
#define OFF_AL  ATILEB
#define OFF_BH  (2 * ATILEB)

__device__ __forceinline__ void load_stage(
    uint32_t smb, int stage,
    const __half* __restrict__ pAh, const __half* __restrict__ pAl,
    const __half* __restrict__ pBh,
    int K, int kc, int tid, bool skip_al)
{
    const uint32_t sb = smb + stage * STAGEB;
    #pragma unroll
    for (int i = 0; i < 4; i++) {
        const int u = tid + i * 256;
        const int row = u >> 2, col = (u & 3) * 8;
        const uint32_t so = (uint32_t)(row * LDS + col) * 2;
        const size_t g = (size_t)row * K + kc + col;
        cp16(sb + so, pAh + g);
        if (!skip_al) cp16(sb + OFF_AL + so, pAl + g);
    }
    #pragma unroll
    for (int i = 0; i < 2; i++) {
        const int u = tid + i * 256;
        const int row = u >> 2, col = (u & 3) * 8;
        const uint32_t so = (uint32_t)(row * LDS + col) * 2;
        cp16(sb + OFF_BH + so, pBh + (size_t)row * K + kc + col);
    }
}

__global__ __launch_bounds__(256, 1) void gemm_tc(
    const __half* __restrict__ Ah, const __half* __restrict__ Al,
    const __half* __restrict__ Bh,
    float* __restrict__ C0, float* __restrict__ C1,
    int M, int N0, int N1, int K, int mode)
{
    extern __shared__ char sm[];
    const uint32_t smb = smem_u32(sm);
    const int tid  = threadIdx.x;
    const int wid  = tid >> 5, lane = tid & 31;
    const int wm   = wid & 3;
    const int wn   = wid >> 2;
    const int mbr  = blockIdx.y * 256, nbr = blockIdx.x * 128;

    float* Cb;
    int Nout, ncol;
    if (nbr < N0) { Cb = C0; Nout = N0; ncol = nbr; }
    else          { Cb = C1; Nout = N1; ncol = nbr - N0; }
    const bool one_term = (mode == 2);

    const __half* pAh = Ah + (size_t)mbr * K;
    const __half* pAl = Al + (size_t)mbr * K;
    const __half* pBh = Bh + (size_t)nbr * K;

    float acc[4][8][4];
    #pragma unroll
    for (int i = 0; i < 4; i++)
        #pragma unroll
        for (int j = 0; j < 8; j++)
            #pragma unroll
            for (int k = 0; k < 4; k++) acc[i][j][k] = 0.f;

    const uint32_t aoff = (uint32_t)((wm * 64 + (lane & 15)) * LDS + ((lane >> 4) * 8)) * 2;
    const uint32_t boff = (uint32_t)((wn * 64 + (lane & 7) + ((lane >> 4) << 3)) * LDS
                                     + (((lane >> 3) & 1) * 8)) * 2;

    const int NC = K / GBK;
    load_stage(smb, 0, pAh, pAl, pBh, K, 0, tid, one_term);
    CP_COMMIT();
    load_stage(smb, 1, pAh, pAl, pBh, K, GBK, tid, one_term);
    CP_COMMIT();

    int st_idx = 0;
    for (int c = 0; c < NC; c++) {
        if (c + 1 < NC) { CP_WAIT(1); } else { CP_WAIT(0); }
        __syncthreads();
        if (c + 2 < NC) {
            int ns = st_idx + 2; if (ns >= NSTAGE) ns -= NSTAGE;
            load_stage(smb, ns, pAh, pAl, pBh, K, (c + 2) * GBK, tid, one_term);
            CP_COMMIT();
        }

        const uint32_t st = smb + st_idx * STAGEB;
        #pragma unroll
        for (int ks = 0; ks < 2; ks++) {
            const uint32_t kb = ks * 32;
            uint32_t bh[16];
            #pragma unroll
            for (int n16 = 0; n16 < 4; n16++)
                ldsm_x4(bh + 4 * n16, st + OFF_BH + boff + n16 * (16 * LDS * 2) + kb);
            #pragma unroll
            for (int mf = 0; mf < 4; mf++) {
                uint32_t ah[4];
                ldsm_x4(ah, st + aoff + mf * (16 * LDS * 2) + kb);
                #pragma unroll
                for (int nf = 0; nf < 8; nf++)
                    mma16816(acc[mf][nf], ah, &bh[(nf >> 1) * 4 + (nf & 1) * 2]);
                if (!one_term) {
                    uint32_t al[4];
                    ldsm_x4(al, st + OFF_AL + aoff + mf * (16 * LDS * 2) + kb);
                    #pragma unroll
                    for (int nf = 0; nf < 8; nf++)
                        mma16816(acc[mf][nf], al, &bh[(nf >> 1) * 4 + (nf & 1) * 2]);
                }
            }
        }
        if (++st_idx == NSTAGE) st_idx = 0;
    }

    #pragma unroll
    for (int mf = 0; mf < 4; mf++) {
        const int r0 = mbr + wm * 64 + mf * 16 + (lane >> 2);
        #pragma unroll
        for (int nf = 0; nf < 8; nf++) {
            const int n0 = ncol + wn * 64 + nf * 8 + (lane & 3) * 2;
            *(float2*)(Cb + (size_t)r0 * Nout + n0)       = make_float2(acc[mf][nf][0], acc[mf][nf][1]);
            *(float2*)(Cb + (size_t)(r0 + 8) * Nout + n0) = make_float2(acc[mf][nf][2], acc[mf][nf][3]);
        }
    }
}

// ---------------- rmsnorm + rope for Q -> fp16 hi --------------------------
__global__ __launch_bounds__(128) void qnorm_rope(
    const float* __restrict__ QG, const float* __restrict__ w,
    const float* __restrict__ cosT, const float* __restrict__ sinT,
    __half* __restrict__ Qh)
{
    const int s = blockIdx.x, h = blockIdx.y, b = blockIdx.z;
    const int d = threadIdx.x;
    const float* src = QG + (((size_t)(b * Sn + s) * Hn + h) * 2 * HD);
    float x = src[d];
    float ss = x * x;
    #pragma unroll
    for (int o = 16; o > 0; o >>= 1) ss += __shfl_xor_sync(0xffffffffu, ss, o);
    __shared__ float wsum[4];
    if ((d & 31) == 0) wsum[d >> 5] = ss;
    __syncthreads();
    float tot = wsum[0] + wsum[1] + wsum[2] + wsum[3];
    float inv = rsqrtf(tot * (1.0f / HD) + EPSf);
    float n = x * inv * (1.0f + w[d]);
    __shared__ float nb[HD];
    nb[d] = n;
    __syncthreads();
    float c  = cosT[(size_t)s * HD + d];
    float sn = sinT[(size_t)s * HD + d];
    float rot = (d < HD / 2) ? -nb[d + HD / 2] : nb[d - HD / 2];
    float y = n * c + rot * sn;
    Qh[((size_t)(b * Hn + h) * Sn + s) * HD + d] = __float2half_rn(y);
}

// ---------------- rmsnorm + rope for K -> fp16 hi, V -> fp16 hi ------------
__global__ __launch_bounds__(128) void knorm_rope_v(
    const float* __restrict__ KV,
    const float* __restrict__ w,
    const float* __restrict__ cosT, const float* __restrict__ sinT,
    __half* __restrict__ Kh, __half* __restrict__ Vh)
{
    const int s = blockIdx.x, g = blockIdx.y, b = blockIdx.z;
    const int d = threadIdx.x;
    const float* row = KV + (size_t)(b * Sn + s) * (2 * Gn * HD) + g * HD;
    float x = row[d];
    float ss = x * x;
    #pragma unroll
    for (int o = 16; o > 0; o >>= 1) ss += __shfl_xor_sync(0xffffffffu, ss, o);
    __shared__ float wsum[4];
    if ((d & 31) == 0) wsum[d >> 5] = ss;
    __syncthreads();
    float tot = wsum[0] + wsum[1] + wsum[2] + wsum[3];
    float inv = rsqrtf(tot * (1.0f / HD) + EPSf);
    float n = x * inv * (1.0f + w[d]);
    __shared__ float nb[HD];
    nb[d] = n;
    __syncthreads();
    float c  = cosT[(size_t)s * HD + d];
    float sn = sinT[(size_t)s * HD + d];
    float rot = (d < HD / 2) ? -nb[d + HD / 2] : nb[d - HD / 2];
    float y = n * c + rot * sn;
    const size_t dst = ((size_t)(b * Gn + g) * Sn + s) * HD + d;
    Kh[dst] = __float2half_rn(y);
    Vh[dst] = __float2half_rn(row[Gn * HD + d]);
}

// ================= HMMA causal flash attention + sigmoid gate ==============
// BQ=128 (8 warps x m16), BK=64, HD=128. 1-term fp16: Qh*Kh, Ph*Vh.
// Q fragments cached in registers. Single __syncthreads per tile.
// Heavy blocks (large qi) scheduled first via reversed blockIdx mapping.
// Epilogue writes fp16 Ctx (A side of 1-term Wo GEMM).
#define AT_LDS  136
#define Q_ELE   (128 * AT_LDS)
#define KT_ELE  (64 * AT_LDS)
#define KVSTAGE_ELE (2 * KT_ELE)
#define ATT_SMEM ((Q_ELE + 2 * KVSTAGE_ELE) * 2)   // 104448 bytes
#define CSC 0.12751666806979654f    // (1/sqrt(128)) * log2(e)
#define NEGINF __int_as_float(0xff800000)

__device__ __forceinline__ void kv_load(
    uint32_t smb, int stage,
    const __half* kh, const __half* vh, int tid)
{
    const uint32_t base = smb + (Q_ELE + stage * KVSTAGE_ELE) * 2;
    #pragma unroll
    for (int i = 0; i < 4; i++) {
        int u = tid + i * 256;          // 0..1023
        int til = u >> 9;               // 0: Kh, 1: Vh
        int uu = u & 511;
        int row = uu >> 3, c8 = (uu & 7) * 16;
        uint32_t so = (uint32_t)(row * AT_LDS + c8) * 2;
        const __half* src = til ? vh : kh;
        cp16(base + (uint32_t)til * (KT_ELE * 2) + so, src + (size_t)row * HD + c8);
        cp16(base + (uint32_t)til * (KT_ELE * 2) + so + 16, src + (size_t)row * HD + c8 + 8);
    }
}

__global__ __launch_bounds__(256, 1) void attn_mma(
    const __half* __restrict__ Qh,
    const __half* __restrict__ Kh, const __half* __restrict__ Vh,
    const float* __restrict__ QG,
    __half* __restrict__ Cxh)
{
    extern __shared__ __half smem_h[];
    const uint32_t smb = smem_u32(smem_h);
    const int qi = gridDim.x - 1 - blockIdx.x;   // heavy blocks first
    const int h = blockIdx.y, b = blockIdx.z;
    const int g  = h / GROUPn;
    const int tid = threadIdx.x, lane = tid & 31, w = tid >> 5;

    const __half* gQh = Qh + ((size_t)(b * Hn + h) * Sn + (size_t)qi * 128) * HD;
    const __half* gKh = Kh + ((size_t)(b * Gn + g) * Sn) * HD;
    const __half* gVh = Vh + ((size_t)(b * Gn + g) * Sn) * HD;

    // load Q into smem (128 x 128)
    #pragma unroll
    for (int i = 0; i < 8; i++) {
        int u = tid + i * 256;
        int row = u >> 4, c8 = (u & 15) * 8;
        *(uint4*)(smem_h + row * AT_LDS + c8) = *(const uint4*)(gQh + (size_t)row * HD + c8);
    }

    float m1s = NEGINF, m2s = NEGINF, l1 = 0.f, l2 = 0.f;
    float oacc[16][4];
    #pragma unroll
    for (int nf = 0; nf < 16; nf++)
        #pragma unroll
        for (int k = 0; k < 4; k++) oacc[nf][k] = 0.f;

    const int r1rel = w * 16 + (lane >> 2);   // 0..127
    const int r1g = qi * 128 + r1rel;
    const int r2g = r1g + 8;

    kv_load(smb, 0, gKh, gVh, tid);
    CP_COMMIT();
    CP_WAIT(0);
    __syncthreads();   // Q smem + KV stage0 ready

    // cache Q fragments in registers for the whole loop
    uint32_t qh_fr[8][4];
    #pragma unroll
    for (int kq = 0; kq < 8; kq++) {
        const uint32_t qaddr = smb +
            (uint32_t)((w * 16 + (lane & 15)) * AT_LDS + ((lane >> 4) << 3) + kq * 16) * 2;
        ldsm_x4(qh_fr[kq], qaddr);
    }

    const int ntiles = 2 * qi + 2;
    for (int t = 0; t < ntiles; t++) {
        if (t > 0) {
            CP_WAIT(0);
            __syncthreads();
        }
        if (t + 1 < ntiles) {
            kv_load(smb, (t + 1) & 1,
                    gKh + (size_t)(t + 1) * 64 * HD, gVh + (size_t)(t + 1) * 64 * HD, tid);
            CP_COMMIT();
        }

        const uint32_t kb = smb + (Q_ELE + (t & 1) * KVSTAGE_ELE) * 2;

        // ---- scores: S = Qh Kh^T (1-term) ----
        float sacc[8][4];
        #pragma unroll
        for (int j = 0; j < 8; j++)
            #pragma unroll
            for (int k = 0; k < 4; k++) sacc[j][k] = 0.f;

        #pragma unroll
        for (int kq = 0; kq < 8; kq++) {
            uint32_t bh[16];
            #pragma unroll
            for (int n16 = 0; n16 < 4; n16++) {
                const uint32_t kaddr = kb +
                    (uint32_t)((n16 * 16 + (lane & 7) + ((lane >> 4) << 3)) * AT_LDS
                               + (((lane >> 3) & 1) << 3) + kq * 16) * 2;
                ldsm_x4(bh + 4 * n16, kaddr);
            }
            #pragma unroll
            for (int n16 = 0; n16 < 4; n16++) {
                mma16816(sacc[2 * n16],     qh_fr[kq], bh + 4 * n16);
                mma16816(sacc[2 * n16 + 1], qh_fr[kq], bh + 4 * n16 + 2);
            }
        }

        // ---- online softmax (log2 domain) ----
        const bool needmask = (t >= 2 * qi);
        float mt1 = m1s, mt2 = m2s;
        #pragma unroll
        for (int j = 0; j < 8; j++) {
            const int c0 = t * 64 + j * 8 + (lane & 3) * 2;
            #pragma unroll
            for (int k = 0; k < 4; k++) sacc[j][k] *= CSC;
            if (needmask) {
                if (c0     > r1g) sacc[j][0] = NEGINF;
                if (c0 + 1 > r1g) sacc[j][1] = NEGINF;
                if (c0     > r2g) sacc[j][2] = NEGINF;
                if (c0 + 1 > r2g) sacc[j][3] = NEGINF;
            }
            mt1 = fmaxf(mt1, fmaxf(sacc[j][0], sacc[j][1]));
            mt2 = fmaxf(mt2, fmaxf(sacc[j][2], sacc[j][3]));
        }
        mt1 = fmaxf(mt1, __shfl_xor_sync(0xffffffffu, mt1, 1));
        mt1 = fmaxf(mt1, __shfl_xor_sync(0xffffffffu, mt1, 2));
        mt2 = fmaxf(mt2, __shfl_xor_sync(0xffffffffu, mt2, 1));
        mt2 = fmaxf(mt2, __shfl_xor_sync(0xffffffffu, mt2, 2));
        const float f1 = ex2f(m1s - mt1), f2 = ex2f(m2s - mt2);
        m1s = mt1; m2s = mt2;
        float s1 = 0.f, s2 = 0.f;
        #pragma unroll
        for (int j = 0; j < 8; j++) {
            sacc[j][0] = ex2f(sacc[j][0] - mt1);
            sacc[j][1] = ex2f(sacc[j][1] - mt1);
            sacc[j][2] = ex2f(sacc[j][2] - mt2);
            sacc[j][3] = ex2f(sacc[j][3] - mt2);
            s1 += sacc[j][0] + sacc[j][1];
            s2 += sacc[j][2] + sacc[j][3];
        }
        l1 = l1 * f1 + s1;
        l2 = l2 * f2 + s2;
        #pragma unroll
        for (int nf = 0; nf < 16; nf++) {
            oacc[nf][0] *= f1; oacc[nf][1] *= f1;
            oacc[nf][2] *= f2; oacc[nf][3] *= f2;
        }

        // ---- PV: out += Ph Vh (1-term) ----
        #pragma unroll
        for (int kk = 0; kk < 4; kk++) {
            uint32_t a_h[4];
            #pragma unroll
            for (int half = 0; half < 2; half++) {
                a_h[2 * half]     = packh2(sacc[2 * kk + half][0], sacc[2 * kk + half][1]);
                a_h[2 * half + 1] = packh2(sacc[2 * kk + half][2], sacc[2 * kk + half][3]);
            }
            #pragma unroll
            for (int dp = 0; dp < 4; dp++) {    // dc = 2dp, 2dp+1
                uint32_t bvh0[4], bvh1[4];
                const uint32_t va0 = kb + KT_ELE * 2 +
                    (uint32_t)((kk * 16 + (lane & 15)) * AT_LDS + (2 * dp) * 16 + ((lane >> 4) << 3)) * 2;
                const uint32_t va1 = va0 + 32;
                ldsm_x4t(bvh0, va0);
                ldsm_x4t(bvh1, va1);
                mma16816(oacc[4 * dp],     a_h, bvh0);
                mma16816(oacc[4 * dp + 1], a_h, bvh0 + 2);
                mma16816(oacc[4 * dp + 2], a_h, bvh1);
                mma16816(oacc[4 * dp + 3], a_h, bvh1 + 2);
            }
        }
    }

    // ---- epilogue: /l, * sigmoid(gate), write fp16 Ctx ----
    l1 += __shfl_xor_sync(0xffffffffu, l1, 1);
    l1 += __shfl_xor_sync(0xffffffffu, l1, 2);
    l2 += __shfl_xor_sync(0xffffffffu, l2, 1);
    l2 += __shfl_xor_sync(0xffffffffu, l2, 2);
    const float inv1 = 1.0f / l1, inv2 = 1.0f / l2;
    #pragma unroll
    for (int nf = 0; nf < 16; nf++) {
        const int dim = nf * 8 + (lane & 3) * 2;
        #pragma unroll
        for (int rr = 0; rr < 2; rr++) {
            const int q = rr ? r2g : r1g;
            const float invl = rr ? inv2 : inv1;
            const float a0 = oacc[nf][2 * rr], a1 = oacc[nf][2 * rr + 1];
            const float2 gt = *(const float2*)(QG + (((size_t)(b * Sn + q) * Hn + h) * 2 * HD) + HD + dim);
            const float v0 = a0 * invl * (1.0f / (1.0f + expf(-gt.x)));
            const float v1 = a1 * invl * (1.0f / (1.0f + expf(-gt.y)));
            *(__half2*)(Cxh + (size_t)(b * Sn + q) * DOUT + h * HD + dim) =
                __halves2half2(__float2half_rn(v0), __float2half_rn(v1));
        }
    }
}

// ---------------------------- launcher -------------------------------------
extern "C" void kernel_launch(void* const* d_in, const int* in_sizes, int n_in,
                              void* d_out, int out_size)
{
    const float* x    = (const float*)d_in[0];
    const float* Wq   = (const float*)d_in[1];
    const float* Wk   = (const float*)d_in[2];
    const float* Wv   = (const float*)d_in[3];
    const float* Wo   = (const float*)d_in[4];
    const float* qw   = (const float*)d_in[5];
    const float* kw   = (const float*)d_in[6];
    const float* cosT = (const float*)d_in[7];
    const float* sinT = (const float*)d_in[8];
    float* out = (float*)d_out;

    float *QG, *KV;
    cudaGetSymbolAddress((void**)&QG, g_QG);
    cudaGetSymbolAddress((void**)&KV, g_KV);

    __half *Qhp, *Khp, *Vhp;
    cudaGetSymbolAddress((void**)&Qhp, g_Qh);
    cudaGetSymbolAddress((void**)&Khp, g_Kh);
    cudaGetSymbolAddress((void**)&Vhp, g_Vh);

    __half *xh, *Wah, *Woh, *Cxh;
    cudaGetSymbolAddress((void**)&xh,  g_xh);
    cudaGetSymbolAddress((void**)&Wah, g_Wah);
    cudaGetSymbolAddress((void**)&Woh, g_Woh);
    cudaGetSymbolAddress((void**)&Cxh, g_Cxh);

    cudaFuncSetAttribute(gemm_tc, cudaFuncAttributeMaxDynamicSharedMemorySize, GEMM_SMEM);
    cudaFuncSetAttribute(attn_mma, cudaFuncAttributeMaxDynamicSharedMemorySize, ATT_SMEM);

    const int M = Mrows;          // 4096
    const int NKV = 2 * Gn * HD;  // 1024

    // (1) convert x to fp16; (2-4) transpose Wq|Wk|Wv
    fconv<<<(M * DIN / 4 + 255) / 256, 256>>>(x, xh, M * DIN);
    tsplit<<<dim3((2 * DOUT) / 32, DIN / 32), dim3(32, 8)>>>(Wq, Wah, DIN, 2 * DOUT);
    tsplit<<<dim3((Gn * HD) / 32, DIN / 32), dim3(32, 8)>>>(
        Wk, Wah + (size_t)(2 * DOUT) * DIN, DIN, Gn * HD);
    tsplit<<<dim3((Gn * HD) / 32, DIN / 32), dim3(32, 8)>>>(
        Wv, Wah + (size_t)(2 * DOUT + Gn * HD) * DIN, DIN, Gn * HD);

    // (5) merged QKV projection, 1-term  [profiled launch]
    gemm_tc<<<dim3(NQKV / 128, M / 256), 256, GEMM_SMEM>>>(
        xh, xh, Wah, QG, KV, M, 2 * DOUT, NKV, DIN, 2);

    // (6) Wo transpose
    tsplit<<<dim3(DIN / 32, DOUT / 32), dim3(32, 8)>>>(Wo, Woh, DOUT, DIN);

    // (7-8) norm + rope -> fp16
    qnorm_rope<<<dim3(Sn, Hn, Bn), 128>>>(QG, qw, cosT, sinT, Qhp);
    knorm_rope_v<<<dim3(Sn, Gn, Bn), 128>>>(KV, kw, cosT, sinT, Khp, Vhp);

    // (9) HMMA causal attention + gate (1-term), heavy-first scheduling
    attn_mma<<<dim3(Sn / 128, Hn, Bn), 256, ATT_SMEM>>>(
        Qhp, Khp, Vhp, QG, Cxh);

    // (10) output projection (1-term)
    gemm_tc<<<dim3(DIN / 128, M / 256), 256, GEMM_SMEM>>>(
        Cxh, Cxh, Woh, out, (float*)nullptr, M, DIN, 0, DOUT, 2);
}

// round 16
// speedup vs baseline: 2.3447x; 1.0449x over previous
#include <cuda_runtime.h>
#include <cuda_fp16.h>
#include <math.h>
#include <stdint.h>

#define Bn    2
#define Sn    2048
#define DIN   2048
#define Hn    16
#define Gn    4
#define HD    128
#define DOUT  2048
#define GROUPn 4          // H / G
#define EPSf  1e-6f
#define Mrows (Bn*Sn)     // 4096
#define NQKV  (2*DOUT + 2*Gn*HD)   // 5120 = Wq(4096) | Wk(512) | Wv(512)

// ---------------- scratch (device globals; no allocation allowed) ----------
__device__ __half g_Gate[(size_t)Bn*Sn*Hn*HD];    // [b,s,h,d] fp16 gate

// fp16 attention operands
__device__ __half g_Qh[(size_t)Bn*Hn*Sn*HD];
__device__ __half g_Kh[(size_t)Bn*Gn*Sn*HD];
__device__ __half g_Vh[(size_t)Bn*Gn*Sn*HD];

// fp16 scratch for GEMMs
__device__ __half g_xh [(size_t)Mrows*DIN];
__device__ __half g_Wah[(size_t)NQKV*DIN];   // packed Wq|Wk|Wv, [N][K]
__device__ __half g_Woh[(size_t)DIN*DOUT];
__device__ __half g_Cxh[(size_t)Mrows*DOUT];

// ======================= PTX helpers (compute_103 baseline only) ==========
__device__ __forceinline__ uint32_t smem_u32(const void* p) {
    uint32_t a;
    asm("{ .reg .u64 t; cvta.to.shared.u64 t, %1; cvt.u32.u64 %0, t; }" : "=r"(a) : "l"(p));
    return a;
}
__device__ __forceinline__ void cp16(uint32_t s, const void* g) {
    asm volatile("cp.async.cg.shared.global [%0], [%1], 16;" :: "r"(s), "l"(g));
}
#define CP_COMMIT() asm volatile("cp.async.commit_group;" ::: "memory")
#define CP_WAIT(n)  asm volatile("cp.async.wait_group %0;" :: "n"(n) : "memory")

__device__ __forceinline__ void ldsm_x4(uint32_t* r, uint32_t addr) {
    asm volatile("ldmatrix.sync.aligned.m8n8.x4.shared.b16 {%0,%1,%2,%3}, [%4];"
        : "=r"(r[0]), "=r"(r[1]), "=r"(r[2]), "=r"(r[3]) : "r"(addr));
}
__device__ __forceinline__ void ldsm_x4t(uint32_t* r, uint32_t addr) {
    asm volatile("ldmatrix.sync.aligned.m8n8.x4.trans.shared.b16 {%0,%1,%2,%3}, [%4];"
        : "=r"(r[0]), "=r"(r[1]), "=r"(r[2]), "=r"(r[3]) : "r"(addr));
}
__device__ __forceinline__ void mma16816(float* d, const uint32_t* a, const uint32_t* b) {
    asm volatile(
        "mma.sync.aligned.m16n8k16.row.col.f32.f16.f16.f32 "
        "{%0,%1,%2,%3}, {%4,%5,%6,%7}, {%8,%9}, {%0,%1,%2,%3};"
        : "+f"(d[0]), "+f"(d[1]), "+f"(d[2]), "+f"(d[3])
        : "r"(a[0]), "r"(a[1]), "r"(a[2]), "r"(a[3]), "r"(b[0]), "r"(b[1]));
}
__device__ __forceinline__ float ex2f(float x) {
    float r; asm("ex2.approx.f32 %0, %1;" : "=f"(r) : "f"(x)); return r;
}
__device__ __forceinline__ uint32_t packh2(float lo, float hi) {
    uint32_t r; asm("cvt.rn.f16x2.f32 %0, %1, %2;" : "=r"(r) : "f"(hi), "f"(lo)); return r;
}

// ======================= convert / transpose ==========================
__global__ __launch_bounds__(256) void fconv(const float* __restrict__ in,
                                             __half* __restrict__ h, int n)
{
    int i = (blockIdx.x * 256 + threadIdx.x) * 4;
    if (i >= n) return;
    float4 v = *(const float4*)(in + i);
    *(__half2*)(h + i)     = __halves2half2(__float2half_rn(v.x), __float2half_rn(v.y));
    *(__half2*)(h + i + 2) = __halves2half2(__float2half_rn(v.z), __float2half_rn(v.w));
}

// W[K,N] fp32 -> Th[N,K] fp16 (transpose)
__global__ __launch_bounds__(256) void tsplit(const float* __restrict__ W,
                                              __half* __restrict__ Th,
                                              int K, int N)
{
    __shared__ float t[32][33];
    const int n0 = blockIdx.x * 32, k0 = blockIdx.y * 32;
    const int tx = threadIdx.x, ty = threadIdx.y;  // (32, 8)
    #pragma unroll
    for (int r = 0; r < 4; r++)
        t[ty + r * 8][tx] = W[(size_t)(k0 + ty + r * 8) * N + n0 + tx];
    __syncthreads();
    #pragma unroll
    for (int r = 0; r < 4; r++) {
        int n = n0 + ty + r * 8, k = k0 + tx;
        Th[(size_t)n * K + k] = __float2half_rn(t[tx][ty + r * 8]);
    }
}

// ======================= HMMA 1-term fp16 GEMM (256x128, 3-stage) ==========
// C = Ah * Bh^T. fused=0: write fp32 C0 (stride N0).
// fused=1 (QKV): per-n-tile typed epilogue:
//   Wq even tile -> rmsnorm+rope -> Qh ; Wq odd tile -> fp16 Gate
//   K tiles -> rmsnorm+rope -> Kh ; V tiles -> fp16 Vh
#define GBK    32
#define LDS    40
#define ATILEB (256 * LDS * 2)   // 20480 B
#define BTILEB (128 * LDS * 2)   // 10240 B
#define STAGEB (ATILEB + BTILEB)          // 30720 B
#define NSTAGE 3
#define EPI_SMEM (256 * 132 * 4)          // 135168 B
#define GEMM_SMEM EPI_SMEM                // > 3*STAGEB (92160)
#define OFF_BH  ATILEB

__device__ __forceinline__ void load_stage(
    uint32_t smb, int stage,
    const __half* __restrict__ pAh, const __half* __restrict__ pBh,
    int K, int kc, int tid)
{
    const uint32_t sb = smb + stage * STAGEB;
    #pragma unroll
    for (int i = 0; i < 4; i++) {
        const int u = tid + i * 256;
        const int row = u >> 2, col = (u & 3) * 8;
        const uint32_t so = (uint32_t)(row * LDS + col) * 2;
        cp16(sb + so, pAh + (size_t)row * K + kc + col);
    }
    #pragma unroll
    for (int i = 0; i < 2; i++) {
        const int u = tid + i * 256;
        const int row = u >> 2, col = (u & 3) * 8;
        const uint32_t so = (uint32_t)(row * LDS + col) * 2;
        cp16(sb + OFF_BH + so, pBh + (size_t)row * K + kc + col);
    }
}

__global__ __launch_bounds__(256, 1) void gemm_tc(
    const __half* __restrict__ Ah, const __half* __restrict__ Bh,
    float* __restrict__ C0, int M, int N0, int K, int fused,
    __half* __restrict__ Qh, __half* __restrict__ Kh, __half* __restrict__ Vh,
    __half* __restrict__ Gate,
    const float* __restrict__ qw, const float* __restrict__ kw,
    const float* __restrict__ cosT, const float* __restrict__ sinT)
{
    extern __shared__ char sm[];
    const uint32_t smb = smem_u32(sm);
    const int tid  = threadIdx.x;
    const int wid  = tid >> 5, lane = tid & 31;
    const int wm   = wid & 3;
    const int wn   = wid >> 2;
    const int mbr  = blockIdx.y * 256, nbr = blockIdx.x * 128;

    const __half* pAh = Ah + (size_t)mbr * K;
    const __half* pBh = Bh + (size_t)nbr * K;

    float acc[4][8][4];
    #pragma unroll
    for (int i = 0; i < 4; i++)
        #pragma unroll
        for (int j = 0; j < 8; j++)
            #pragma unroll
            for (int k = 0; k < 4; k++) acc[i][j][k] = 0.f;

    const uint32_t aoff = (uint32_t)((wm * 64 + (lane & 15)) * LDS + ((lane >> 4) * 8)) * 2;
    const uint32_t boff = (uint32_t)((wn * 64 + (lane & 7) + ((lane >> 4) << 3)) * LDS
                                     + (((lane >> 3) & 1) * 8)) * 2;

    const int NC = K / GBK;
    load_stage(smb, 0, pAh, pBh, K, 0, tid);
    CP_COMMIT();
    load_stage(smb, 1, pAh, pBh, K, GBK, tid);
    CP_COMMIT();

    int st_idx = 0;
    for (int c = 0; c < NC; c++) {
        if (c + 1 < NC) { CP_WAIT(1); } else { CP_WAIT(0); }
        __syncthreads();
        if (c + 2 < NC) {
            int ns = st_idx + 2; if (ns >= NSTAGE) ns -= NSTAGE;
            load_stage(smb, ns, pAh, pBh, K, (c + 2) * GBK, tid);
            CP_COMMIT();
        }

        const uint32_t st = smb + st_idx * STAGEB;
        #pragma unroll
        for (int ks = 0; ks < 2; ks++) {
            const uint32_t kb = ks * 32;
            uint32_t bh[16];
            #pragma unroll
            for (int n16 = 0; n16 < 4; n16++)
                ldsm_x4(bh + 4 * n16, st + OFF_BH + boff + n16 * (16 * LDS * 2) + kb);
            #pragma unroll
            for (int mf = 0; mf < 4; mf++) {
                uint32_t ah[4];
                ldsm_x4(ah, st + aoff + mf * (16 * LDS * 2) + kb);
                #pragma unroll
                for (int nf = 0; nf < 8; nf++)
                    mma16816(acc[mf][nf], ah, &bh[(nf >> 1) * 4 + (nf & 1) * 2]);
            }
        }
        if (++st_idx == NSTAGE) st_idx = 0;
    }

    if (!fused) {
        #pragma unroll
        for (int mf = 0; mf < 4; mf++) {
            const int r0 = mbr + wm * 64 + mf * 16 + (lane >> 2);
            #pragma unroll
            for (int nf = 0; nf < 8; nf++) {
                const int n0 = nbr + wn * 64 + nf * 8 + (lane & 3) * 2;
                *(float2*)(C0 + (size_t)r0 * N0 + n0)       = make_float2(acc[mf][nf][0], acc[mf][nf][1]);
                *(float2*)(C0 + (size_t)(r0 + 8) * N0 + n0) = make_float2(acc[mf][nf][2], acc[mf][nf][3]);
            }
        }
        return;
    }

    // ---------------- fused QKV epilogue ----------------
    // type: 0=q (rmsnorm+rope->Qh), 1=gate (->Gate), 2=K (->Kh), 3=V (->Vh)
    int type, head;
    if (nbr < 2 * DOUT)       { head = nbr >> 8; type = (nbr >> 7) & 1; }
    else if (nbr < 2 * DOUT + Gn * HD) { head = (nbr - 2 * DOUT) >> 7; type = 2; }
    else                      { head = (nbr - 2 * DOUT - Gn * HD) >> 7; type = 3; }

    __syncthreads();                // all warps done with stage smem
    float* smf = (float*)sm;        // [256][132]
    #pragma unroll
    for (int mf = 0; mf < 4; mf++) {
        const int r0 = wm * 64 + mf * 16 + (lane >> 2);
        #pragma unroll
        for (int nf = 0; nf < 8; nf++) {
            const int c0 = wn * 64 + nf * 8 + (lane & 3) * 2;
            smf[r0 * 132 + c0]           = acc[mf][nf][0];
            smf[r0 * 132 + c0 + 1]       = acc[mf][nf][1];
            smf[(r0 + 8) * 132 + c0]     = acc[mf][nf][2];
            smf[(r0 + 8) * 132 + c0 + 1] = acc[mf][nf][3];
        }
    }
    __syncthreads();

    if (type == 0 || type == 2) {
        const float* w = (type == 0) ? qw : kw;
        const float wv0 = 1.f + w[lane],      wv1 = 1.f + w[lane + 32];
        const float wv2 = 1.f + w[lane + 64], wv3 = 1.f + w[lane + 96];
        __half* base = (type == 0)
            ? Qh + (size_t)head * Sn * HD     // + b*Hn*Sn*HD added per row
            : Kh + (size_t)head * Sn * HD;
        const size_t bstride = (type == 0) ? (size_t)Hn * Sn * HD : (size_t)Gn * Sn * HD;
        for (int rr = 0; rr < 32; rr++) {
            const int r = wid * 32 + rr;
            const int m = mbr + r;
            const int b = m >> 11, s = m & (Sn - 1);
            float v0 = smf[r * 132 + lane],      v1 = smf[r * 132 + lane + 32];
            float v2 = smf[r * 132 + lane + 64], v3 = smf[r * 132 + lane + 96];
            float ss = v0 * v0 + v1 * v1 + v2 * v2 + v3 * v3;
            #pragma unroll
            for (int o = 16; o > 0; o >>= 1) ss += __shfl_xor_sync(0xffffffffu, ss, o);
            const float inv = rsqrtf(ss * (1.0f / HD) + EPSf);
            const float n0 = v0 * inv * wv0, n1 = v1 * inv * wv1;
            const float n2 = v2 * inv * wv2, n3 = v3 * inv * wv3;
            const float* cp = cosT + (size_t)s * HD;
            const float* sp = sinT + (size_t)s * HD;
            const float y0 = n0 * cp[lane]      - n2 * sp[lane];
            const float y1 = n1 * cp[lane + 32] - n3 * sp[lane + 32];
            const float y2 = n2 * cp[lane + 64] + n0 * sp[lane + 64];
            const float y3 = n3 * cp[lane + 96] + n1 * sp[lane + 96];
            __half* dst = base + (size_t)b * bstride + (size_t)s * HD;
            dst[lane]      = __float2half_rn(y0);
            dst[lane + 32] = __float2half_rn(y1);
            dst[lane + 64] = __float2half_rn(y2);
            dst[lane + 96] = __float2half_rn(y3);
        }
    } else {
        for (int i = tid; i < 256 * 128; i += 256) {
            const int r = i >> 7, c = i & 127;
            const int m = mbr + r;
            const int b = m >> 11, s = m & (Sn - 1);
            const __half v = __float2half_rn(smf[r * 132 + c]);
            if (type == 1)
                Gate[((size_t)(b * Sn + s) * Hn + head) * HD + c] = v;
            else
                Vh[((size_t)(b * Gn + head) * Sn + s) * HD + c] = v;
        }
    }
}

// ================= HMMA causal flash attention + sigmoid gate ==============
// BQ=128 (8 warps x m16), BK=64, HD=128. 1-term fp16. Q fragments in regs.
// Heavy blocks first. Gate read fp16. Epilogue writes fp16 Ctx.
#define AT_LDS  136
#define Q_ELE   (128 * AT_LDS)
#define KT_ELE  (64 * AT_LDS)
#define KVSTAGE_ELE (2 * KT_ELE)
#define ATT_SMEM ((Q_ELE + 2 * KVSTAGE_ELE) * 2)   // 104448 bytes
#define CSC 0.12751666806979654f    // (1/sqrt(128)) * log2(e)
#define NEGINF __int_as_float(0xff800000)

__device__ __forceinline__ void kv_load(
    uint32_t smb, int stage,
    const __half* kh, const __half* vh, int tid)
{
    const uint32_t base = smb + (Q_ELE + stage * KVSTAGE_ELE) * 2;
    #pragma unroll
    for (int i = 0; i < 4; i++) {
        int u = tid + i * 256;          // 0..1023
        int til = u >> 9;               // 0: Kh, 1: Vh
        int uu = u & 511;
        int row = uu >> 3, c8 = (uu & 7) * 16;
        uint32_t so = (uint32_t)(row * AT_LDS + c8) * 2;
        const __half* src = til ? vh : kh;
        cp16(base + (uint32_t)til * (KT_ELE * 2) + so, src + (size_t)row * HD + c8);
        cp16(base + (uint32_t)til * (KT_ELE * 2) + so + 16, src + (size_t)row * HD + c8 + 8);
    }
}

__global__ __launch_bounds__(256, 1) void attn_mma(
    const __half* __restrict__ Qh,
    const __half* __restrict__ Kh, const __half* __restrict__ Vh,
    const __half* __restrict__ Gate,
    __half* __restrict__ Cxh)
{
    extern __shared__ __half smem_h[];
    const uint32_t smb = smem_u32(smem_h);
    const int qi = gridDim.x - 1 - blockIdx.x;   // heavy blocks first
    const int h = blockIdx.y, b = blockIdx.z;
    const int g  = h / GROUPn;
    const int tid = threadIdx.x, lane = tid & 31, w = tid >> 5;

    const __half* gQh = Qh + ((size_t)(b * Hn + h) * Sn + (size_t)qi * 128) * HD;
    const __half* gKh = Kh + ((size_t)(b * Gn + g) * Sn) * HD;
    const __half* gVh = Vh + ((size_t)(b * Gn + g) * Sn) * HD;

    // load Q into smem (128 x 128)
    #pragma unroll
    for (int i = 0; i < 8; i++) {
        int u = tid + i * 256;
        int row = u >> 4, c8 = (u & 15) * 8;
        *(uint4*)(smem_h + row * AT_LDS + c8) = *(const uint4*)(gQh + (size_t)row * HD + c8);
    }

    float m1s = NEGINF, m2s = NEGINF, l1 = 0.f, l2 = 0.f;
    float oacc[16][4];
    #pragma unroll
    for (int nf = 0; nf < 16; nf++)
        #pragma unroll
        for (int k = 0; k < 4; k++) oacc[nf][k] = 0.f;

    const int r1rel = w * 16 + (lane >> 2);
    const int r1g = qi * 128 + r1rel;
    const int r2g = r1g + 8;

    kv_load(smb, 0, gKh, gVh, tid);
    CP_COMMIT();
    CP_WAIT(0);
    __syncthreads();

    uint32_t qh_fr[8][4];
    #pragma unroll
    for (int kq = 0; kq < 8; kq++) {
        const uint32_t qaddr = smb +
            (uint32_t)((w * 16 + (lane & 15)) * AT_LDS + ((lane >> 4) << 3) + kq * 16) * 2;
        ldsm_x4(qh_fr[kq], qaddr);
    }

    const int ntiles = 2 * qi + 2;
    for (int t = 0; t < ntiles; t++) {
        if (t > 0) {
            CP_WAIT(0);
            __syncthreads();
        }
        if (t + 1 < ntiles) {
            kv_load(smb, (t + 1) & 1,
                    gKh + (size_t)(t + 1) * 64 * HD, gVh + (size_t)(t + 1) * 64 * HD, tid);
            CP_COMMIT();
        }

        const uint32_t kb = smb + (Q_ELE + (t & 1) * KVSTAGE_ELE) * 2;

        float sacc[8][4];
        #pragma unroll
        for (int j = 0; j < 8; j++)
            #pragma unroll
            for (int k = 0; k < 4; k++) sacc[j][k] = 0.f;

        #pragma unroll
        for (int kq = 0; kq < 8; kq++) {
            uint32_t bh[16];
            #pragma unroll
            for (int n16 = 0; n16 < 4; n16++) {
                const uint32_t kaddr = kb +
                    (uint32_t)((n16 * 16 + (lane & 7) + ((lane >> 4) << 3)) * AT_LDS
                               + (((lane >> 3) & 1) << 3) + kq * 16) * 2;
                ldsm_x4(bh + 4 * n16, kaddr);
            }
            #pragma unroll
            for (int n16 = 0; n16 < 4; n16++) {
                mma16816(sacc[2 * n16],     qh_fr[kq], bh + 4 * n16);
                mma16816(sacc[2 * n16 + 1], qh_fr[kq], bh + 4 * n16 + 2);
            }
        }

        const bool needmask = (t >= 2 * qi);
        float mt1 = m1s, mt2 = m2s;
        #pragma unroll
        for (int j = 0; j < 8; j++) {
            const int c0 = t * 64 + j * 8 + (lane & 3) * 2;
            #pragma unroll
            for (int k = 0; k < 4; k++) sacc[j][k] *= CSC;
            if (needmask) {
                if (c0     > r1g) sacc[j][0] = NEGINF;
                if (c0 + 1 > r1g) sacc[j][1] = NEGINF;
                if (c0     > r2g) sacc[j][2] = NEGINF;
                if (c0 + 1 > r2g) sacc[j][3] = NEGINF;
            }
            mt1 = fmaxf(mt1, fmaxf(sacc[j][0], sacc[j][1]));
            mt2 = fmaxf(mt2, fmaxf(sacc[j][2], sacc[j][3]));
        }
        mt1 = fmaxf(mt1, __shfl_xor_sync(0xffffffffu, mt1, 1));
        mt1 = fmaxf(mt1, __shfl_xor_sync(0xffffffffu, mt1, 2));
        mt2 = fmaxf(mt2, __shfl_xor_sync(0xffffffffu, mt2, 1));
        mt2 = fmaxf(mt2, __shfl_xor_sync(0xffffffffu, mt2, 2));
        const float f1 = ex2f(m1s - mt1), f2 = ex2f(m2s - mt2);
        m1s = mt1; m2s = mt2;
        float s1 = 0.f, s2 = 0.f;
        #pragma unroll
        for (int j = 0; j < 8; j++) {
            sacc[j][0] = ex2f(sacc[j][0] - mt1);
            sacc[j][1] = ex2f(sacc[j][1] - mt1);
            sacc[j][2] = ex2f(sacc[j][2] - mt2);
            sacc[j][3] = ex2f(sacc[j][3] - mt2);
            s1 += sacc[j][0] + sacc[j][1];
            s2 += sacc[j][2] + sacc[j][3];
        }
        l1 = l1 * f1 + s1;
        l2 = l2 * f2 + s2;
        #pragma unroll
        for (int nf = 0; nf < 16; nf++) {
            oacc[nf][0] *= f1; oacc[nf][1] *= f1;
            oacc[nf][2] *= f2; oacc[nf][3] *= f2;
        }

        #pragma unroll
        for (int kk = 0; kk < 4; kk++) {
            uint32_t a_h[4];
            #pragma unroll
            for (int half = 0; half < 2; half++) {
                a_h[2 * half]     = packh2(sacc[2 * kk + half][0], sacc[2 * kk + half][1]);
                a_h[2 * half + 1] = packh2(sacc[2 * kk + half][2], sacc[2 * kk + half][3]);
            }
            #pragma unroll
            for (int dp = 0; dp < 4; dp++) {
                uint32_t bvh0[4], bvh1[4];
                const uint32_t va0 = kb + KT_ELE * 2 +
                    (uint32_t)((kk * 16 + (lane & 15)) * AT_LDS + (2 * dp) * 16 + ((lane >> 4) << 3)) * 2;
                const uint32_t va1 = va0 + 32;
                ldsm_x4t(bvh0, va0);
                ldsm_x4t(bvh1, va1);
                mma16816(oacc[4 * dp],     a_h, bvh0);
                mma16816(oacc[4 * dp + 1], a_h, bvh0 + 2);
                mma16816(oacc[4 * dp + 2], a_h, bvh1);
                mma16816(oacc[4 * dp + 3], a_h, bvh1 + 2);
            }
        }
    }

    // ---- epilogue: /l, * sigmoid(gate fp16), write fp16 Ctx ----
    l1 += __shfl_xor_sync(0xffffffffu, l1, 1);
    l1 += __shfl_xor_sync(0xffffffffu, l1, 2);
    l2 += __shfl_xor_sync(0xffffffffu, l2, 1);
    l2 += __shfl_xor_sync(0xffffffffu, l2, 2);
    const float inv1 = 1.0f / l1, inv2 = 1.0f / l2;
    #pragma unroll
    for (int nf = 0; nf < 16; nf++) {
        const int dim = nf * 8 + (lane & 3) * 2;
        #pragma unroll
        for (int rr = 0; rr < 2; rr++) {
            const int q = rr ? r2g : r1g;
            const float invl = rr ? inv2 : inv1;
            const float a0 = oacc[nf][2 * rr], a1 = oacc[nf][2 * rr + 1];
            const __half2 gt = *(const __half2*)(Gate + ((size_t)(b * Sn + q) * Hn + h) * HD + dim);
            const float g0 = __low2float(gt), g1 = __high2float(gt);
            const float v0 = a0 * invl * (1.0f / (1.0f + expf(-g0)));
            const float v1 = a1 * invl * (1.0f / (1.0f + expf(-g1)));
            *(__half2*)(Cxh + (size_t)(b * Sn + q) * DOUT + h * HD + dim) =
                __halves2half2(__float2half_rn(v0), __float2half_rn(v1));
        }
    }
}

// ---------------------------- launcher -------------------------------------
extern "C" void kernel_launch(void* const* d_in, const int* in_sizes, int n_in,
                              void* d_out, int out_size)
{
    const float* x    = (const float*)d_in[0];
    const float* Wq   = (const float*)d_in[1];
    const float* Wk   = (const float*)d_in[2];
    const float* Wv   = (const float*)d_in[3];
    const float* Wo   = (const float*)d_in[4];
    const float* qw   = (const float*)d_in[5];
    const float* kw   = (const float*)d_in[6];
    const float* cosT = (const float*)d_in[7];
    const float* sinT = (const float*)d_in[8];
    float* out = (float*)d_out;

    __half *Qhp, *Khp, *Vhp, *Gp;
    cudaGetSymbolAddress((void**)&Qhp, g_Qh);
    cudaGetSymbolAddress((void**)&Khp, g_Kh);
    cudaGetSymbolAddress((void**)&Vhp, g_Vh);
    cudaGetSymbolAddress((void**)&Gp,  g_Gate);

    __half *xh, *Wah, *Woh, *Cxh;
    cudaGetSymbolAddress((void**)&xh,  g_xh);
    cudaGetSymbolAddress((void**)&Wah, g_Wah);
    cudaGetSymbolAddress((void**)&Woh, g_Woh);
    cudaGetSymbolAddress((void**)&Cxh, g_Cxh);

    cudaFuncSetAttribute(gemm_tc, cudaFuncAttributeMaxDynamicSharedMemorySize, GEMM_SMEM);
    cudaFuncSetAttribute(attn_mma, cudaFuncAttributeMaxDynamicSharedMemorySize, ATT_SMEM);

    const int M = Mrows;          // 4096

    // (1) convert x; (2-5) transpose weights
    fconv<<<(M * DIN / 4 + 255) / 256, 256>>>(x, xh, M * DIN);
    tsplit<<<dim3((2 * DOUT) / 32, DIN / 32), dim3(32, 8)>>>(Wq, Wah, DIN, 2 * DOUT);
    tsplit<<<dim3((Gn * HD) / 32, DIN / 32), dim3(32, 8)>>>(
        Wk, Wah + (size_t)(2 * DOUT) * DIN, DIN, Gn * HD);
    tsplit<<<dim3((Gn * HD) / 32, DIN / 32), dim3(32, 8)>>>(
        Wv, Wah + (size_t)(2 * DOUT + Gn * HD) * DIN, DIN, Gn * HD);
    tsplit<<<dim3(DIN / 32, DOUT / 32), dim3(32, 8)>>>(Wo, Woh, DOUT, DIN);

    // (6) merged QKV projection with fused norm/rope/gate epilogue [profiled]
    gemm_tc<<<dim3(NQKV / 128, M / 256), 256, GEMM_SMEM>>>(
        xh, Wah, (float*)nullptr, M, NQKV, DIN, 1,
        Qhp, Khp, Vhp, Gp, qw, kw, cosT, sinT);

    // (7) HMMA causal attention + gate
    attn_mma<<<dim3(Sn / 128, Hn, Bn), 256, ATT_SMEM>>>(
        Qhp, Khp, Vhp, Gp, Cxh);

    // (8) output projection
    gemm_tc<<<dim3(DIN / 128, M / 256), 256, GEMM_SMEM>>>(
        Cxh, Woh, out, M, DIN, DOUT, 0,
        (__half*)nullptr, (__half*)nullptr, (__half*)nullptr, (__half*)nullptr,
        (const float*)nullptr, (const float*)nullptr,
        (const float*)nullptr, (const float*)nullptr);
}